// round 9
// baseline (speedup 1.0000x reference)
#include <cuda_runtime.h>
#include <cuda_bf16.h>
#include <cstdint>
#include <math.h>

#define SPOS 8192
#define CCH  512
#define CONVK 13824   // 27*512

typedef __nv_bfloat16 bf16;

// ---------------- scratch (static device memory) ----------------
__device__ __align__(256) bf16 g_nHi[SPOS*CCH], g_nLo[SPOS*CCH];
__device__ __align__(256) bf16 g_w1Hi[CCH*CONVK], g_w1Lo[CCH*CONVK];
__device__ __align__(256) bf16 g_w2Hi[CCH*CONVK], g_w2Lo[CCH*CONVK];
__device__ __align__(256) bf16 g_w3Hi[CCH*CONVK], g_w3Lo[CCH*CONVK];
__device__ __align__(256) bf16 g_w4Hi[CCH*CONVK], g_w4Lo[CCH*CONVK];
__device__ __align__(256) bf16 g_qwHi[CCH*CCH], g_qwLo[CCH*CCH];
__device__ __align__(256) bf16 g_kwHi[CCH*CCH], g_kwLo[CCH*CCH];
__device__ __align__(256) bf16 g_vwHi[CCH*CCH], g_vwLo[CCH*CCH];
__device__ __align__(256) bf16 g_pwHi[CCH*CCH], g_pwLo[CCH*CCH];
__device__ __align__(256) bf16 g_qHi[SPOS*CCH], g_qLo[SPOS*CCH];
__device__ __align__(256) bf16 g_kHi[SPOS*CCH], g_kLo[SPOS*CCH];
__device__ __align__(256) bf16 g_vtHi[SPOS*CCH], g_vtLo[SPOS*CCH];
__device__ __align__(256) float g_s[(size_t)SPOS*SPOS];
__device__ __align__(256) float g_rm[SPOS], g_ri[SPOS];
__device__ __align__(256) float g_t[SPOS*CCH], g_h[SPOS*CCH], g_y[SPOS*CCH];

// ---------------- helpers ----------------
__device__ __forceinline__ uint32_t smem_u32(const void* p) {
    uint32_t a;
    asm("{ .reg .u64 t; cvta.to.shared.u64 t, %1; cvt.u32.u64 %0, t; }" : "=r"(a) : "l"(p));
    return a;
}
__device__ __forceinline__ void cp16(uint32_t dst, const void* src) {
    asm volatile("cp.async.cg.shared.global [%0], [%1], 16;" :: "r"(dst), "l"(src));
}
#define CP_COMMIT() asm volatile("cp.async.commit_group;" ::: "memory")
#define CP_WAIT1()  asm volatile("cp.async.wait_group 1;" ::: "memory")
#define CP_WAIT0()  asm volatile("cp.async.wait_group 0;" ::: "memory")
#define SWZ128(b) ((b) ^ (((b) >> 3) & 0x70))

#define LDSM_X4(r, addr) \
    asm volatile("ldmatrix.sync.aligned.m8n8.x4.shared.b16 {%0,%1,%2,%3}, [%4];" \
        : "=r"((r)[0]), "=r"((r)[1]), "=r"((r)[2]), "=r"((r)[3]) : "r"(addr))

__device__ __forceinline__ void mma16816(float* c, const uint32_t* a, const uint32_t* b) {
    asm volatile(
        "mma.sync.aligned.m16n8k16.row.col.f32.bf16.bf16.f32 "
        "{%0,%1,%2,%3},{%4,%5,%6,%7},{%8,%9},{%0,%1,%2,%3};"
        : "+f"(c[0]), "+f"(c[1]), "+f"(c[2]), "+f"(c[3])
        : "r"(a[0]), "r"(a[1]), "r"(a[2]), "r"(a[3]), "r"(b[0]), "r"(b[1]));
}

__device__ __forceinline__ float warpReduceSum(float v) {
#pragma unroll
    for (int o = 16; o; o >>= 1) v += __shfl_xor_sync(0xffffffffu, v, o);
    return v;
}
__device__ __forceinline__ float warpReduceMax(float v) {
#pragma unroll
    for (int o = 16; o; o >>= 1) v = fmaxf(v, __shfl_xor_sync(0xffffffffu, v, o));
    return v;
}

// ---------------- rmsnorm + silu + bf16 split ----------------
__global__ __launch_bounds__(128) void rmsnorm_split(
    const float* __restrict__ x, const float* __restrict__ g,
    bf16* __restrict__ hi, bf16* __restrict__ lo, int do_silu)
{
    __shared__ float red[4];
    const int r = blockIdx.x, tid = threadIdx.x;
    const float4 v = *(const float4*)(x + (size_t)r * CCH + tid * 4);
    float ss = v.x*v.x + v.y*v.y + v.z*v.z + v.w*v.w;
    ss = warpReduceSum(ss);
    if ((tid & 31) == 0) red[tid >> 5] = ss;
    __syncthreads();
    const float tot = red[0] + red[1] + red[2] + red[3];
    const float scale = 22.62741699796952f / (sqrtf(tot) + 1e-8f);
    const float4 gg = *(const float4*)(g + tid * 4);
    float o[4];
    o[0] = v.x*scale*gg.x; o[1] = v.y*scale*gg.y; o[2] = v.z*scale*gg.z; o[3] = v.w*scale*gg.w;
    if (do_silu) {
#pragma unroll
        for (int i = 0; i < 4; i++) o[i] = o[i] / (1.0f + __expf(-o[i]));
    }
    const size_t base = (size_t)r * CCH + tid * 4;
#pragma unroll
    for (int i = 0; i < 4; i++) {
        bf16 h = __float2bfloat16(o[i]);
        hi[base + i] = h;
        lo[base + i] = __float2bfloat16(o[i] - __bfloat162float(h));
    }
}

// ---------------- transpose + split ----------------
__global__ void transpose_split(
    const float* __restrict__ in, bf16* __restrict__ hi, bf16* __restrict__ lo, int R, int Cc)
{
    __shared__ float t[32][33];
    const int c0 = blockIdx.x * 32, r0 = blockIdx.y * 32;
    const int tx = threadIdx.x;
    for (int j = threadIdx.y; j < 32; j += 8)
        t[j][tx] = in[(size_t)(r0 + j) * Cc + c0 + tx];
    __syncthreads();
    for (int j = threadIdx.y; j < 32; j += 8) {
        float v = t[tx][j];
        bf16 h = __float2bfloat16(v);
        const size_t o = (size_t)(c0 + j) * R + r0 + tx;
        hi[o] = h;
        lo[o] = __float2bfloat16(v - __bfloat162float(h));
    }
}

// ---------------- row max + 1/sum over block-causal scores ----------------
__global__ __launch_bounds__(256) void rowmaxsum(
    const float* __restrict__ S, float* __restrict__ rm, float* __restrict__ ri)
{
    __shared__ float red[8];
    const int r = blockIdx.x, tid = threadIdx.x;
    const int cnt = (((r >> 10) + 1) << 10) >> 8;
    const float* row = S + (size_t)r * SPOS;

    float vals[32];
    float mx = -3.4e38f;
#pragma unroll
    for (int i = 0; i < 32; i++)
        if (i < cnt) { vals[i] = row[i * 256 + tid]; mx = fmaxf(mx, vals[i]); }
    mx = warpReduceMax(mx);
    if ((tid & 31) == 0) red[tid >> 5] = mx;
    __syncthreads();
    float m2 = red[0];
#pragma unroll
    for (int i = 1; i < 8; i++) m2 = fmaxf(m2, red[i]);
    __syncthreads();
    float sum = 0.0f;
#pragma unroll
    for (int i = 0; i < 32; i++)
        if (i < cnt) sum += __expf(vals[i] - m2);
    sum = warpReduceSum(sum);
    if ((tid & 31) == 0) red[tid >> 5] = sum;
    __syncthreads();
    if (tid == 0) {
        float tot = 0.0f;
#pragma unroll
        for (int i = 0; i < 8; i++) tot += red[i];
        rm[r] = m2;
        ri[r] = 1.0f / tot;
    }
}

// ---------------- HMMA split-bf16 GEMM, CTA tile BMx256, 512 threads ----------------
#define TCG_GATHER 1
#define TCG_VARK   2
#define TCG_CAUSAL 4

// BM=128: 16 warps as 2x8, warp tile 64x32.  BM=64: 16 warps as 1x16, warp tile 64x16.
// SMAX: A operand is fp32 scores Sf; loader applies exp(s-rowM)*rowI and splits in-register.
template<int BM, bool SMAX>
__global__ __launch_bounds__(512) void tc_gemm(
    const bf16* __restrict__ AHi, const bf16* __restrict__ ALo, int ldA,
    const bf16* __restrict__ BHi, const bf16* __restrict__ BLo, int ldB,
    const float* __restrict__ bias, const float* __restrict__ resid,
    float* __restrict__ C, bf16* __restrict__ outHi, bf16* __restrict__ outLo,
    int ldc, int Ktot, int flags, float scale,
    const float* __restrict__ Sf, const float* __restrict__ rowM, const float* __restrict__ rowI)
{
    constexpr int WN = (BM == 128) ? 8 : 16;      // warps along n
    constexpr int NT = 32 / WN * 2 / 2;           // n-subtiles of 8: 4 or 2
    constexpr int NP = (BM == 128) ? 2 : 1;       // 16-row B groups per warp
    constexpr int WNW = 256 / WN;                 // warp n width: 32 or 16
    constexpr int ABYTES = BM * 128;              // A hi tile bytes
    constexpr int STAGEB = 2 * ABYTES + 65536;    // Ah+Al+Bh+Bl

    extern __shared__ char smem[];
    int mtile = blockIdx.y;
    if (flags & TCG_VARK) mtile = gridDim.y - 1 - blockIdx.y;   // descending-K order
    const int m0 = mtile * BM, n0 = blockIdx.x * 256;
    if (flags & TCG_CAUSAL) { if (n0 >= (((m0 >> 10) + 1) << 10)) return; }
    int Keff = Ktot;
    if (flags & TCG_VARK)   { Keff = ((m0 >> 10) + 1) << 10; }

    const uint32_t sb = smem_u32(smem);
    const uint32_t tbase = (sb + 1023) & ~1023u;
    char* tiles = smem + (tbase - sb);
    int* sBase = (int*)(tiles + 2 * STAGEB);

    const int tid = threadIdx.x, wid = tid >> 5, lid = tid & 31;
    const int wm = wid / WN, wn = wid % WN;
    const bool gather = (flags & TCG_GATHER);

    if (gather && !SMAX) {
        for (int i = tid; i < BM * 27; i += 512) {
            const int mloc = i / 27, tap = i - mloc * 27;
            const int m = m0 + mloc;
            const int kt = tap / 9, r9 = tap - kt * 9, kh = r9 / 3, kw = r9 - kh * 3;
            const int t = m >> 10, hw = m & 1023, h = hw >> 5, w = hw & 31;
            int tin = t + kt - 2; tin = tin < 0 ? 0 : tin;
            int hin = h + kh - 1; hin = hin < 0 ? 0 : (hin > 31 ? 31 : hin);
            int win = w + kw - 1; win = win < 0 ? 0 : (win > 31 ? 31 : win);
            sBase[i] = ((tin << 10) + (hin << 5) + win) << 9;
        }
        __syncthreads();
    }

    auto load_B = [&](int c, int buf) {
        const uint32_t tbu = tbase + buf * STAGEB;
        const long kkB = (long)c << 6;
#pragma unroll
        for (int it = 0; it < 4; it++) {           // B: 256 rows x 8 segs
            const int i = it * 512 + tid;
            const int row = i >> 3, seg = i & 7;
            const long offB = (long)(n0 + row) * ldB + kkB + (seg << 3);
            const uint32_t d = SWZ128((uint32_t)(row * 128 + seg * 16));
            cp16(tbu + 2 * ABYTES + d,         BHi + offB);
            cp16(tbu + 2 * ABYTES + 32768 + d, BLo + offB);
        }
    };

    auto load_A_async = [&](int c, int buf) {
        const uint32_t tbu = tbase + buf * STAGEB;
        const long kkB = (long)c << 6;
        const int tap = c >> 3, c0 = (c & 7) << 6;
#pragma unroll
        for (int it = 0; it < BM / 64; it++) {     // A: BM rows x 8 segs, 512 thr
            const int i = it * 512 + tid;
            const int row = i >> 3, seg = i & 7;
            long offA;
            if (gather) offA = (long)sBase[row * 27 + tap] + c0 + (seg << 3);
            else        offA = (long)(m0 + row) * ldA + kkB + (seg << 3);
            const uint32_t d = SWZ128((uint32_t)(row * 128 + seg * 16));
            cp16(tbu + d,          AHi + offA);
            cp16(tbu + ABYTES + d, ALo + offA);
        }
    };

    float acc[4][NT][4];
#pragma unroll
    for (int a = 0; a < 4; a++)
#pragma unroll
        for (int b = 0; b < NT; b++)
#pragma unroll
            for (int i = 0; i < 4; i++) acc[a][b][i] = 0.0f;

    const int a_r = lid & 15, a_ko = (lid >> 4) * 16;
    const int b_r = ((lid >> 4) << 3) + (lid & 7);
    const int b_ko = ((lid >> 3) & 1) * 16;

    auto mma_chunk = [&](int buf) {
        const uint32_t tbu = tbase + buf * STAGEB;
#pragma unroll
        for (int ks = 0; ks < 4; ks++) {
            const int kb = ks * 32;
            uint32_t ah[4][4], al[4][4];
#pragma unroll
            for (int mt = 0; mt < 4; mt++) {
                const int row = wm * 64 + mt * 16 + a_r;
                const uint32_t off = SWZ128((uint32_t)(row * 128 + kb + a_ko));
                LDSM_X4(ah[mt], tbu + off);
                LDSM_X4(al[mt], tbu + ABYTES + off);
            }
#pragma unroll
            for (int p = 0; p < NP; p++) {
                const int row = wn * WNW + p * 16 + b_r;
                const uint32_t off = SWZ128((uint32_t)(row * 128 + kb + b_ko));
                uint32_t rh[4], rl[4];
                LDSM_X4(rh, tbu + 2 * ABYTES + off);
                LDSM_X4(rl, tbu + 2 * ABYTES + 32768 + off);
#pragma unroll
                for (int mt = 0; mt < 4; mt++) {
                    mma16816(acc[mt][2*p],   ah[mt], rh);
                    mma16816(acc[mt][2*p],   ah[mt], rl);
                    mma16816(acc[mt][2*p],   al[mt], rh);
                    mma16816(acc[mt][2*p+1], ah[mt], rh + 2);
                    mma16816(acc[mt][2*p+1], ah[mt], rl + 2);
                    mma16816(acc[mt][2*p+1], al[mt], rh + 2);
                }
            }
        }
    };

    const int nc = Keff >> 6;

    if constexpr (SMAX) {
        // A = softmax(Sf) computed in-register: row per thread fixed (64 rows x 8 segs = 512 thr)
        const int arow = tid >> 3, aseg = tid & 7;
        const float rm = rowM[m0 + arow], ri = rowI[m0 + arow];
        const uint32_t ad = SWZ128((uint32_t)(arow * 128 + aseg * 16));
        float sa[8];

        auto ldA_regs = [&](int c) {
            const float* sp = Sf + (size_t)(m0 + arow) * SPOS + ((long)c << 6) + (aseg << 3);
            const float4 v0 = *(const float4*)sp;
            const float4 v1 = *(const float4*)(sp + 4);
            sa[0]=v0.x; sa[1]=v0.y; sa[2]=v0.z; sa[3]=v0.w;
            sa[4]=v1.x; sa[5]=v1.y; sa[6]=v1.z; sa[7]=v1.w;
        };
        auto stsA = [&](int buf) {
            uint32_t hi4[4], lo4[4];
#pragma unroll
            for (int j = 0; j < 4; j++) {
                const float p0 = __expf(sa[2*j]   - rm) * ri;
                const float p1 = __expf(sa[2*j+1] - rm) * ri;
                const bf16 h0 = __float2bfloat16(p0), h1 = __float2bfloat16(p1);
                __nv_bfloat162 hh; hh.x = h0; hh.y = h1;
                __nv_bfloat162 ll;
                ll.x = __float2bfloat16(p0 - __bfloat162float(h0));
                ll.y = __float2bfloat16(p1 - __bfloat162float(h1));
                hi4[j] = *(uint32_t*)&hh;
                lo4[j] = *(uint32_t*)&ll;
            }
            char* tb = tiles + buf * STAGEB;
            *(uint4*)(tb + ad)          = make_uint4(hi4[0], hi4[1], hi4[2], hi4[3]);
            *(uint4*)(tb + ABYTES + ad) = make_uint4(lo4[0], lo4[1], lo4[2], lo4[3]);
        };

        ldA_regs(0);
        load_B(0, 0);
        CP_COMMIT();
        for (int c = 0; c < nc; c++) {
            stsA(c & 1);
            if (c + 1 < nc) {
                ldA_regs(c + 1);
                load_B(c + 1, (c + 1) & 1);
                CP_COMMIT(); CP_WAIT1();
            } else CP_WAIT0();
            __syncthreads();
            mma_chunk(c & 1);
            __syncthreads();
        }
    } else {
        load_A_async(0, 0);
        load_B(0, 0);
        CP_COMMIT();
        for (int c = 0; c < nc; c++) {
            if (c + 1 < nc) {
                load_A_async(c + 1, (c + 1) & 1);
                load_B(c + 1, (c + 1) & 1);
                CP_COMMIT(); CP_WAIT1();
            } else CP_WAIT0();
            __syncthreads();
            mma_chunk(c & 1);
            __syncthreads();
        }
    }

    // epilogue
    const int er = lid >> 2, ec = (lid & 3) * 2;
#pragma unroll
    for (int mt = 0; mt < 4; mt++) {
#pragma unroll
        for (int nt = 0; nt < NT; nt++) {
            const int n = n0 + wn * WNW + nt * 8 + ec;
            float b0 = 0.f, b1 = 0.f;
            if (bias) { b0 = bias[n]; b1 = bias[n + 1]; }
#pragma unroll
            for (int half = 0; half < 2; half++) {
                const int m = m0 + wm * 64 + mt * 16 + er + half * 8;
                float v0 = acc[mt][nt][half * 2 + 0] * scale + b0;
                float v1 = acc[mt][nt][half * 2 + 1] * scale + b1;
                if (resid) {
                    const float2 rv = *(const float2*)(resid + (size_t)m * ldc + n);
                    v0 += rv.x; v1 += rv.y;
                }
                if (C)
                    *(float2*)(C + (size_t)m * ldc + n) = make_float2(v0, v1);
                if (outHi) {
                    bf16 h0 = __float2bfloat16(v0), h1 = __float2bfloat16(v1);
                    __nv_bfloat162 hh; hh.x = h0; hh.y = h1;
                    __nv_bfloat162 ll;
                    ll.x = __float2bfloat16(v0 - __bfloat162float(h0));
                    ll.y = __float2bfloat16(v1 - __bfloat162float(h1));
                    *(__nv_bfloat162*)(outHi + (size_t)m * ldc + n) = hh;
                    *(__nv_bfloat162*)(outLo + (size_t)m * ldc + n) = ll;
                }
            }
        }
    }
}

// ---------------- host orchestration ----------------
extern "C" void kernel_launch(void* const* d_in, const int* in_sizes, int n_in,
                              void* d_out, int out_size)
{
    const float* x    = (const float*)d_in[0];
    const float* r1g1 = (const float*)d_in[1];
    const float* r1w1 = (const float*)d_in[2];
    const float* r1b1 = (const float*)d_in[3];
    const float* r1g2 = (const float*)d_in[4];
    const float* r1w2 = (const float*)d_in[5];
    const float* r1b2 = (const float*)d_in[6];
    const float* atg  = (const float*)d_in[7];
    const float* qw   = (const float*)d_in[8];
    const float* qb   = (const float*)d_in[9];
    const float* kw   = (const float*)d_in[10];
    const float* kb   = (const float*)d_in[11];
    const float* vw   = (const float*)d_in[12];
    const float* vb   = (const float*)d_in[13];
    const float* pw   = (const float*)d_in[14];
    const float* pb   = (const float*)d_in[15];
    const float* r2g1 = (const float*)d_in[16];
    const float* r2w1 = (const float*)d_in[17];
    const float* r2b1 = (const float*)d_in[18];
    const float* r2g2 = (const float*)d_in[19];
    const float* r2w2 = (const float*)d_in[20];
    const float* r2b2 = (const float*)d_in[21];
    float* out = (float*)d_out;

    bf16 *nHi, *nLo, *qHi, *qLo, *kHi, *kLo, *vtHi, *vtLo;
    bf16 *w1Hi, *w1Lo, *w2Hi, *w2Lo, *w3Hi, *w3Lo, *w4Hi, *w4Lo;
    bf16 *qwHi, *qwLo, *kwHi, *kwLo, *vwHi, *vwLo, *pwHi, *pwLo;
    float *s, *t, *h, *y, *rmG, *riG;
    cudaGetSymbolAddress((void**)&nHi, g_nHi);  cudaGetSymbolAddress((void**)&nLo, g_nLo);
    cudaGetSymbolAddress((void**)&w1Hi, g_w1Hi); cudaGetSymbolAddress((void**)&w1Lo, g_w1Lo);
    cudaGetSymbolAddress((void**)&w2Hi, g_w2Hi); cudaGetSymbolAddress((void**)&w2Lo, g_w2Lo);
    cudaGetSymbolAddress((void**)&w3Hi, g_w3Hi); cudaGetSymbolAddress((void**)&w3Lo, g_w3Lo);
    cudaGetSymbolAddress((void**)&w4Hi, g_w4Hi); cudaGetSymbolAddress((void**)&w4Lo, g_w4Lo);
    cudaGetSymbolAddress((void**)&qwHi, g_qwHi); cudaGetSymbolAddress((void**)&qwLo, g_qwLo);
    cudaGetSymbolAddress((void**)&kwHi, g_kwHi); cudaGetSymbolAddress((void**)&kwLo, g_kwLo);
    cudaGetSymbolAddress((void**)&vwHi, g_vwHi); cudaGetSymbolAddress((void**)&vwLo, g_vwLo);
    cudaGetSymbolAddress((void**)&pwHi, g_pwHi); cudaGetSymbolAddress((void**)&pwLo, g_pwLo);
    cudaGetSymbolAddress((void**)&qHi, g_qHi);  cudaGetSymbolAddress((void**)&qLo, g_qLo);
    cudaGetSymbolAddress((void**)&kHi, g_kHi);  cudaGetSymbolAddress((void**)&kLo, g_kLo);
    cudaGetSymbolAddress((void**)&vtHi, g_vtHi); cudaGetSymbolAddress((void**)&vtLo, g_vtLo);
    cudaGetSymbolAddress((void**)&s, g_s);
    cudaGetSymbolAddress((void**)&t, g_t);
    cudaGetSymbolAddress((void**)&h, g_h);
    cudaGetSymbolAddress((void**)&y, g_y);
    cudaGetSymbolAddress((void**)&rmG, g_rm);
    cudaGetSymbolAddress((void**)&riG, g_ri);

    const int SMB128 = 1024 + 2 * (2 * 128 * 128 + 65536) + 128 * 27 * 4;  // 211456
    const int SMB64  = 1024 + 2 * (2 * 64 * 128 + 65536);                  // 164864
    cudaFuncSetAttribute(tc_gemm<128,false>, cudaFuncAttributeMaxDynamicSharedMemorySize, SMB128);
    cudaFuncSetAttribute(tc_gemm<64,true>,   cudaFuncAttributeMaxDynamicSharedMemorySize, SMB64);

    const dim3 gStd(2, 64);            // 128-row tiles
    const dim3 gNT(32, 64);            // scores
    const dim3 gAV(2, 128);            // 64-row tiles, descending-K
    const dim3 tBlk(32, 8);
    const dim3 gWT3(16, 432);
    const dim3 gWT1(16, 16);
    const dim3 gVT(16, 256);
    const float rs512 = 0.04419417382415922f;

    // ---- fork weight prep onto a side stream (all input-only work) ----
    cudaStream_t s2;
    cudaStreamCreateWithFlags(&s2, cudaStreamNonBlocking);
    cudaEvent_t evFork;
    cudaEventCreateWithFlags(&evFork, cudaEventDisableTiming);
    cudaEvent_t evW[8];
    for (int i = 0; i < 8; i++) cudaEventCreateWithFlags(&evW[i], cudaEventDisableTiming);

    cudaEventRecord(evFork, 0);
    cudaStreamWaitEvent(s2, evFork, 0);
    transpose_split<<<gWT3, tBlk, 0, s2>>>(r1w1, w1Hi, w1Lo, CONVK, CCH); cudaEventRecord(evW[0], s2);
    transpose_split<<<gWT3, tBlk, 0, s2>>>(r1w2, w2Hi, w2Lo, CONVK, CCH); cudaEventRecord(evW[1], s2);
    transpose_split<<<gWT1, tBlk, 0, s2>>>(qw, qwHi, qwLo, CCH, CCH);     cudaEventRecord(evW[2], s2);
    transpose_split<<<gWT1, tBlk, 0, s2>>>(kw, kwHi, kwLo, CCH, CCH);     cudaEventRecord(evW[3], s2);
    transpose_split<<<gWT1, tBlk, 0, s2>>>(vw, vwHi, vwLo, CCH, CCH);     cudaEventRecord(evW[4], s2);
    transpose_split<<<gWT1, tBlk, 0, s2>>>(pw, pwHi, pwLo, CCH, CCH);     cudaEventRecord(evW[5], s2);
    transpose_split<<<gWT3, tBlk, 0, s2>>>(r2w1, w3Hi, w3Lo, CONVK, CCH); cudaEventRecord(evW[6], s2);
    transpose_split<<<gWT3, tBlk, 0, s2>>>(r2w2, w4Hi, w4Lo, CONVK, CCH); cudaEventRecord(evW[7], s2);

    // ---- resnet 1 ----
    rmsnorm_split<<<SPOS, 128>>>(x, r1g1, nHi, nLo, 1);
    cudaStreamWaitEvent(0, evW[0], 0);
    tc_gemm<128,false><<<gStd, 512, SMB128>>>(nHi, nLo, CCH, w1Hi, w1Lo, CONVK, r1b1, nullptr, h, nullptr, nullptr, CCH, CONVK, TCG_GATHER, 1.0f, nullptr, nullptr, nullptr);
    rmsnorm_split<<<SPOS, 128>>>(h, r1g2, nHi, nLo, 1);
    cudaStreamWaitEvent(0, evW[1], 0);
    tc_gemm<128,false><<<gStd, 512, SMB128>>>(nHi, nLo, CCH, w2Hi, w2Lo, CONVK, r1b2, x, y, nullptr, nullptr, CCH, CONVK, TCG_GATHER, 1.0f, nullptr, nullptr, nullptr);

    // ---- attention ----
    rmsnorm_split<<<SPOS, 128>>>(y, atg, nHi, nLo, 0);
    cudaStreamWaitEvent(0, evW[2], 0);
    tc_gemm<128,false><<<gStd, 512, SMB128>>>(nHi, nLo, CCH, qwHi, qwLo, CCH, qb, nullptr, nullptr, qHi, qLo, CCH, CCH, 0, 1.0f, nullptr, nullptr, nullptr);
    cudaStreamWaitEvent(0, evW[3], 0);
    tc_gemm<128,false><<<gStd, 512, SMB128>>>(nHi, nLo, CCH, kwHi, kwLo, CCH, kb, nullptr, nullptr, kHi, kLo, CCH, CCH, 0, 1.0f, nullptr, nullptr, nullptr);
    cudaStreamWaitEvent(0, evW[4], 0);
    tc_gemm<128,false><<<gStd, 512, SMB128>>>(nHi, nLo, CCH, vwHi, vwLo, CCH, vb, nullptr, t, nullptr, nullptr, CCH, CCH, 0, 1.0f, nullptr, nullptr, nullptr);
    transpose_split<<<gVT, tBlk>>>(t, vtHi, vtLo, SPOS, CCH);

    tc_gemm<128,false><<<gNT, 512, SMB128>>>(qHi, qLo, CCH, kHi, kLo, CCH, nullptr, nullptr, s, nullptr, nullptr, SPOS, CCH, TCG_CAUSAL, rs512, nullptr, nullptr, nullptr);
    rowmaxsum<<<SPOS, 256>>>(s, rmG, riG);
    tc_gemm<64,true><<<gAV, 512, SMB64>>>(nullptr, nullptr, SPOS, vtHi, vtLo, SPOS, nullptr, nullptr, nullptr, qHi, qLo, CCH, SPOS, TCG_VARK, 1.0f, s, rmG, riG);
    cudaStreamWaitEvent(0, evW[5], 0);
    tc_gemm<128,false><<<gStd, 512, SMB128>>>(qHi, qLo, CCH, pwHi, pwLo, CCH, pb, y, h, nullptr, nullptr, CCH, CCH, 0, 1.0f, nullptr, nullptr, nullptr);

    // ---- resnet 2 ----
    rmsnorm_split<<<SPOS, 128>>>(h, r2g1, nHi, nLo, 1);
    cudaStreamWaitEvent(0, evW[6], 0);
    tc_gemm<128,false><<<gStd, 512, SMB128>>>(nHi, nLo, CCH, w3Hi, w3Lo, CONVK, r2b1, nullptr, t, nullptr, nullptr, CCH, CONVK, TCG_GATHER, 1.0f, nullptr, nullptr, nullptr);
    rmsnorm_split<<<SPOS, 128>>>(t, r2g2, nHi, nLo, 1);
    cudaStreamWaitEvent(0, evW[7], 0);
    tc_gemm<128,false><<<gStd, 512, SMB128>>>(nHi, nLo, CCH, w4Hi, w4Lo, CONVK, r2b2, h, out, nullptr, nullptr, CCH, CONVK, TCG_GATHER, 1.0f, nullptr, nullptr, nullptr);
}

// round 10
// speedup vs baseline: 1.0148x; 1.0148x over previous
#include <cuda_runtime.h>
#include <cuda_bf16.h>
#include <cstdint>
#include <math.h>

#define SPOS 8192
#define CCH  512
#define CONVK 13824   // 27*512

typedef __nv_bfloat16 bf16;

// ---------------- scratch (static device memory) ----------------
__device__ __align__(256) bf16 g_nHi[SPOS*CCH], g_nLo[SPOS*CCH];
__device__ __align__(256) bf16 g_w1Hi[CCH*CONVK], g_w1Lo[CCH*CONVK];
__device__ __align__(256) bf16 g_w2Hi[CCH*CONVK], g_w2Lo[CCH*CONVK];
__device__ __align__(256) bf16 g_w3Hi[CCH*CONVK], g_w3Lo[CCH*CONVK];
__device__ __align__(256) bf16 g_w4Hi[CCH*CONVK], g_w4Lo[CCH*CONVK];
__device__ __align__(256) bf16 g_qwHi[CCH*CCH], g_qwLo[CCH*CCH];
__device__ __align__(256) bf16 g_kwHi[CCH*CCH], g_kwLo[CCH*CCH];
__device__ __align__(256) bf16 g_vwHi[CCH*CCH], g_vwLo[CCH*CCH];
__device__ __align__(256) bf16 g_pwHi[CCH*CCH], g_pwLo[CCH*CCH];
__device__ __align__(256) bf16 g_qHi[SPOS*CCH], g_qLo[SPOS*CCH];
__device__ __align__(256) bf16 g_kHi[SPOS*CCH], g_kLo[SPOS*CCH];
__device__ __align__(256) bf16 g_vtHi[SPOS*CCH], g_vtLo[SPOS*CCH];
__device__ __align__(256) bf16 g_pHi[(size_t)SPOS*SPOS], g_pLo[(size_t)SPOS*SPOS];
__device__ __align__(256) float g_s[(size_t)SPOS*SPOS];
__device__ __align__(256) float g_t[SPOS*CCH], g_h[SPOS*CCH], g_y[SPOS*CCH];
__device__ __align__(256) float g_v[SPOS*CCH];

// ---------------- helpers ----------------
__device__ __forceinline__ uint32_t smem_u32(const void* p) {
    uint32_t a;
    asm("{ .reg .u64 t; cvta.to.shared.u64 t, %1; cvt.u32.u64 %0, t; }" : "=r"(a) : "l"(p));
    return a;
}
__device__ __forceinline__ void cp16(uint32_t dst, const void* src) {
    asm volatile("cp.async.cg.shared.global [%0], [%1], 16;" :: "r"(dst), "l"(src));
}
#define CP_COMMIT() asm volatile("cp.async.commit_group;" ::: "memory")
#define CP_WAIT1()  asm volatile("cp.async.wait_group 1;" ::: "memory")
#define CP_WAIT0()  asm volatile("cp.async.wait_group 0;" ::: "memory")
#define SWZ128(b) ((b) ^ (((b) >> 3) & 0x70))

#define LDSM_X4(r, addr) \
    asm volatile("ldmatrix.sync.aligned.m8n8.x4.shared.b16 {%0,%1,%2,%3}, [%4];" \
        : "=r"((r)[0]), "=r"((r)[1]), "=r"((r)[2]), "=r"((r)[3]) : "r"(addr))

__device__ __forceinline__ void mma16816(float* c, const uint32_t* a, const uint32_t* b) {
    asm volatile(
        "mma.sync.aligned.m16n8k16.row.col.f32.bf16.bf16.f32 "
        "{%0,%1,%2,%3},{%4,%5,%6,%7},{%8,%9},{%0,%1,%2,%3};"
        : "+f"(c[0]), "+f"(c[1]), "+f"(c[2]), "+f"(c[3])
        : "r"(a[0]), "r"(a[1]), "r"(a[2]), "r"(a[3]), "r"(b[0]), "r"(b[1]));
}

__device__ __forceinline__ float warpReduceSum(float v) {
#pragma unroll
    for (int o = 16; o; o >>= 1) v += __shfl_xor_sync(0xffffffffu, v, o);
    return v;
}
__device__ __forceinline__ float warpReduceMax(float v) {
#pragma unroll
    for (int o = 16; o; o >>= 1) v = fmaxf(v, __shfl_xor_sync(0xffffffffu, v, o));
    return v;
}

// ---------------- rmsnorm + silu + bf16 split ----------------
__global__ __launch_bounds__(128) void rmsnorm_split(
    const float* __restrict__ x, const float* __restrict__ g,
    bf16* __restrict__ hi, bf16* __restrict__ lo, int do_silu)
{
    __shared__ float red[4];
    const int r = blockIdx.x, tid = threadIdx.x;
    const float4 v = *(const float4*)(x + (size_t)r * CCH + tid * 4);
    float ss = v.x*v.x + v.y*v.y + v.z*v.z + v.w*v.w;
    ss = warpReduceSum(ss);
    if ((tid & 31) == 0) red[tid >> 5] = ss;
    __syncthreads();
    const float tot = red[0] + red[1] + red[2] + red[3];
    const float scale = 22.62741699796952f / (sqrtf(tot) + 1e-8f);
    const float4 gg = *(const float4*)(g + tid * 4);
    float o[4];
    o[0] = v.x*scale*gg.x; o[1] = v.y*scale*gg.y; o[2] = v.z*scale*gg.z; o[3] = v.w*scale*gg.w;
    if (do_silu) {
#pragma unroll
        for (int i = 0; i < 4; i++) o[i] = o[i] / (1.0f + __expf(-o[i]));
    }
    const size_t base = (size_t)r * CCH + tid * 4;
#pragma unroll
    for (int i = 0; i < 4; i++) {
        bf16 h = __float2bfloat16(o[i]);
        hi[base + i] = h;
        lo[base + i] = __float2bfloat16(o[i] - __bfloat162float(h));
    }
}

// ---------------- transpose + split ----------------
__global__ void transpose_split(
    const float* __restrict__ in, bf16* __restrict__ hi, bf16* __restrict__ lo, int R, int Cc)
{
    __shared__ float t[32][33];
    const int c0 = blockIdx.x * 32, r0 = blockIdx.y * 32;
    const int tx = threadIdx.x;
    for (int j = threadIdx.y; j < 32; j += 8)
        t[j][tx] = in[(size_t)(r0 + j) * Cc + c0 + tx];
    __syncthreads();
    for (int j = threadIdx.y; j < 32; j += 8) {
        float v = t[tx][j];
        bf16 h = __float2bfloat16(v);
        const size_t o = (size_t)(c0 + j) * R + r0 + tx;
        hi[o] = h;
        lo[o] = __float2bfloat16(v - __bfloat162float(h));
    }
}

// ---------------- softmax -> bf16 split probs ----------------
__global__ __launch_bounds__(256) void softmax_split(
    const float* __restrict__ S, bf16* __restrict__ PHi, bf16* __restrict__ PLo)
{
    __shared__ float red[8];
    const int r = blockIdx.x, tid = threadIdx.x;
    const int cnt = (((r >> 10) + 1) << 10) >> 8;
    const float* row = S + (size_t)r * SPOS;

    float vals[32];
    float mx = -3.4e38f;
#pragma unroll
    for (int i = 0; i < 32; i++)
        if (i < cnt) { vals[i] = row[i * 256 + tid]; mx = fmaxf(mx, vals[i]); }
    mx = warpReduceMax(mx);
    if ((tid & 31) == 0) red[tid >> 5] = mx;
    __syncthreads();
    float m2 = red[0];
#pragma unroll
    for (int i = 1; i < 8; i++) m2 = fmaxf(m2, red[i]);
    __syncthreads();
    float sum = 0.0f;
#pragma unroll
    for (int i = 0; i < 32; i++)
        if (i < cnt) { vals[i] = __expf(vals[i] - m2); sum += vals[i]; }
    sum = warpReduceSum(sum);
    if ((tid & 31) == 0) red[tid >> 5] = sum;
    __syncthreads();
    float tot = 0.0f;
#pragma unroll
    for (int i = 0; i < 8; i++) tot += red[i];
    const float inv = 1.0f / tot;
    bf16* ph = PHi + (size_t)r * SPOS;
    bf16* pl = PLo + (size_t)r * SPOS;
#pragma unroll
    for (int i = 0; i < 32; i++)
        if (i < cnt) {
            float p = vals[i] * inv;
            bf16 h = __float2bfloat16(p);
            ph[i * 256 + tid] = h;
            pl[i * 256 + tid] = __float2bfloat16(p - __bfloat162float(h));
        }
}

// ---------------- HMMA split-bf16 GEMM, CTA tile BMx256, 512 threads ----------------
#define TCG_GATHER 1
#define TCG_VARK   2
#define TCG_CAUSAL 4

// BM=128: 16 warps as 2x8, warp tile 64x32.  BM=64: 16 warps as 1x16, warp tile 64x16.
template<int BM>
__global__ __launch_bounds__(512) void tc_gemm(
    const bf16* __restrict__ AHi, const bf16* __restrict__ ALo, int ldA,
    const bf16* __restrict__ BHi, const bf16* __restrict__ BLo, int ldB,
    const float* __restrict__ bias, const float* __restrict__ resid,
    float* __restrict__ C, bf16* __restrict__ outHi, bf16* __restrict__ outLo,
    int ldc, int Ktot, int flags, float scale)
{
    constexpr int WN = (BM == 128) ? 8 : 16;      // warps along n
    constexpr int NT = 32 / WN * 2 / 2;           // n-subtiles of 8: 4 or 2
    constexpr int NP = (BM == 128) ? 2 : 1;       // 16-row B groups per warp
    constexpr int WNW = 256 / WN;                 // warp n width: 32 or 16
    constexpr int ABYTES = BM * 128;              // A hi tile bytes
    constexpr int STAGEB = 2 * ABYTES + 65536;    // Ah+Al+Bh+Bl

    extern __shared__ char smem[];
    int mtile = blockIdx.y;
    if (flags & TCG_VARK) mtile = gridDim.y - 1 - blockIdx.y;   // descending-K order
    const int m0 = mtile * BM, n0 = blockIdx.x * 256;
    if (flags & TCG_CAUSAL) { if (n0 >= (((m0 >> 10) + 1) << 10)) return; }
    int Keff = Ktot;
    if (flags & TCG_VARK)   { Keff = ((m0 >> 10) + 1) << 10; }

    const uint32_t sb = smem_u32(smem);
    const uint32_t tbase = (sb + 1023) & ~1023u;
    char* tiles = smem + (tbase - sb);
    int* sBase = (int*)(tiles + 2 * STAGEB);

    const int tid = threadIdx.x, wid = tid >> 5, lid = tid & 31;
    const int wm = wid / WN, wn = wid % WN;
    const bool gather = (flags & TCG_GATHER);

    if (gather) {
        for (int i = tid; i < BM * 27; i += 512) {
            const int mloc = i / 27, tap = i - mloc * 27;
            const int m = m0 + mloc;
            const int kt = tap / 9, r9 = tap - kt * 9, kh = r9 / 3, kw = r9 - kh * 3;
            const int t = m >> 10, hw = m & 1023, h = hw >> 5, w = hw & 31;
            int tin = t + kt - 2; tin = tin < 0 ? 0 : tin;
            int hin = h + kh - 1; hin = hin < 0 ? 0 : (hin > 31 ? 31 : hin);
            int win = w + kw - 1; win = win < 0 ? 0 : (win > 31 ? 31 : win);
            sBase[i] = ((tin << 10) + (hin << 5) + win) << 9;
        }
        __syncthreads();
    }

    auto load_chunk = [&](int c, int buf) {
        const uint32_t tbu = tbase + buf * STAGEB;
        const long kkB = (long)c << 6;
        const int tap = c >> 3, c0 = (c & 7) << 6;
#pragma unroll
        for (int it = 0; it < BM / 64; it++) {     // A: BM rows x 8 segs, 512 thr
            const int i = it * 512 + tid;
            const int row = i >> 3, seg = i & 7;
            long offA;
            if (gather) offA = (long)sBase[row * 27 + tap] + c0 + (seg << 3);
            else        offA = (long)(m0 + row) * ldA + kkB + (seg << 3);
            const uint32_t d = SWZ128((uint32_t)(row * 128 + seg * 16));
            cp16(tbu + d,          AHi + offA);
            cp16(tbu + ABYTES + d, ALo + offA);
        }
#pragma unroll
        for (int it = 0; it < 4; it++) {           // B: 256 rows x 8 segs
            const int i = it * 512 + tid;
            const int row = i >> 3, seg = i & 7;
            const long offB = (long)(n0 + row) * ldB + kkB + (seg << 3);
            const uint32_t d = SWZ128((uint32_t)(row * 128 + seg * 16));
            cp16(tbu + 2 * ABYTES + d,         BHi + offB);
            cp16(tbu + 2 * ABYTES + 32768 + d, BLo + offB);
        }
    };

    float acc[4][NT][4];
#pragma unroll
    for (int a = 0; a < 4; a++)
#pragma unroll
        for (int b = 0; b < NT; b++)
#pragma unroll
            for (int i = 0; i < 4; i++) acc[a][b][i] = 0.0f;

    const int a_r = lid & 15, a_ko = (lid >> 4) * 16;
    const int b_r = ((lid >> 4) << 3) + (lid & 7);
    const int b_ko = ((lid >> 3) & 1) * 16;

    const int nc = Keff >> 6;
    load_chunk(0, 0);
    CP_COMMIT();

    for (int c = 0; c < nc; c++) {
        if (c + 1 < nc) { load_chunk(c + 1, (c + 1) & 1); CP_COMMIT(); CP_WAIT1(); }
        else            { CP_WAIT0(); }
        __syncthreads();

        const uint32_t tbu = tbase + (c & 1) * STAGEB;
#pragma unroll
        for (int ks = 0; ks < 4; ks++) {
            const int kb = ks * 32;
            uint32_t ah[4][4], al[4][4];
#pragma unroll
            for (int mt = 0; mt < 4; mt++) {
                const int row = wm * 64 + mt * 16 + a_r;
                const uint32_t off = SWZ128((uint32_t)(row * 128 + kb + a_ko));
                LDSM_X4(ah[mt], tbu + off);
                LDSM_X4(al[mt], tbu + ABYTES + off);
            }
#pragma unroll
            for (int p = 0; p < NP; p++) {
                const int row = wn * WNW + p * 16 + b_r;
                const uint32_t off = SWZ128((uint32_t)(row * 128 + kb + b_ko));
                uint32_t rh[4], rl[4];
                LDSM_X4(rh, tbu + 2 * ABYTES + off);
                LDSM_X4(rl, tbu + 2 * ABYTES + 32768 + off);
#pragma unroll
                for (int mt = 0; mt < 4; mt++) {
                    mma16816(acc[mt][2*p],   ah[mt], rh);
                    mma16816(acc[mt][2*p],   ah[mt], rl);
                    mma16816(acc[mt][2*p],   al[mt], rh);
                    mma16816(acc[mt][2*p+1], ah[mt], rh + 2);
                    mma16816(acc[mt][2*p+1], ah[mt], rl + 2);
                    mma16816(acc[mt][2*p+1], al[mt], rh + 2);
                }
            }
        }
        __syncthreads();
    }

    // epilogue
    const int er = lid >> 2, ec = (lid & 3) * 2;
#pragma unroll
    for (int mt = 0; mt < 4; mt++) {
#pragma unroll
        for (int nt = 0; nt < NT; nt++) {
            const int n = n0 + wn * WNW + nt * 8 + ec;
            float b0 = 0.f, b1 = 0.f;
            if (bias) { b0 = bias[n]; b1 = bias[n + 1]; }
#pragma unroll
            for (int half = 0; half < 2; half++) {
                const int m = m0 + wm * 64 + mt * 16 + er + half * 8;
                float v0 = acc[mt][nt][half * 2 + 0] * scale + b0;
                float v1 = acc[mt][nt][half * 2 + 1] * scale + b1;
                if (resid) {
                    const float2 rv = *(const float2*)(resid + (size_t)m * ldc + n);
                    v0 += rv.x; v1 += rv.y;
                }
                if (C)
                    *(float2*)(C + (size_t)m * ldc + n) = make_float2(v0, v1);
                if (outHi) {
                    bf16 h0 = __float2bfloat16(v0), h1 = __float2bfloat16(v1);
                    __nv_bfloat162 hh; hh.x = h0; hh.y = h1;
                    __nv_bfloat162 ll;
                    ll.x = __float2bfloat16(v0 - __bfloat162float(h0));
                    ll.y = __float2bfloat16(v1 - __bfloat162float(h1));
                    *(__nv_bfloat162*)(outHi + (size_t)m * ldc + n) = hh;
                    *(__nv_bfloat162*)(outLo + (size_t)m * ldc + n) = ll;
                }
            }
        }
    }
}

// ---------------- host orchestration ----------------
extern "C" void kernel_launch(void* const* d_in, const int* in_sizes, int n_in,
                              void* d_out, int out_size)
{
    const float* x    = (const float*)d_in[0];
    const float* r1g1 = (const float*)d_in[1];
    const float* r1w1 = (const float*)d_in[2];
    const float* r1b1 = (const float*)d_in[3];
    const float* r1g2 = (const float*)d_in[4];
    const float* r1w2 = (const float*)d_in[5];
    const float* r1b2 = (const float*)d_in[6];
    const float* atg  = (const float*)d_in[7];
    const float* qw   = (const float*)d_in[8];
    const float* qb   = (const float*)d_in[9];
    const float* kw   = (const float*)d_in[10];
    const float* kb   = (const float*)d_in[11];
    const float* vw   = (const float*)d_in[12];
    const float* vb   = (const float*)d_in[13];
    const float* pw   = (const float*)d_in[14];
    const float* pb   = (const float*)d_in[15];
    const float* r2g1 = (const float*)d_in[16];
    const float* r2w1 = (const float*)d_in[17];
    const float* r2b1 = (const float*)d_in[18];
    const float* r2g2 = (const float*)d_in[19];
    const float* r2w2 = (const float*)d_in[20];
    const float* r2b2 = (const float*)d_in[21];
    float* out = (float*)d_out;

    bf16 *nHi, *nLo, *qHi, *qLo, *kHi, *kLo, *vtHi, *vtLo, *pHi, *pLo;
    bf16 *w1Hi, *w1Lo, *w2Hi, *w2Lo, *w3Hi, *w3Lo, *w4Hi, *w4Lo;
    bf16 *qwHi, *qwLo, *kwHi, *kwLo, *vwHi, *vwLo, *pwHi, *pwLo;
    float *s, *t, *h, *y, *v;
    cudaGetSymbolAddress((void**)&nHi, g_nHi);  cudaGetSymbolAddress((void**)&nLo, g_nLo);
    cudaGetSymbolAddress((void**)&w1Hi, g_w1Hi); cudaGetSymbolAddress((void**)&w1Lo, g_w1Lo);
    cudaGetSymbolAddress((void**)&w2Hi, g_w2Hi); cudaGetSymbolAddress((void**)&w2Lo, g_w2Lo);
    cudaGetSymbolAddress((void**)&w3Hi, g_w3Hi); cudaGetSymbolAddress((void**)&w3Lo, g_w3Lo);
    cudaGetSymbolAddress((void**)&w4Hi, g_w4Hi); cudaGetSymbolAddress((void**)&w4Lo, g_w4Lo);
    cudaGetSymbolAddress((void**)&qwHi, g_qwHi); cudaGetSymbolAddress((void**)&qwLo, g_qwLo);
    cudaGetSymbolAddress((void**)&kwHi, g_kwHi); cudaGetSymbolAddress((void**)&kwLo, g_kwLo);
    cudaGetSymbolAddress((void**)&vwHi, g_vwHi); cudaGetSymbolAddress((void**)&vwLo, g_vwLo);
    cudaGetSymbolAddress((void**)&pwHi, g_pwHi); cudaGetSymbolAddress((void**)&pwLo, g_pwLo);
    cudaGetSymbolAddress((void**)&qHi, g_qHi);  cudaGetSymbolAddress((void**)&qLo, g_qLo);
    cudaGetSymbolAddress((void**)&kHi, g_kHi);  cudaGetSymbolAddress((void**)&kLo, g_kLo);
    cudaGetSymbolAddress((void**)&vtHi, g_vtHi); cudaGetSymbolAddress((void**)&vtLo, g_vtLo);
    cudaGetSymbolAddress((void**)&pHi, g_pHi);  cudaGetSymbolAddress((void**)&pLo, g_pLo);
    cudaGetSymbolAddress((void**)&s, g_s);
    cudaGetSymbolAddress((void**)&t, g_t);
    cudaGetSymbolAddress((void**)&h, g_h);
    cudaGetSymbolAddress((void**)&y, g_y);
    cudaGetSymbolAddress((void**)&v, g_v);

    const int SMB128 = 1024 + 2 * (2 * 128 * 128 + 65536) + 128 * 27 * 4;  // 211456
    const int SMB64  = 1024 + 2 * (2 * 64 * 128 + 65536)  + 64 * 27 * 4;   // 171776
    cudaFuncSetAttribute(tc_gemm<128>, cudaFuncAttributeMaxDynamicSharedMemorySize, SMB128);
    cudaFuncSetAttribute(tc_gemm<64>,  cudaFuncAttributeMaxDynamicSharedMemorySize, SMB64);

    const dim3 gStd(2, 64);            // 128-row tiles
    const dim3 gNT(32, 64);            // scores
    const dim3 gAV(2, 128);            // 64-row tiles, descending-K
    const dim3 tBlk(32, 8);
    const dim3 gWT3(16, 432);
    const dim3 gWT1(16, 16);
    const dim3 gVT(16, 256);
    const float rs512 = 0.04419417382415922f;

    // ---- streams & events ----
    cudaStream_t s2;
    cudaStreamCreateWithFlags(&s2, cudaStreamNonBlocking);
    cudaEvent_t evFork, evN3, evVT;
    cudaEventCreateWithFlags(&evFork, cudaEventDisableTiming);
    cudaEventCreateWithFlags(&evN3, cudaEventDisableTiming);
    cudaEventCreateWithFlags(&evVT, cudaEventDisableTiming);
    cudaEvent_t evW[8];
    for (int i = 0; i < 8; i++) cudaEventCreateWithFlags(&evW[i], cudaEventDisableTiming);

    // ---- fork weight prep onto the side stream (input-only work) ----
    cudaEventRecord(evFork, 0);
    cudaStreamWaitEvent(s2, evFork, 0);
    transpose_split<<<gWT3, tBlk, 0, s2>>>(r1w1, w1Hi, w1Lo, CONVK, CCH); cudaEventRecord(evW[0], s2);
    transpose_split<<<gWT3, tBlk, 0, s2>>>(r1w2, w2Hi, w2Lo, CONVK, CCH); cudaEventRecord(evW[1], s2);
    transpose_split<<<gWT1, tBlk, 0, s2>>>(qw, qwHi, qwLo, CCH, CCH);     cudaEventRecord(evW[2], s2);
    transpose_split<<<gWT1, tBlk, 0, s2>>>(kw, kwHi, kwLo, CCH, CCH);     cudaEventRecord(evW[3], s2);
    transpose_split<<<gWT1, tBlk, 0, s2>>>(vw, vwHi, vwLo, CCH, CCH);     cudaEventRecord(evW[4], s2);
    transpose_split<<<gWT1, tBlk, 0, s2>>>(pw, pwHi, pwLo, CCH, CCH);     cudaEventRecord(evW[5], s2);
    transpose_split<<<gWT3, tBlk, 0, s2>>>(r2w1, w3Hi, w3Lo, CONVK, CCH); cudaEventRecord(evW[6], s2);
    transpose_split<<<gWT3, tBlk, 0, s2>>>(r2w2, w4Hi, w4Lo, CONVK, CCH); cudaEventRecord(evW[7], s2);

    // ---- resnet 1 ----
    rmsnorm_split<<<SPOS, 128>>>(x, r1g1, nHi, nLo, 1);
    cudaStreamWaitEvent(0, evW[0], 0);
    tc_gemm<128><<<gStd, 512, SMB128>>>(nHi, nLo, CCH, w1Hi, w1Lo, CONVK, r1b1, nullptr, h, nullptr, nullptr, CCH, CONVK, TCG_GATHER, 1.0f);
    rmsnorm_split<<<SPOS, 128>>>(h, r1g2, nHi, nLo, 1);
    cudaStreamWaitEvent(0, evW[1], 0);
    tc_gemm<128><<<gStd, 512, SMB128>>>(nHi, nLo, CCH, w2Hi, w2Lo, CONVK, r1b2, x, y, nullptr, nullptr, CCH, CONVK, TCG_GATHER, 1.0f);

    // ---- attention ----
    rmsnorm_split<<<SPOS, 128>>>(y, atg, nHi, nLo, 0);
    cudaEventRecord(evN3, 0);

    // V chain on side stream, hidden under Q/K projections + QK^T
    cudaStreamWaitEvent(s2, evN3, 0);   // s2 already ordered after evW[4] (in-stream)
    tc_gemm<128><<<gStd, 512, SMB128, s2>>>(nHi, nLo, CCH, vwHi, vwLo, CCH, vb, nullptr, v, nullptr, nullptr, CCH, CCH, 0, 1.0f);
    transpose_split<<<gVT, tBlk, 0, s2>>>(v, vtHi, vtLo, SPOS, CCH);
    cudaEventRecord(evVT, s2);

    cudaStreamWaitEvent(0, evW[2], 0);
    tc_gemm<128><<<gStd, 512, SMB128>>>(nHi, nLo, CCH, qwHi, qwLo, CCH, qb, nullptr, nullptr, qHi, qLo, CCH, CCH, 0, 1.0f);
    cudaStreamWaitEvent(0, evW[3], 0);
    tc_gemm<128><<<gStd, 512, SMB128>>>(nHi, nLo, CCH, kwHi, kwLo, CCH, kb, nullptr, nullptr, kHi, kLo, CCH, CCH, 0, 1.0f);

    tc_gemm<128><<<gNT, 512, SMB128>>>(qHi, qLo, CCH, kHi, kLo, CCH, nullptr, nullptr, s, nullptr, nullptr, SPOS, CCH, TCG_CAUSAL, rs512);
    softmax_split<<<SPOS, 256>>>(s, pHi, pLo);
    cudaStreamWaitEvent(0, evVT, 0);
    tc_gemm<64><<<gAV, 512, SMB64>>>(pHi, pLo, SPOS, vtHi, vtLo, SPOS, nullptr, nullptr, nullptr, qHi, qLo, CCH, SPOS, TCG_VARK, 1.0f);
    cudaStreamWaitEvent(0, evW[5], 0);
    tc_gemm<128><<<gStd, 512, SMB128>>>(qHi, qLo, CCH, pwHi, pwLo, CCH, pb, y, h, nullptr, nullptr, CCH, CCH, 0, 1.0f);

    // ---- resnet 2 ----
    rmsnorm_split<<<SPOS, 128>>>(h, r2g1, nHi, nLo, 1);
    cudaStreamWaitEvent(0, evW[6], 0);
    tc_gemm<128><<<gStd, 512, SMB128>>>(nHi, nLo, CCH, w3Hi, w3Lo, CONVK, r2b1, nullptr, t, nullptr, nullptr, CCH, CONVK, TCG_GATHER, 1.0f);
    rmsnorm_split<<<SPOS, 128>>>(t, r2g2, nHi, nLo, 1);
    cudaStreamWaitEvent(0, evW[7], 0);
    tc_gemm<128><<<gStd, 512, SMB128>>>(nHi, nLo, CCH, w4Hi, w4Lo, CONVK, r2b2, h, out, nullptr, nullptr, CCH, CONVK, TCG_GATHER, 1.0f);
}

// round 11
// speedup vs baseline: 1.1354x; 1.1188x over previous
#include <cuda_runtime.h>
#include <cuda_bf16.h>
#include <cstdint>
#include <math.h>

#define SPOS 8192
#define CCH  512
#define CONVK 13824   // 27*512

typedef __nv_bfloat16 bf16;

// ---------------- scratch (static device memory) ----------------
__device__ __align__(256) bf16 g_nHi[SPOS*CCH], g_nLo[SPOS*CCH];
__device__ __align__(256) bf16 g_w1Hi[CCH*CONVK], g_w1Lo[CCH*CONVK];
__device__ __align__(256) bf16 g_w2Hi[CCH*CONVK], g_w2Lo[CCH*CONVK];
__device__ __align__(256) bf16 g_w3Hi[CCH*CONVK], g_w3Lo[CCH*CONVK];
__device__ __align__(256) bf16 g_w4Hi[CCH*CONVK], g_w4Lo[CCH*CONVK];
__device__ __align__(256) bf16 g_qwHi[CCH*CCH], g_qwLo[CCH*CCH];
__device__ __align__(256) bf16 g_kwHi[CCH*CCH], g_kwLo[CCH*CCH];
__device__ __align__(256) bf16 g_vwHi[CCH*CCH], g_vwLo[CCH*CCH];
__device__ __align__(256) bf16 g_pwHi[CCH*CCH], g_pwLo[CCH*CCH];
__device__ __align__(256) bf16 g_qHi[SPOS*CCH], g_qLo[SPOS*CCH];
__device__ __align__(256) bf16 g_kHi[SPOS*CCH], g_kLo[SPOS*CCH];
__device__ __align__(256) bf16 g_vtHi[SPOS*CCH], g_vtLo[SPOS*CCH];
__device__ __align__(256) bf16 g_pHi[(size_t)SPOS*SPOS], g_pLo[(size_t)SPOS*SPOS];
__device__ __align__(256) float g_s[(size_t)SPOS*SPOS];
__device__ __align__(256) float g_t[SPOS*CCH], g_h[SPOS*CCH], g_y[SPOS*CCH];

// ---------------- helpers ----------------
__device__ __forceinline__ uint32_t smem_u32(const void* p) {
    uint32_t a;
    asm("{ .reg .u64 t; cvta.to.shared.u64 t, %1; cvt.u32.u64 %0, t; }" : "=r"(a) : "l"(p));
    return a;
}
__device__ __forceinline__ void cp16(uint32_t dst, const void* src) {
    asm volatile("cp.async.cg.shared.global [%0], [%1], 16;" :: "r"(dst), "l"(src));
}
#define CP_COMMIT() asm volatile("cp.async.commit_group;" ::: "memory")
#define CP_WAIT1()  asm volatile("cp.async.wait_group 1;" ::: "memory")
#define CP_WAIT0()  asm volatile("cp.async.wait_group 0;" ::: "memory")
#define SWZ128(b) ((b) ^ (((b) >> 3) & 0x70))

#define LDSM_X4(r, addr) \
    asm volatile("ldmatrix.sync.aligned.m8n8.x4.shared.b16 {%0,%1,%2,%3}, [%4];" \
        : "=r"((r)[0]), "=r"((r)[1]), "=r"((r)[2]), "=r"((r)[3]) : "r"(addr))

__device__ __forceinline__ void mma16816(float* c, const uint32_t* a, const uint32_t* b) {
    asm volatile(
        "mma.sync.aligned.m16n8k16.row.col.f32.bf16.bf16.f32 "
        "{%0,%1,%2,%3},{%4,%5,%6,%7},{%8,%9},{%0,%1,%2,%3};"
        : "+f"(c[0]), "+f"(c[1]), "+f"(c[2]), "+f"(c[3])
        : "r"(a[0]), "r"(a[1]), "r"(a[2]), "r"(a[3]), "r"(b[0]), "r"(b[1]));
}

__device__ __forceinline__ float warpReduceSum(float v) {
#pragma unroll
    for (int o = 16; o; o >>= 1) v += __shfl_xor_sync(0xffffffffu, v, o);
    return v;
}
__device__ __forceinline__ float warpReduceMax(float v) {
#pragma unroll
    for (int o = 16; o; o >>= 1) v = fmaxf(v, __shfl_xor_sync(0xffffffffu, v, o));
    return v;
}

// ---------------- rmsnorm + silu + bf16 split ----------------
__global__ __launch_bounds__(128) void rmsnorm_split(
    const float* __restrict__ x, const float* __restrict__ g,
    bf16* __restrict__ hi, bf16* __restrict__ lo, int do_silu)
{
    __shared__ float red[4];
    const int r = blockIdx.x, tid = threadIdx.x;
    const float4 v = *(const float4*)(x + (size_t)r * CCH + tid * 4);
    float ss = v.x*v.x + v.y*v.y + v.z*v.z + v.w*v.w;
    ss = warpReduceSum(ss);
    if ((tid & 31) == 0) red[tid >> 5] = ss;
    __syncthreads();
    const float tot = red[0] + red[1] + red[2] + red[3];
    const float scale = 22.62741699796952f / (sqrtf(tot) + 1e-8f);
    const float4 gg = *(const float4*)(g + tid * 4);
    float o[4];
    o[0] = v.x*scale*gg.x; o[1] = v.y*scale*gg.y; o[2] = v.z*scale*gg.z; o[3] = v.w*scale*gg.w;
    if (do_silu) {
#pragma unroll
        for (int i = 0; i < 4; i++) o[i] = o[i] / (1.0f + __expf(-o[i]));
    }
    const size_t base = (size_t)r * CCH + tid * 4;
#pragma unroll
    for (int i = 0; i < 4; i++) {
        bf16 h = __float2bfloat16(o[i]);
        hi[base + i] = h;
        lo[base + i] = __float2bfloat16(o[i] - __bfloat162float(h));
    }
}

// ---------------- transpose + split ----------------
__global__ void transpose_split(
    const float* __restrict__ in, bf16* __restrict__ hi, bf16* __restrict__ lo, int R, int Cc)
{
    __shared__ float t[32][33];
    const int c0 = blockIdx.x * 32, r0 = blockIdx.y * 32;
    const int tx = threadIdx.x;
    for (int j = threadIdx.y; j < 32; j += 8)
        t[j][tx] = in[(size_t)(r0 + j) * Cc + c0 + tx];
    __syncthreads();
    for (int j = threadIdx.y; j < 32; j += 8) {
        float v = t[tx][j];
        bf16 h = __float2bfloat16(v);
        const size_t o = (size_t)(c0 + j) * R + r0 + tx;
        hi[o] = h;
        lo[o] = __float2bfloat16(v - __bfloat162float(h));
    }
}

// ---------------- softmax -> bf16 split probs ----------------
__global__ __launch_bounds__(256) void softmax_split(
    const float* __restrict__ S, bf16* __restrict__ PHi, bf16* __restrict__ PLo)
{
    __shared__ float red[8];
    const int r = blockIdx.x, tid = threadIdx.x;
    const int cnt = (((r >> 10) + 1) << 10) >> 8;
    const float* row = S + (size_t)r * SPOS;

    float vals[32];
    float mx = -3.4e38f;
#pragma unroll
    for (int i = 0; i < 32; i++)
        if (i < cnt) { vals[i] = row[i * 256 + tid]; mx = fmaxf(mx, vals[i]); }
    mx = warpReduceMax(mx);
    if ((tid & 31) == 0) red[tid >> 5] = mx;
    __syncthreads();
    float m2 = red[0];
#pragma unroll
    for (int i = 1; i < 8; i++) m2 = fmaxf(m2, red[i]);
    __syncthreads();
    float sum = 0.0f;
#pragma unroll
    for (int i = 0; i < 32; i++)
        if (i < cnt) { vals[i] = __expf(vals[i] - m2); sum += vals[i]; }
    sum = warpReduceSum(sum);
    if ((tid & 31) == 0) red[tid >> 5] = sum;
    __syncthreads();
    float tot = 0.0f;
#pragma unroll
    for (int i = 0; i < 8; i++) tot += red[i];
    const float inv = 1.0f / tot;
    bf16* ph = PHi + (size_t)r * SPOS;
    bf16* pl = PLo + (size_t)r * SPOS;
#pragma unroll
    for (int i = 0; i < 32; i++)
        if (i < cnt) {
            float p = vals[i] * inv;
            bf16 h = __float2bfloat16(p);
            ph[i * 256 + tid] = h;
            pl[i * 256 + tid] = __float2bfloat16(p - __bfloat162float(h));
        }
}

// ---------------- HMMA split-bf16 GEMM, CTA tile BMx256, 512 threads ----------------
#define TCG_GATHER 1
#define TCG_VARK   2
#define TCG_CAUSAL 4

template<int BM>
__global__ __launch_bounds__(512) void tc_gemm(
    const bf16* __restrict__ AHi, const bf16* __restrict__ ALo, int ldA,
    const bf16* __restrict__ BHi, const bf16* __restrict__ BLo, int ldB,
    const float* __restrict__ bias, const float* __restrict__ resid,
    float* __restrict__ C, bf16* __restrict__ outHi, bf16* __restrict__ outLo,
    int ldc, int Ktot, int flags, float scale)
{
    constexpr int WN = (BM == 128) ? 8 : 16;
    constexpr int NT = 32 / WN * 2 / 2;
    constexpr int NP = (BM == 128) ? 2 : 1;
    constexpr int WNW = 256 / WN;
    constexpr int ABYTES = BM * 128;
    constexpr int STAGEB = 2 * ABYTES + 65536;

    extern __shared__ char smem[];
    int mtile = blockIdx.y;
    if (flags & TCG_VARK) mtile = gridDim.y - 1 - blockIdx.y;
    const int m0 = mtile * BM, n0 = blockIdx.x * 256;
    if (flags & TCG_CAUSAL) { if (n0 >= (((m0 >> 10) + 1) << 10)) return; }
    int Keff = Ktot;
    if (flags & TCG_VARK)   { Keff = ((m0 >> 10) + 1) << 10; }

    const uint32_t sb = smem_u32(smem);
    const uint32_t tbase = (sb + 1023) & ~1023u;
    char* tiles = smem + (tbase - sb);
    int* sBase = (int*)(tiles + 2 * STAGEB);

    const int tid = threadIdx.x, wid = tid >> 5, lid = tid & 31;
    const int wm = wid / WN, wn = wid % WN;
    const bool gather = (flags & TCG_GATHER);

    if (gather) {
        for (int i = tid; i < BM * 27; i += 512) {
            const int mloc = i / 27, tap = i - mloc * 27;
            const int m = m0 + mloc;
            const int kt = tap / 9, r9 = tap - kt * 9, kh = r9 / 3, kw = r9 - kh * 3;
            const int t = m >> 10, hw = m & 1023, h = hw >> 5, w = hw & 31;
            int tin = t + kt - 2; tin = tin < 0 ? 0 : tin;
            int hin = h + kh - 1; hin = hin < 0 ? 0 : (hin > 31 ? 31 : hin);
            int win = w + kw - 1; win = win < 0 ? 0 : (win > 31 ? 31 : win);
            sBase[i] = ((tin << 10) + (hin << 5) + win) << 9;
        }
        __syncthreads();
    }

    auto load_chunk = [&](int c, int buf) {
        const uint32_t tbu = tbase + buf * STAGEB;
        const long kkB = (long)c << 6;
        const int tap = c >> 3, c0 = (c & 7) << 6;
#pragma unroll
        for (int it = 0; it < BM / 64; it++) {
            const int i = it * 512 + tid;
            const int row = i >> 3, seg = i & 7;
            long offA;
            if (gather) offA = (long)sBase[row * 27 + tap] + c0 + (seg << 3);
            else        offA = (long)(m0 + row) * ldA + kkB + (seg << 3);
            const uint32_t d = SWZ128((uint32_t)(row * 128 + seg * 16));
            cp16(tbu + d,          AHi + offA);
            cp16(tbu + ABYTES + d, ALo + offA);
        }
#pragma unroll
        for (int it = 0; it < 4; it++) {
            const int i = it * 512 + tid;
            const int row = i >> 3, seg = i & 7;
            const long offB = (long)(n0 + row) * ldB + kkB + (seg << 3);
            const uint32_t d = SWZ128((uint32_t)(row * 128 + seg * 16));
            cp16(tbu + 2 * ABYTES + d,         BHi + offB);
            cp16(tbu + 2 * ABYTES + 32768 + d, BLo + offB);
        }
    };

    float acc[4][NT][4];
#pragma unroll
    for (int a = 0; a < 4; a++)
#pragma unroll
        for (int b = 0; b < NT; b++)
#pragma unroll
            for (int i = 0; i < 4; i++) acc[a][b][i] = 0.0f;

    const int a_r = lid & 15, a_ko = (lid >> 4) * 16;
    const int b_r = ((lid >> 4) << 3) + (lid & 7);
    const int b_ko = ((lid >> 3) & 1) * 16;

    const int nc = Keff >> 6;
    load_chunk(0, 0);
    CP_COMMIT();

    for (int c = 0; c < nc; c++) {
        if (c + 1 < nc) { load_chunk(c + 1, (c + 1) & 1); CP_COMMIT(); CP_WAIT1(); }
        else            { CP_WAIT0(); }
        __syncthreads();

        const uint32_t tbu = tbase + (c & 1) * STAGEB;
#pragma unroll
        for (int ks = 0; ks < 4; ks++) {
            const int kb = ks * 32;
            uint32_t ah[4][4], al[4][4];
#pragma unroll
            for (int mt = 0; mt < 4; mt++) {
                const int row = wm * 64 + mt * 16 + a_r;
                const uint32_t off = SWZ128((uint32_t)(row * 128 + kb + a_ko));
                LDSM_X4(ah[mt], tbu + off);
                LDSM_X4(al[mt], tbu + ABYTES + off);
            }
#pragma unroll
            for (int p = 0; p < NP; p++) {
                const int row = wn * WNW + p * 16 + b_r;
                const uint32_t off = SWZ128((uint32_t)(row * 128 + kb + b_ko));
                uint32_t rh[4], rl[4];
                LDSM_X4(rh, tbu + 2 * ABYTES + off);
                LDSM_X4(rl, tbu + 2 * ABYTES + 32768 + off);
#pragma unroll
                for (int mt = 0; mt < 4; mt++) {
                    mma16816(acc[mt][2*p],   ah[mt], rh);
                    mma16816(acc[mt][2*p],   ah[mt], rl);
                    mma16816(acc[mt][2*p],   al[mt], rh);
                    mma16816(acc[mt][2*p+1], ah[mt], rh + 2);
                    mma16816(acc[mt][2*p+1], ah[mt], rl + 2);
                    mma16816(acc[mt][2*p+1], al[mt], rh + 2);
                }
            }
        }
        __syncthreads();
    }

    const int er = lid >> 2, ec = (lid & 3) * 2;
#pragma unroll
    for (int mt = 0; mt < 4; mt++) {
#pragma unroll
        for (int nt = 0; nt < NT; nt++) {
            const int n = n0 + wn * WNW + nt * 8 + ec;
            float b0 = 0.f, b1 = 0.f;
            if (bias) { b0 = bias[n]; b1 = bias[n + 1]; }
#pragma unroll
            for (int half = 0; half < 2; half++) {
                const int m = m0 + wm * 64 + mt * 16 + er + half * 8;
                float v0 = acc[mt][nt][half * 2 + 0] * scale + b0;
                float v1 = acc[mt][nt][half * 2 + 1] * scale + b1;
                if (resid) {
                    const float2 rv = *(const float2*)(resid + (size_t)m * ldc + n);
                    v0 += rv.x; v1 += rv.y;
                }
                if (C)
                    *(float2*)(C + (size_t)m * ldc + n) = make_float2(v0, v1);
                if (outHi) {
                    bf16 h0 = __float2bfloat16(v0), h1 = __float2bfloat16(v1);
                    __nv_bfloat162 hh; hh.x = h0; hh.y = h1;
                    __nv_bfloat162 ll;
                    ll.x = __float2bfloat16(v0 - __bfloat162float(h0));
                    ll.y = __float2bfloat16(v1 - __bfloat162float(h1));
                    *(__nv_bfloat162*)(outHi + (size_t)m * ldc + n) = hh;
                    *(__nv_bfloat162*)(outLo + (size_t)m * ldc + n) = ll;
                }
            }
        }
    }
}

// ---------------- persistent balanced split-K conv GEMM ----------------
// 128x256 tiles, 2 n-tiles x 64 m-tiles = 128 tiles x 216 chunks = 27648 units
// spread evenly over nW workers; partial tiles accumulated via atomicAdd into
// pre-zeroed C. Segment with c0==0 contributes bias (+resid).
__global__ __launch_bounds__(512) void tc_conv_ps(
    const bf16* __restrict__ AHi, const bf16* __restrict__ ALo,
    const bf16* __restrict__ BHi, const bf16* __restrict__ BLo,
    const float* __restrict__ bias, const float* __restrict__ resid,
    float* __restrict__ C, int nW)
{
    constexpr int ABYTES = 128 * 128;             // 16384
    constexpr int STAGEB = 2 * ABYTES + 65536;    // 98304

    extern __shared__ char smem[];
    const uint32_t sb = smem_u32(smem);
    const uint32_t tbase = (sb + 1023) & ~1023u;
    char* tiles = smem + (tbase - sb);
    int* sBase = (int*)(tiles + 2 * STAGEB);

    const int tid = threadIdx.x, wid = tid >> 5, lid = tid & 31;
    const int wm = wid >> 3, wn = wid & 7;        // 2x8 warps, 64x32 warp tiles
    const int a_r = lid & 15, a_ko = (lid >> 4) * 16;
    const int b_r = ((lid >> 4) << 3) + (lid & 7);
    const int b_ko = ((lid >> 3) & 1) * 16;
    const int er = lid >> 2, ec = (lid & 3) * 2;

    const long TC = 128L * 216;
    const long u0 = (long)blockIdx.x * TC / nW;
    const long u1 = (long)(blockIdx.x + 1) * TC / nW;
    if (u1 <= u0) return;
    const int t0 = (int)(u0 / 216), t1 = (int)((u1 - 1) / 216);

    for (int tau = t0; tau <= t1; tau++) {
        const int c0 = (tau == t0) ? (int)(u0 - (long)tau * 216) : 0;
        const int c1 = (tau == t1) ? (int)(u1 - (long)tau * 216) : 216;
        const int m0 = (tau >> 1) * 128, n0 = (tau & 1) * 256;

        // tap table for this m-tile
        for (int i = tid; i < 128 * 27; i += 512) {
            const int mloc = i / 27, tap = i - mloc * 27;
            const int m = m0 + mloc;
            const int kt = tap / 9, r9 = tap - kt * 9, kh = r9 / 3, kw = r9 - kh * 3;
            const int t = m >> 10, hw = m & 1023, h = hw >> 5, w = hw & 31;
            int tin = t + kt - 2; tin = tin < 0 ? 0 : tin;
            int hin = h + kh - 1; hin = hin < 0 ? 0 : (hin > 31 ? 31 : hin);
            int win = w + kw - 1; win = win < 0 ? 0 : (win > 31 ? 31 : win);
            sBase[i] = ((tin << 10) + (hin << 5) + win) << 9;
        }
        __syncthreads();

        auto load_chunk = [&](int c, int buf) {
            const uint32_t tbu = tbase + buf * STAGEB;
            const long kkB = (long)c << 6;
            const int tap = c >> 3, cc0 = (c & 7) << 6;
#pragma unroll
            for (int it = 0; it < 2; it++) {
                const int i = it * 512 + tid;
                const int row = i >> 3, seg = i & 7;
                const long offA = (long)sBase[row * 27 + tap] + cc0 + (seg << 3);
                const uint32_t d = SWZ128((uint32_t)(row * 128 + seg * 16));
                cp16(tbu + d,          AHi + offA);
                cp16(tbu + ABYTES + d, ALo + offA);
            }
#pragma unroll
            for (int it = 0; it < 4; it++) {
                const int i = it * 512 + tid;
                const int row = i >> 3, seg = i & 7;
                const long offB = (long)(n0 + row) * CONVK + kkB + (seg << 3);
                const uint32_t d = SWZ128((uint32_t)(row * 128 + seg * 16));
                cp16(tbu + 2 * ABYTES + d,         BHi + offB);
                cp16(tbu + 2 * ABYTES + 32768 + d, BLo + offB);
            }
        };

        float acc[4][4][4];
#pragma unroll
        for (int a = 0; a < 4; a++)
#pragma unroll
            for (int b = 0; b < 4; b++)
#pragma unroll
                for (int i = 0; i < 4; i++) acc[a][b][i] = 0.0f;

        load_chunk(c0, c0 & 1);
        CP_COMMIT();

        for (int c = c0; c < c1; c++) {
            if (c + 1 < c1) { load_chunk(c + 1, (c + 1) & 1); CP_COMMIT(); CP_WAIT1(); }
            else            { CP_WAIT0(); }
            __syncthreads();

            const uint32_t tbu = tbase + (c & 1) * STAGEB;
#pragma unroll
            for (int ks = 0; ks < 4; ks++) {
                const int kb = ks * 32;
                uint32_t ah[4][4], al[4][4];
#pragma unroll
                for (int mt = 0; mt < 4; mt++) {
                    const int row = wm * 64 + mt * 16 + a_r;
                    const uint32_t off = SWZ128((uint32_t)(row * 128 + kb + a_ko));
                    LDSM_X4(ah[mt], tbu + off);
                    LDSM_X4(al[mt], tbu + ABYTES + off);
                }
#pragma unroll
                for (int p = 0; p < 2; p++) {
                    const int row = wn * 32 + p * 16 + b_r;
                    const uint32_t off = SWZ128((uint32_t)(row * 128 + kb + b_ko));
                    uint32_t rh[4], rl[4];
                    LDSM_X4(rh, tbu + 2 * ABYTES + off);
                    LDSM_X4(rl, tbu + 2 * ABYTES + 32768 + off);
#pragma unroll
                    for (int mt = 0; mt < 4; mt++) {
                        mma16816(acc[mt][2*p],   ah[mt], rh);
                        mma16816(acc[mt][2*p],   ah[mt], rl);
                        mma16816(acc[mt][2*p],   al[mt], rh);
                        mma16816(acc[mt][2*p+1], ah[mt], rh + 2);
                        mma16816(acc[mt][2*p+1], ah[mt], rl + 2);
                        mma16816(acc[mt][2*p+1], al[mt], rh + 2);
                    }
                }
            }
            __syncthreads();
        }

        // atomic epilogue (bias/resid from the c0==0 segment only)
        const bool lead = (c0 == 0);
#pragma unroll
        for (int mt = 0; mt < 4; mt++) {
#pragma unroll
            for (int nt = 0; nt < 4; nt++) {
                const int n = n0 + wn * 32 + nt * 8 + ec;
                float b0 = 0.f, b1 = 0.f;
                if (lead) { b0 = bias[n]; b1 = bias[n + 1]; }
#pragma unroll
                for (int half = 0; half < 2; half++) {
                    const int m = m0 + wm * 64 + mt * 16 + er + half * 8;
                    float v0 = acc[mt][nt][half * 2 + 0] + b0;
                    float v1 = acc[mt][nt][half * 2 + 1] + b1;
                    if (lead && resid) {
                        const float2 rv = *(const float2*)(resid + (size_t)m * CCH + n);
                        v0 += rv.x; v1 += rv.y;
                    }
                    atomicAdd(C + (size_t)m * CCH + n,     v0);
                    atomicAdd(C + (size_t)m * CCH + n + 1, v1);
                }
            }
        }
        __syncthreads();
    }
}

// ---------------- host orchestration ----------------
extern "C" void kernel_launch(void* const* d_in, const int* in_sizes, int n_in,
                              void* d_out, int out_size)
{
    const float* x    = (const float*)d_in[0];
    const float* r1g1 = (const float*)d_in[1];
    const float* r1w1 = (const float*)d_in[2];
    const float* r1b1 = (const float*)d_in[3];
    const float* r1g2 = (const float*)d_in[4];
    const float* r1w2 = (const float*)d_in[5];
    const float* r1b2 = (const float*)d_in[6];
    const float* atg  = (const float*)d_in[7];
    const float* qw   = (const float*)d_in[8];
    const float* qb   = (const float*)d_in[9];
    const float* kw   = (const float*)d_in[10];
    const float* kb   = (const float*)d_in[11];
    const float* vw   = (const float*)d_in[12];
    const float* vb   = (const float*)d_in[13];
    const float* pw   = (const float*)d_in[14];
    const float* pb   = (const float*)d_in[15];
    const float* r2g1 = (const float*)d_in[16];
    const float* r2w1 = (const float*)d_in[17];
    const float* r2b1 = (const float*)d_in[18];
    const float* r2g2 = (const float*)d_in[19];
    const float* r2w2 = (const float*)d_in[20];
    const float* r2b2 = (const float*)d_in[21];
    float* out = (float*)d_out;

    bf16 *nHi, *nLo, *qHi, *qLo, *kHi, *kLo, *vtHi, *vtLo, *pHi, *pLo;
    bf16 *w1Hi, *w1Lo, *w2Hi, *w2Lo, *w3Hi, *w3Lo, *w4Hi, *w4Lo;
    bf16 *qwHi, *qwLo, *kwHi, *kwLo, *vwHi, *vwLo, *pwHi, *pwLo;
    float *s, *t, *h, *y;
    cudaGetSymbolAddress((void**)&nHi, g_nHi);  cudaGetSymbolAddress((void**)&nLo, g_nLo);
    cudaGetSymbolAddress((void**)&w1Hi, g_w1Hi); cudaGetSymbolAddress((void**)&w1Lo, g_w1Lo);
    cudaGetSymbolAddress((void**)&w2Hi, g_w2Hi); cudaGetSymbolAddress((void**)&w2Lo, g_w2Lo);
    cudaGetSymbolAddress((void**)&w3Hi, g_w3Hi); cudaGetSymbolAddress((void**)&w3Lo, g_w3Lo);
    cudaGetSymbolAddress((void**)&w4Hi, g_w4Hi); cudaGetSymbolAddress((void**)&w4Lo, g_w4Lo);
    cudaGetSymbolAddress((void**)&qwHi, g_qwHi); cudaGetSymbolAddress((void**)&qwLo, g_qwLo);
    cudaGetSymbolAddress((void**)&kwHi, g_kwHi); cudaGetSymbolAddress((void**)&kwLo, g_kwLo);
    cudaGetSymbolAddress((void**)&vwHi, g_vwHi); cudaGetSymbolAddress((void**)&vwLo, g_vwLo);
    cudaGetSymbolAddress((void**)&pwHi, g_pwHi); cudaGetSymbolAddress((void**)&pwLo, g_pwLo);
    cudaGetSymbolAddress((void**)&qHi, g_qHi);  cudaGetSymbolAddress((void**)&qLo, g_qLo);
    cudaGetSymbolAddress((void**)&kHi, g_kHi);  cudaGetSymbolAddress((void**)&kLo, g_kLo);
    cudaGetSymbolAddress((void**)&vtHi, g_vtHi); cudaGetSymbolAddress((void**)&vtLo, g_vtLo);
    cudaGetSymbolAddress((void**)&pHi, g_pHi);  cudaGetSymbolAddress((void**)&pLo, g_pLo);
    cudaGetSymbolAddress((void**)&s, g_s);
    cudaGetSymbolAddress((void**)&t, g_t);
    cudaGetSymbolAddress((void**)&h, g_h);
    cudaGetSymbolAddress((void**)&y, g_y);

    int nSM = 148;
    cudaDeviceGetAttribute(&nSM, cudaDevAttrMultiProcessorCount, 0);

    const int SMB128 = 1024 + 2 * (2 * 128 * 128 + 65536) + 128 * 27 * 4;  // 211456
    const int SMB64  = 1024 + 2 * (2 * 64 * 128 + 65536)  + 64 * 27 * 4;   // 171776
    cudaFuncSetAttribute(tc_gemm<128>, cudaFuncAttributeMaxDynamicSharedMemorySize, SMB128);
    cudaFuncSetAttribute(tc_gemm<64>,  cudaFuncAttributeMaxDynamicSharedMemorySize, SMB64);
    cudaFuncSetAttribute(tc_conv_ps,   cudaFuncAttributeMaxDynamicSharedMemorySize, SMB128);

    const dim3 gStd(2, 64);
    const dim3 gNT(32, 64);
    const dim3 gAV(2, 128);
    const dim3 tBlk(32, 8);
    const dim3 gWT3(16, 432);
    const dim3 gWT1(16, 16);
    const dim3 gVT(16, 256);
    const float rs512 = 0.04419417382415922f;
    const size_t ZB = (size_t)SPOS * CCH * sizeof(float);

    // ---- fork weight prep onto a side stream (all input-only work) ----
    cudaStream_t s2;
    cudaStreamCreateWithFlags(&s2, cudaStreamNonBlocking);
    cudaEvent_t evFork;
    cudaEventCreateWithFlags(&evFork, cudaEventDisableTiming);
    cudaEvent_t evW[8];
    for (int i = 0; i < 8; i++) cudaEventCreateWithFlags(&evW[i], cudaEventDisableTiming);

    cudaEventRecord(evFork, 0);
    cudaStreamWaitEvent(s2, evFork, 0);
    transpose_split<<<gWT3, tBlk, 0, s2>>>(r1w1, w1Hi, w1Lo, CONVK, CCH); cudaEventRecord(evW[0], s2);
    transpose_split<<<gWT3, tBlk, 0, s2>>>(r1w2, w2Hi, w2Lo, CONVK, CCH); cudaEventRecord(evW[1], s2);
    transpose_split<<<gWT1, tBlk, 0, s2>>>(qw, qwHi, qwLo, CCH, CCH);     cudaEventRecord(evW[2], s2);
    transpose_split<<<gWT1, tBlk, 0, s2>>>(kw, kwHi, kwLo, CCH, CCH);     cudaEventRecord(evW[3], s2);
    transpose_split<<<gWT1, tBlk, 0, s2>>>(vw, vwHi, vwLo, CCH, CCH);     cudaEventRecord(evW[4], s2);
    transpose_split<<<gWT1, tBlk, 0, s2>>>(pw, pwHi, pwLo, CCH, CCH);     cudaEventRecord(evW[5], s2);
    transpose_split<<<gWT3, tBlk, 0, s2>>>(r2w1, w3Hi, w3Lo, CONVK, CCH); cudaEventRecord(evW[6], s2);
    transpose_split<<<gWT3, tBlk, 0, s2>>>(r2w2, w4Hi, w4Lo, CONVK, CCH); cudaEventRecord(evW[7], s2);

    // ---- resnet 1 ----
    rmsnorm_split<<<SPOS, 128>>>(x, r1g1, nHi, nLo, 1);
    cudaMemsetAsync(h, 0, ZB, 0);
    cudaStreamWaitEvent(0, evW[0], 0);
    tc_conv_ps<<<nSM, 512, SMB128>>>(nHi, nLo, w1Hi, w1Lo, r1b1, nullptr, h, nSM);
    rmsnorm_split<<<SPOS, 128>>>(h, r1g2, nHi, nLo, 1);
    cudaMemsetAsync(y, 0, ZB, 0);
    cudaStreamWaitEvent(0, evW[1], 0);
    tc_conv_ps<<<nSM, 512, SMB128>>>(nHi, nLo, w2Hi, w2Lo, r1b2, x, y, nSM);

    // ---- attention ----
    rmsnorm_split<<<SPOS, 128>>>(y, atg, nHi, nLo, 0);
    cudaStreamWaitEvent(0, evW[2], 0);
    tc_gemm<128><<<gStd, 512, SMB128>>>(nHi, nLo, CCH, qwHi, qwLo, CCH, qb, nullptr, nullptr, qHi, qLo, CCH, CCH, 0, 1.0f);
    cudaStreamWaitEvent(0, evW[3], 0);
    tc_gemm<128><<<gStd, 512, SMB128>>>(nHi, nLo, CCH, kwHi, kwLo, CCH, kb, nullptr, nullptr, kHi, kLo, CCH, CCH, 0, 1.0f);
    cudaStreamWaitEvent(0, evW[4], 0);
    tc_gemm<128><<<gStd, 512, SMB128>>>(nHi, nLo, CCH, vwHi, vwLo, CCH, vb, nullptr, t, nullptr, nullptr, CCH, CCH, 0, 1.0f);
    transpose_split<<<gVT, tBlk>>>(t, vtHi, vtLo, SPOS, CCH);

    tc_gemm<128><<<gNT, 512, SMB128>>>(qHi, qLo, CCH, kHi, kLo, CCH, nullptr, nullptr, s, nullptr, nullptr, SPOS, CCH, TCG_CAUSAL, rs512);
    softmax_split<<<SPOS, 256>>>(s, pHi, pLo);
    tc_gemm<64><<<gAV, 512, SMB64>>>(pHi, pLo, SPOS, vtHi, vtLo, SPOS, nullptr, nullptr, nullptr, qHi, qLo, CCH, SPOS, TCG_VARK, 1.0f);
    cudaStreamWaitEvent(0, evW[5], 0);
    tc_gemm<128><<<gStd, 512, SMB128>>>(qHi, qLo, CCH, pwHi, pwLo, CCH, pb, y, h, nullptr, nullptr, CCH, CCH, 0, 1.0f);

    // ---- resnet 2 ----
    rmsnorm_split<<<SPOS, 128>>>(h, r2g1, nHi, nLo, 1);
    cudaMemsetAsync(t, 0, ZB, 0);
    cudaStreamWaitEvent(0, evW[6], 0);
    tc_conv_ps<<<nSM, 512, SMB128>>>(nHi, nLo, w3Hi, w3Lo, r2b1, nullptr, t, nSM);
    rmsnorm_split<<<SPOS, 128>>>(t, r2g2, nHi, nLo, 1);
    cudaMemsetAsync(out, 0, ZB, 0);
    cudaStreamWaitEvent(0, evW[7], 0);
    tc_conv_ps<<<nSM, 512, SMB128>>>(nHi, nLo, w4Hi, w4Lo, r2b2, h, out, nSM);
}

// round 12
// speedup vs baseline: 1.1599x; 1.0216x over previous
#include <cuda_runtime.h>
#include <cuda_bf16.h>
#include <cstdint>
#include <math.h>

#define SPOS 8192
#define CCH  512
#define CONVK 13824   // 27*512

typedef __nv_bfloat16 bf16;

// ---------------- scratch (static device memory) ----------------
__device__ __align__(256) bf16 g_nHi[SPOS*CCH], g_nLo[SPOS*CCH];
__device__ __align__(256) bf16 g_w1Hi[CCH*CONVK], g_w1Lo[CCH*CONVK];
__device__ __align__(256) bf16 g_w2Hi[CCH*CONVK], g_w2Lo[CCH*CONVK];
__device__ __align__(256) bf16 g_w3Hi[CCH*CONVK], g_w3Lo[CCH*CONVK];
__device__ __align__(256) bf16 g_w4Hi[CCH*CONVK], g_w4Lo[CCH*CONVK];
__device__ __align__(256) bf16 g_qwHi[CCH*CCH], g_qwLo[CCH*CCH];
__device__ __align__(256) bf16 g_kwHi[CCH*CCH], g_kwLo[CCH*CCH];
__device__ __align__(256) bf16 g_vwHi[CCH*CCH], g_vwLo[CCH*CCH];
__device__ __align__(256) bf16 g_pwHi[CCH*CCH], g_pwLo[CCH*CCH];
__device__ __align__(256) bf16 g_qHi[SPOS*CCH], g_qLo[SPOS*CCH];
__device__ __align__(256) bf16 g_kHi[SPOS*CCH], g_kLo[SPOS*CCH];
__device__ __align__(256) bf16 g_vtHi[SPOS*CCH], g_vtLo[SPOS*CCH];
__device__ __align__(256) bf16 g_pHi[(size_t)SPOS*SPOS], g_pLo[(size_t)SPOS*SPOS];
__device__ __align__(256) float g_s[(size_t)SPOS*SPOS];
__device__ __align__(256) float g_t[SPOS*CCH], g_h[SPOS*CCH], g_y[SPOS*CCH];

// ---------------- helpers ----------------
__device__ __forceinline__ uint32_t smem_u32(const void* p) {
    uint32_t a;
    asm("{ .reg .u64 t; cvta.to.shared.u64 t, %1; cvt.u32.u64 %0, t; }" : "=r"(a) : "l"(p));
    return a;
}
__device__ __forceinline__ void cp16(uint32_t dst, const void* src) {
    asm volatile("cp.async.cg.shared.global [%0], [%1], 16;" :: "r"(dst), "l"(src));
}
#define CP_COMMIT() asm volatile("cp.async.commit_group;" ::: "memory")
#define CP_WAIT1()  asm volatile("cp.async.wait_group 1;" ::: "memory")
#define CP_WAIT0()  asm volatile("cp.async.wait_group 0;" ::: "memory")
#define SWZ128(b) ((b) ^ (((b) >> 3) & 0x70))

#define LDSM_X4(r, addr) \
    asm volatile("ldmatrix.sync.aligned.m8n8.x4.shared.b16 {%0,%1,%2,%3}, [%4];" \
        : "=r"((r)[0]), "=r"((r)[1]), "=r"((r)[2]), "=r"((r)[3]) : "r"(addr))

__device__ __forceinline__ void mma16816(float* c, const uint32_t* a, const uint32_t* b) {
    asm volatile(
        "mma.sync.aligned.m16n8k16.row.col.f32.bf16.bf16.f32 "
        "{%0,%1,%2,%3},{%4,%5,%6,%7},{%8,%9},{%0,%1,%2,%3};"
        : "+f"(c[0]), "+f"(c[1]), "+f"(c[2]), "+f"(c[3])
        : "r"(a[0]), "r"(a[1]), "r"(a[2]), "r"(a[3]), "r"(b[0]), "r"(b[1]));
}

__device__ __forceinline__ float warpReduceSum(float v) {
#pragma unroll
    for (int o = 16; o; o >>= 1) v += __shfl_xor_sync(0xffffffffu, v, o);
    return v;
}
__device__ __forceinline__ float warpReduceMax(float v) {
#pragma unroll
    for (int o = 16; o; o >>= 1) v = fmaxf(v, __shfl_xor_sync(0xffffffffu, v, o));
    return v;
}

// ---------------- rmsnorm + silu + bf16 split ----------------
__global__ __launch_bounds__(128) void rmsnorm_split(
    const float* __restrict__ x, const float* __restrict__ g,
    bf16* __restrict__ hi, bf16* __restrict__ lo, int do_silu)
{
    __shared__ float red[4];
    const int r = blockIdx.x, tid = threadIdx.x;
    const float4 v = *(const float4*)(x + (size_t)r * CCH + tid * 4);
    float ss = v.x*v.x + v.y*v.y + v.z*v.z + v.w*v.w;
    ss = warpReduceSum(ss);
    if ((tid & 31) == 0) red[tid >> 5] = ss;
    __syncthreads();
    const float tot = red[0] + red[1] + red[2] + red[3];
    const float scale = 22.62741699796952f / (sqrtf(tot) + 1e-8f);
    const float4 gg = *(const float4*)(g + tid * 4);
    float o[4];
    o[0] = v.x*scale*gg.x; o[1] = v.y*scale*gg.y; o[2] = v.z*scale*gg.z; o[3] = v.w*scale*gg.w;
    if (do_silu) {
#pragma unroll
        for (int i = 0; i < 4; i++) o[i] = o[i] / (1.0f + __expf(-o[i]));
    }
    const size_t base = (size_t)r * CCH + tid * 4;
#pragma unroll
    for (int i = 0; i < 4; i++) {
        bf16 h = __float2bfloat16(o[i]);
        hi[base + i] = h;
        lo[base + i] = __float2bfloat16(o[i] - __bfloat162float(h));
    }
}

// ---------------- transpose + split ----------------
__global__ void transpose_split(
    const float* __restrict__ in, bf16* __restrict__ hi, bf16* __restrict__ lo, int R, int Cc)
{
    __shared__ float t[32][33];
    const int c0 = blockIdx.x * 32, r0 = blockIdx.y * 32;
    const int tx = threadIdx.x;
    for (int j = threadIdx.y; j < 32; j += 8)
        t[j][tx] = in[(size_t)(r0 + j) * Cc + c0 + tx];
    __syncthreads();
    for (int j = threadIdx.y; j < 32; j += 8) {
        float v = t[tx][j];
        bf16 h = __float2bfloat16(v);
        const size_t o = (size_t)(c0 + j) * R + r0 + tx;
        hi[o] = h;
        lo[o] = __float2bfloat16(v - __bfloat162float(h));
    }
}

// ---------------- softmax -> bf16 split probs ----------------
__global__ __launch_bounds__(256) void softmax_split(
    const float* __restrict__ S, bf16* __restrict__ PHi, bf16* __restrict__ PLo)
{
    __shared__ float red[8];
    const int r = blockIdx.x, tid = threadIdx.x;
    const int cnt = (((r >> 10) + 1) << 10) >> 8;
    const float* row = S + (size_t)r * SPOS;

    float vals[32];
    float mx = -3.4e38f;
#pragma unroll
    for (int i = 0; i < 32; i++)
        if (i < cnt) { vals[i] = row[i * 256 + tid]; mx = fmaxf(mx, vals[i]); }
    mx = warpReduceMax(mx);
    if ((tid & 31) == 0) red[tid >> 5] = mx;
    __syncthreads();
    float m2 = red[0];
#pragma unroll
    for (int i = 1; i < 8; i++) m2 = fmaxf(m2, red[i]);
    __syncthreads();
    float sum = 0.0f;
#pragma unroll
    for (int i = 0; i < 32; i++)
        if (i < cnt) { vals[i] = __expf(vals[i] - m2); sum += vals[i]; }
    sum = warpReduceSum(sum);
    if ((tid & 31) == 0) red[tid >> 5] = sum;
    __syncthreads();
    float tot = 0.0f;
#pragma unroll
    for (int i = 0; i < 8; i++) tot += red[i];
    const float inv = 1.0f / tot;
    bf16* ph = PHi + (size_t)r * SPOS;
    bf16* pl = PLo + (size_t)r * SPOS;
#pragma unroll
    for (int i = 0; i < 32; i++)
        if (i < cnt) {
            float p = vals[i] * inv;
            bf16 h = __float2bfloat16(p);
            ph[i * 256 + tid] = h;
            pl[i * 256 + tid] = __float2bfloat16(p - __bfloat162float(h));
        }
}

// ---------------- HMMA split-bf16 GEMM, CTA tile BMx256, 512 threads ----------------
#define TCG_GATHER 1
#define TCG_VARK   2
#define TCG_CAUSAL 4

template<int BM>
__global__ __launch_bounds__(512) void tc_gemm(
    const bf16* __restrict__ AHi, const bf16* __restrict__ ALo, int ldA,
    const bf16* __restrict__ BHi, const bf16* __restrict__ BLo, int ldB,
    const float* __restrict__ bias, const float* __restrict__ resid,
    float* __restrict__ C, bf16* __restrict__ outHi, bf16* __restrict__ outLo,
    int ldc, int Ktot, int flags, float scale)
{
    constexpr int WN = (BM == 128) ? 8 : 16;
    constexpr int NT = 32 / WN * 2 / 2;
    constexpr int NP = (BM == 128) ? 2 : 1;
    constexpr int WNW = 256 / WN;
    constexpr int ABYTES = BM * 128;
    constexpr int STAGEB = 2 * ABYTES + 65536;

    extern __shared__ char smem[];
    int mtile = blockIdx.y;
    if (flags & TCG_VARK) mtile = gridDim.y - 1 - blockIdx.y;
    const int m0 = mtile * BM, n0 = blockIdx.x * 256;
    if (flags & TCG_CAUSAL) { if (n0 >= (((m0 >> 10) + 1) << 10)) return; }
    int Keff = Ktot;
    if (flags & TCG_VARK)   { Keff = ((m0 >> 10) + 1) << 10; }

    const uint32_t sb = smem_u32(smem);
    const uint32_t tbase = (sb + 1023) & ~1023u;
    char* tiles = smem + (tbase - sb);
    int* sBase = (int*)(tiles + 2 * STAGEB);

    const int tid = threadIdx.x, wid = tid >> 5, lid = tid & 31;
    const int wm = wid / WN, wn = wid % WN;
    const bool gather = (flags & TCG_GATHER);

    if (gather) {
        for (int i = tid; i < BM * 27; i += 512) {
            const int mloc = i / 27, tap = i - mloc * 27;
            const int m = m0 + mloc;
            const int kt = tap / 9, r9 = tap - kt * 9, kh = r9 / 3, kw = r9 - kh * 3;
            const int t = m >> 10, hw = m & 1023, h = hw >> 5, w = hw & 31;
            int tin = t + kt - 2; tin = tin < 0 ? 0 : tin;
            int hin = h + kh - 1; hin = hin < 0 ? 0 : (hin > 31 ? 31 : hin);
            int win = w + kw - 1; win = win < 0 ? 0 : (win > 31 ? 31 : win);
            sBase[i] = ((tin << 10) + (hin << 5) + win) << 9;
        }
        __syncthreads();
    }

    auto load_chunk = [&](int c, int buf) {
        const uint32_t tbu = tbase + buf * STAGEB;
        const long kkB = (long)c << 6;
        const int tap = c >> 3, c0 = (c & 7) << 6;
#pragma unroll
        for (int it = 0; it < BM / 64; it++) {
            const int i = it * 512 + tid;
            const int row = i >> 3, seg = i & 7;
            long offA;
            if (gather) offA = (long)sBase[row * 27 + tap] + c0 + (seg << 3);
            else        offA = (long)(m0 + row) * ldA + kkB + (seg << 3);
            const uint32_t d = SWZ128((uint32_t)(row * 128 + seg * 16));
            cp16(tbu + d,          AHi + offA);
            cp16(tbu + ABYTES + d, ALo + offA);
        }
#pragma unroll
        for (int it = 0; it < 4; it++) {
            const int i = it * 512 + tid;
            const int row = i >> 3, seg = i & 7;
            const long offB = (long)(n0 + row) * ldB + kkB + (seg << 3);
            const uint32_t d = SWZ128((uint32_t)(row * 128 + seg * 16));
            cp16(tbu + 2 * ABYTES + d,         BHi + offB);
            cp16(tbu + 2 * ABYTES + 32768 + d, BLo + offB);
        }
    };

    float acc[4][NT][4];
#pragma unroll
    for (int a = 0; a < 4; a++)
#pragma unroll
        for (int b = 0; b < NT; b++)
#pragma unroll
            for (int i = 0; i < 4; i++) acc[a][b][i] = 0.0f;

    const int a_r = lid & 15, a_ko = (lid >> 4) * 16;
    const int b_r = ((lid >> 4) << 3) + (lid & 7);
    const int b_ko = ((lid >> 3) & 1) * 16;

    const int nc = Keff >> 6;
    load_chunk(0, 0);
    CP_COMMIT();

    for (int c = 0; c < nc; c++) {
        if (c + 1 < nc) { load_chunk(c + 1, (c + 1) & 1); CP_COMMIT(); CP_WAIT1(); }
        else            { CP_WAIT0(); }
        __syncthreads();

        const uint32_t tbu = tbase + (c & 1) * STAGEB;
#pragma unroll
        for (int ks = 0; ks < 4; ks++) {
            const int kb = ks * 32;
            uint32_t ah[4][4], al[4][4];
#pragma unroll
            for (int mt = 0; mt < 4; mt++) {
                const int row = wm * 64 + mt * 16 + a_r;
                const uint32_t off = SWZ128((uint32_t)(row * 128 + kb + a_ko));
                LDSM_X4(ah[mt], tbu + off);
                LDSM_X4(al[mt], tbu + ABYTES + off);
            }
#pragma unroll
            for (int p = 0; p < NP; p++) {
                const int row = wn * WNW + p * 16 + b_r;
                const uint32_t off = SWZ128((uint32_t)(row * 128 + kb + b_ko));
                uint32_t rh[4], rl[4];
                LDSM_X4(rh, tbu + 2 * ABYTES + off);
                LDSM_X4(rl, tbu + 2 * ABYTES + 32768 + off);
#pragma unroll
                for (int mt = 0; mt < 4; mt++) {
                    mma16816(acc[mt][2*p],   ah[mt], rh);
                    mma16816(acc[mt][2*p],   ah[mt], rl);
                    mma16816(acc[mt][2*p],   al[mt], rh);
                    mma16816(acc[mt][2*p+1], ah[mt], rh + 2);
                    mma16816(acc[mt][2*p+1], ah[mt], rl + 2);
                    mma16816(acc[mt][2*p+1], al[mt], rh + 2);
                }
            }
        }
        __syncthreads();
    }

    const int er = lid >> 2, ec = (lid & 3) * 2;
#pragma unroll
    for (int mt = 0; mt < 4; mt++) {
#pragma unroll
        for (int nt = 0; nt < NT; nt++) {
            const int n = n0 + wn * WNW + nt * 8 + ec;
            float b0 = 0.f, b1 = 0.f;
            if (bias) { b0 = bias[n]; b1 = bias[n + 1]; }
#pragma unroll
            for (int half = 0; half < 2; half++) {
                const int m = m0 + wm * 64 + mt * 16 + er + half * 8;
                float v0 = acc[mt][nt][half * 2 + 0] * scale + b0;
                float v1 = acc[mt][nt][half * 2 + 1] * scale + b1;
                if (resid) {
                    const float2 rv = *(const float2*)(resid + (size_t)m * ldc + n);
                    v0 += rv.x; v1 += rv.y;
                }
                if (C)
                    *(float2*)(C + (size_t)m * ldc + n) = make_float2(v0, v1);
                if (outHi) {
                    bf16 h0 = __float2bfloat16(v0), h1 = __float2bfloat16(v1);
                    __nv_bfloat162 hh; hh.x = h0; hh.y = h1;
                    __nv_bfloat162 ll;
                    ll.x = __float2bfloat16(v0 - __bfloat162float(h0));
                    ll.y = __float2bfloat16(v1 - __bfloat162float(h1));
                    *(__nv_bfloat162*)(outHi + (size_t)m * ldc + n) = hh;
                    *(__nv_bfloat162*)(outLo + (size_t)m * ldc + n) = ll;
                }
            }
        }
    }
}

// ---------------- persistent balanced split-K conv GEMM ----------------
// 128x256 tiles, 256 threads, 8 warps as 2x4, warp tile 64x64 (reduced LDSM traffic).
// 128 tiles x 216 chunks = 27648 units spread evenly over nW workers; partials
// accumulated via atomicAdd into pre-zeroed C. c0==0 segment contributes bias/resid.
__global__ __launch_bounds__(256) void tc_conv_ps(
    const bf16* __restrict__ AHi, const bf16* __restrict__ ALo,
    const bf16* __restrict__ BHi, const bf16* __restrict__ BLo,
    const float* __restrict__ bias, const float* __restrict__ resid,
    float* __restrict__ C, int nW)
{
    constexpr int ABYTES = 128 * 128;             // 16384
    constexpr int STAGEB = 2 * ABYTES + 65536;    // 98304

    extern __shared__ char smem[];
    const uint32_t sb = smem_u32(smem);
    const uint32_t tbase = (sb + 1023) & ~1023u;
    char* tiles = smem + (tbase - sb);
    int* sBase = (int*)(tiles + 2 * STAGEB);

    const int tid = threadIdx.x, wid = tid >> 5, lid = tid & 31;
    const int wm = wid >> 2, wn = wid & 3;        // 2x4 warps, 64x64 warp tiles
    const int a_r = lid & 15, a_ko = (lid >> 4) * 16;
    const int b_r = ((lid >> 4) << 3) + (lid & 7);
    const int b_ko = ((lid >> 3) & 1) * 16;
    const int er = lid >> 2, ec = (lid & 3) * 2;

    const long TC = 128L * 216;
    const long u0 = (long)blockIdx.x * TC / nW;
    const long u1 = (long)(blockIdx.x + 1) * TC / nW;
    if (u1 <= u0) return;
    const int t0 = (int)(u0 / 216), t1 = (int)((u1 - 1) / 216);

    for (int tau = t0; tau <= t1; tau++) {
        const int c0 = (tau == t0) ? (int)(u0 - (long)tau * 216) : 0;
        const int c1 = (tau == t1) ? (int)(u1 - (long)tau * 216) : 216;
        const int m0 = (tau >> 1) * 128, n0 = (tau & 1) * 256;

        for (int i = tid; i < 128 * 27; i += 256) {
            const int mloc = i / 27, tap = i - mloc * 27;
            const int m = m0 + mloc;
            const int kt = tap / 9, r9 = tap - kt * 9, kh = r9 / 3, kw = r9 - kh * 3;
            const int t = m >> 10, hw = m & 1023, h = hw >> 5, w = hw & 31;
            int tin = t + kt - 2; tin = tin < 0 ? 0 : tin;
            int hin = h + kh - 1; hin = hin < 0 ? 0 : (hin > 31 ? 31 : hin);
            int win = w + kw - 1; win = win < 0 ? 0 : (win > 31 ? 31 : win);
            sBase[i] = ((tin << 10) + (hin << 5) + win) << 9;
        }
        __syncthreads();

        auto load_chunk = [&](int c, int buf) {
            const uint32_t tbu = tbase + buf * STAGEB;
            const long kkB = (long)c << 6;
            const int tap = c >> 3, cc0 = (c & 7) << 6;
#pragma unroll
            for (int it = 0; it < 4; it++) {          // A: 128 rows x 8 segs, 256 thr
                const int i = it * 256 + tid;
                const int row = i >> 3, seg = i & 7;
                const long offA = (long)sBase[row * 27 + tap] + cc0 + (seg << 3);
                const uint32_t d = SWZ128((uint32_t)(row * 128 + seg * 16));
                cp16(tbu + d,          AHi + offA);
                cp16(tbu + ABYTES + d, ALo + offA);
            }
#pragma unroll
            for (int it = 0; it < 8; it++) {          // B: 256 rows x 8 segs
                const int i = it * 256 + tid;
                const int row = i >> 3, seg = i & 7;
                const long offB = (long)(n0 + row) * CONVK + kkB + (seg << 3);
                const uint32_t d = SWZ128((uint32_t)(row * 128 + seg * 16));
                cp16(tbu + 2 * ABYTES + d,         BHi + offB);
                cp16(tbu + 2 * ABYTES + 32768 + d, BLo + offB);
            }
        };

        float acc[4][8][4];
#pragma unroll
        for (int a = 0; a < 4; a++)
#pragma unroll
            for (int b = 0; b < 8; b++)
#pragma unroll
                for (int i = 0; i < 4; i++) acc[a][b][i] = 0.0f;

        load_chunk(c0, c0 & 1);
        CP_COMMIT();

        for (int c = c0; c < c1; c++) {
            if (c + 1 < c1) { load_chunk(c + 1, (c + 1) & 1); CP_COMMIT(); CP_WAIT1(); }
            else            { CP_WAIT0(); }
            __syncthreads();

            const uint32_t tbu = tbase + (c & 1) * STAGEB;
#pragma unroll
            for (int ks = 0; ks < 4; ks++) {
                const int kb = ks * 32;
                uint32_t ah[4][4], al[4][4];
#pragma unroll
                for (int mt = 0; mt < 4; mt++) {
                    const int row = wm * 64 + mt * 16 + a_r;
                    const uint32_t off = SWZ128((uint32_t)(row * 128 + kb + a_ko));
                    LDSM_X4(ah[mt], tbu + off);
                    LDSM_X4(al[mt], tbu + ABYTES + off);
                }
#pragma unroll
                for (int p = 0; p < 4; p++) {
                    const int row = wn * 64 + p * 16 + b_r;
                    const uint32_t off = SWZ128((uint32_t)(row * 128 + kb + b_ko));
                    uint32_t rh[4], rl[4];
                    LDSM_X4(rh, tbu + 2 * ABYTES + off);
                    LDSM_X4(rl, tbu + 2 * ABYTES + 32768 + off);
#pragma unroll
                    for (int mt = 0; mt < 4; mt++) {
                        mma16816(acc[mt][2*p],   ah[mt], rh);
                        mma16816(acc[mt][2*p],   ah[mt], rl);
                        mma16816(acc[mt][2*p],   al[mt], rh);
                        mma16816(acc[mt][2*p+1], ah[mt], rh + 2);
                        mma16816(acc[mt][2*p+1], ah[mt], rl + 2);
                        mma16816(acc[mt][2*p+1], al[mt], rh + 2);
                    }
                }
            }
            __syncthreads();
        }

        const bool lead = (c0 == 0);
#pragma unroll
        for (int mt = 0; mt < 4; mt++) {
#pragma unroll
            for (int nt = 0; nt < 8; nt++) {
                const int n = n0 + wn * 64 + nt * 8 + ec;
                float b0 = 0.f, b1 = 0.f;
                if (lead) { b0 = bias[n]; b1 = bias[n + 1]; }
#pragma unroll
                for (int half = 0; half < 2; half++) {
                    const int m = m0 + wm * 64 + mt * 16 + er + half * 8;
                    float v0 = acc[mt][nt][half * 2 + 0] + b0;
                    float v1 = acc[mt][nt][half * 2 + 1] + b1;
                    if (lead && resid) {
                        const float2 rv = *(const float2*)(resid + (size_t)m * CCH + n);
                        v0 += rv.x; v1 += rv.y;
                    }
                    atomicAdd(C + (size_t)m * CCH + n,     v0);
                    atomicAdd(C + (size_t)m * CCH + n + 1, v1);
                }
            }
        }
        __syncthreads();
    }
}

// ---------------- host orchestration ----------------
extern "C" void kernel_launch(void* const* d_in, const int* in_sizes, int n_in,
                              void* d_out, int out_size)
{
    const float* x    = (const float*)d_in[0];
    const float* r1g1 = (const float*)d_in[1];
    const float* r1w1 = (const float*)d_in[2];
    const float* r1b1 = (const float*)d_in[3];
    const float* r1g2 = (const float*)d_in[4];
    const float* r1w2 = (const float*)d_in[5];
    const float* r1b2 = (const float*)d_in[6];
    const float* atg  = (const float*)d_in[7];
    const float* qw   = (const float*)d_in[8];
    const float* qb   = (const float*)d_in[9];
    const float* kw   = (const float*)d_in[10];
    const float* kb   = (const float*)d_in[11];
    const float* vw   = (const float*)d_in[12];
    const float* vb   = (const float*)d_in[13];
    const float* pw   = (const float*)d_in[14];
    const float* pb   = (const float*)d_in[15];
    const float* r2g1 = (const float*)d_in[16];
    const float* r2w1 = (const float*)d_in[17];
    const float* r2b1 = (const float*)d_in[18];
    const float* r2g2 = (const float*)d_in[19];
    const float* r2w2 = (const float*)d_in[20];
    const float* r2b2 = (const float*)d_in[21];
    float* out = (float*)d_out;

    bf16 *nHi, *nLo, *qHi, *qLo, *kHi, *kLo, *vtHi, *vtLo, *pHi, *pLo;
    bf16 *w1Hi, *w1Lo, *w2Hi, *w2Lo, *w3Hi, *w3Lo, *w4Hi, *w4Lo;
    bf16 *qwHi, *qwLo, *kwHi, *kwLo, *vwHi, *vwLo, *pwHi, *pwLo;
    float *s, *t, *h, *y;
    cudaGetSymbolAddress((void**)&nHi, g_nHi);  cudaGetSymbolAddress((void**)&nLo, g_nLo);
    cudaGetSymbolAddress((void**)&w1Hi, g_w1Hi); cudaGetSymbolAddress((void**)&w1Lo, g_w1Lo);
    cudaGetSymbolAddress((void**)&w2Hi, g_w2Hi); cudaGetSymbolAddress((void**)&w2Lo, g_w2Lo);
    cudaGetSymbolAddress((void**)&w3Hi, g_w3Hi); cudaGetSymbolAddress((void**)&w3Lo, g_w3Lo);
    cudaGetSymbolAddress((void**)&w4Hi, g_w4Hi); cudaGetSymbolAddress((void**)&w4Lo, g_w4Lo);
    cudaGetSymbolAddress((void**)&qwHi, g_qwHi); cudaGetSymbolAddress((void**)&qwLo, g_qwLo);
    cudaGetSymbolAddress((void**)&kwHi, g_kwHi); cudaGetSymbolAddress((void**)&kwLo, g_kwLo);
    cudaGetSymbolAddress((void**)&vwHi, g_vwHi); cudaGetSymbolAddress((void**)&vwLo, g_vwLo);
    cudaGetSymbolAddress((void**)&pwHi, g_pwHi); cudaGetSymbolAddress((void**)&pwLo, g_pwLo);
    cudaGetSymbolAddress((void**)&qHi, g_qHi);  cudaGetSymbolAddress((void**)&qLo, g_qLo);
    cudaGetSymbolAddress((void**)&kHi, g_kHi);  cudaGetSymbolAddress((void**)&kLo, g_kLo);
    cudaGetSymbolAddress((void**)&vtHi, g_vtHi); cudaGetSymbolAddress((void**)&vtLo, g_vtLo);
    cudaGetSymbolAddress((void**)&pHi, g_pHi);  cudaGetSymbolAddress((void**)&pLo, g_pLo);
    cudaGetSymbolAddress((void**)&s, g_s);
    cudaGetSymbolAddress((void**)&t, g_t);
    cudaGetSymbolAddress((void**)&h, g_h);
    cudaGetSymbolAddress((void**)&y, g_y);

    int nSM = 148;
    cudaDeviceGetAttribute(&nSM, cudaDevAttrMultiProcessorCount, 0);

    const int SMB128 = 1024 + 2 * (2 * 128 * 128 + 65536) + 128 * 27 * 4;  // 211456
    const int SMB64  = 1024 + 2 * (2 * 64 * 128 + 65536)  + 64 * 27 * 4;   // 171776
    cudaFuncSetAttribute(tc_gemm<128>, cudaFuncAttributeMaxDynamicSharedMemorySize, SMB128);
    cudaFuncSetAttribute(tc_gemm<64>,  cudaFuncAttributeMaxDynamicSharedMemorySize, SMB64);
    cudaFuncSetAttribute(tc_conv_ps,   cudaFuncAttributeMaxDynamicSharedMemorySize, SMB128);

    const dim3 gStd(2, 64);
    const dim3 gNT(32, 64);
    const dim3 gAV(2, 128);
    const dim3 tBlk(32, 8);
    const dim3 gWT3(16, 432);
    const dim3 gWT1(16, 16);
    const dim3 gVT(16, 256);
    const float rs512 = 0.04419417382415922f;
    const size_t ZB = (size_t)SPOS * CCH * sizeof(float);

    // ---- fork weight prep onto a side stream (all input-only work) ----
    cudaStream_t s2;
    cudaStreamCreateWithFlags(&s2, cudaStreamNonBlocking);
    cudaEvent_t evFork;
    cudaEventCreateWithFlags(&evFork, cudaEventDisableTiming);
    cudaEvent_t evW[8];
    for (int i = 0; i < 8; i++) cudaEventCreateWithFlags(&evW[i], cudaEventDisableTiming);

    cudaEventRecord(evFork, 0);
    cudaStreamWaitEvent(s2, evFork, 0);
    transpose_split<<<gWT3, tBlk, 0, s2>>>(r1w1, w1Hi, w1Lo, CONVK, CCH); cudaEventRecord(evW[0], s2);
    transpose_split<<<gWT3, tBlk, 0, s2>>>(r1w2, w2Hi, w2Lo, CONVK, CCH); cudaEventRecord(evW[1], s2);
    transpose_split<<<gWT1, tBlk, 0, s2>>>(qw, qwHi, qwLo, CCH, CCH);     cudaEventRecord(evW[2], s2);
    transpose_split<<<gWT1, tBlk, 0, s2>>>(kw, kwHi, kwLo, CCH, CCH);     cudaEventRecord(evW[3], s2);
    transpose_split<<<gWT1, tBlk, 0, s2>>>(vw, vwHi, vwLo, CCH, CCH);     cudaEventRecord(evW[4], s2);
    transpose_split<<<gWT1, tBlk, 0, s2>>>(pw, pwHi, pwLo, CCH, CCH);     cudaEventRecord(evW[5], s2);
    transpose_split<<<gWT3, tBlk, 0, s2>>>(r2w1, w3Hi, w3Lo, CONVK, CCH); cudaEventRecord(evW[6], s2);
    transpose_split<<<gWT3, tBlk, 0, s2>>>(r2w2, w4Hi, w4Lo, CONVK, CCH); cudaEventRecord(evW[7], s2);

    // ---- hoisted zero-fills for conv accumulation targets (off critical path) ----
    cudaMemsetAsync(h, 0, ZB, 0);
    cudaMemsetAsync(y, 0, ZB, 0);
    cudaMemsetAsync(out, 0, ZB, 0);

    // ---- resnet 1 ----
    rmsnorm_split<<<SPOS, 128>>>(x, r1g1, nHi, nLo, 1);
    cudaStreamWaitEvent(0, evW[0], 0);
    tc_conv_ps<<<nSM, 256, SMB128>>>(nHi, nLo, w1Hi, w1Lo, r1b1, nullptr, h, nSM);
    rmsnorm_split<<<SPOS, 128>>>(h, r1g2, nHi, nLo, 1);
    cudaStreamWaitEvent(0, evW[1], 0);
    tc_conv_ps<<<nSM, 256, SMB128>>>(nHi, nLo, w2Hi, w2Lo, r1b2, x, y, nSM);

    // ---- attention ----
    rmsnorm_split<<<SPOS, 128>>>(y, atg, nHi, nLo, 0);
    cudaStreamWaitEvent(0, evW[2], 0);
    tc_gemm<128><<<gStd, 512, SMB128>>>(nHi, nLo, CCH, qwHi, qwLo, CCH, qb, nullptr, nullptr, qHi, qLo, CCH, CCH, 0, 1.0f);
    cudaStreamWaitEvent(0, evW[3], 0);
    tc_gemm<128><<<gStd, 512, SMB128>>>(nHi, nLo, CCH, kwHi, kwLo, CCH, kb, nullptr, nullptr, kHi, kLo, CCH, CCH, 0, 1.0f);
    cudaStreamWaitEvent(0, evW[4], 0);
    tc_gemm<128><<<gStd, 512, SMB128>>>(nHi, nLo, CCH, vwHi, vwLo, CCH, vb, nullptr, t, nullptr, nullptr, CCH, CCH, 0, 1.0f);
    transpose_split<<<gVT, tBlk>>>(t, vtHi, vtLo, SPOS, CCH);

    tc_gemm<128><<<gNT, 512, SMB128>>>(qHi, qLo, CCH, kHi, kLo, CCH, nullptr, nullptr, s, nullptr, nullptr, SPOS, CCH, TCG_CAUSAL, rs512);
    softmax_split<<<SPOS, 256>>>(s, pHi, pLo);
    tc_gemm<64><<<gAV, 512, SMB64>>>(pHi, pLo, SPOS, vtHi, vtLo, SPOS, nullptr, nullptr, nullptr, qHi, qLo, CCH, SPOS, TCG_VARK, 1.0f);
    cudaStreamWaitEvent(0, evW[5], 0);
    tc_gemm<128><<<gStd, 512, SMB128>>>(qHi, qLo, CCH, pwHi, pwLo, CCH, pb, y, h, nullptr, nullptr, CCH, CCH, 0, 1.0f);

    // ---- resnet 2 ----
    rmsnorm_split<<<SPOS, 128>>>(h, r2g1, nHi, nLo, 1);
    cudaMemsetAsync(t, 0, ZB, 0);
    cudaStreamWaitEvent(0, evW[6], 0);
    tc_conv_ps<<<nSM, 256, SMB128>>>(nHi, nLo, w3Hi, w3Lo, r2b1, nullptr, t, nSM);
    rmsnorm_split<<<SPOS, 128>>>(t, r2g2, nHi, nLo, 1);
    cudaStreamWaitEvent(0, evW[7], 0);
    tc_conv_ps<<<nSM, 256, SMB128>>>(nHi, nLo, w4Hi, w4Lo, r2b2, h, out, nSM);
}

// round 13
// speedup vs baseline: 1.1639x; 1.0035x over previous
#include <cuda_runtime.h>
#include <cuda_bf16.h>
#include <cstdint>
#include <math.h>

#define SPOS 8192
#define CCH  512
#define CONVK 13824   // 27*512

typedef __nv_bfloat16 bf16;

// ---------------- scratch (static device memory) ----------------
__device__ __align__(256) bf16 g_nHi[SPOS*CCH], g_nLo[SPOS*CCH];
__device__ __align__(256) bf16 g_w1Hi[CCH*CONVK], g_w1Lo[CCH*CONVK];
__device__ __align__(256) bf16 g_w2Hi[CCH*CONVK], g_w2Lo[CCH*CONVK];
__device__ __align__(256) bf16 g_w3Hi[CCH*CONVK], g_w3Lo[CCH*CONVK];
__device__ __align__(256) bf16 g_w4Hi[CCH*CONVK], g_w4Lo[CCH*CONVK];
__device__ __align__(256) bf16 g_qwHi[CCH*CCH], g_qwLo[CCH*CCH];
__device__ __align__(256) bf16 g_kwHi[CCH*CCH], g_kwLo[CCH*CCH];
__device__ __align__(256) bf16 g_vwHi[CCH*CCH], g_vwLo[CCH*CCH];
__device__ __align__(256) bf16 g_pwHi[CCH*CCH], g_pwLo[CCH*CCH];
__device__ __align__(256) bf16 g_qHi[SPOS*CCH], g_qLo[SPOS*CCH];
__device__ __align__(256) bf16 g_kHi[SPOS*CCH], g_kLo[SPOS*CCH];
__device__ __align__(256) bf16 g_vtHi[SPOS*CCH], g_vtLo[SPOS*CCH];
__device__ __align__(256) bf16 g_pHi[(size_t)SPOS*SPOS], g_pLo[(size_t)SPOS*SPOS];
__device__ __align__(256) float g_s[(size_t)SPOS*SPOS];
__device__ __align__(256) float g_t[SPOS*CCH], g_h[SPOS*CCH], g_y[SPOS*CCH];
__device__ __align__(256) float g_o[SPOS*CCH];

// ---------------- helpers ----------------
__device__ __forceinline__ uint32_t smem_u32(const void* p) {
    uint32_t a;
    asm("{ .reg .u64 t; cvta.to.shared.u64 t, %1; cvt.u32.u64 %0, t; }" : "=r"(a) : "l"(p));
    return a;
}
__device__ __forceinline__ void cp16(uint32_t dst, const void* src) {
    asm volatile("cp.async.cg.shared.global [%0], [%1], 16;" :: "r"(dst), "l"(src));
}
#define CP_COMMIT() asm volatile("cp.async.commit_group;" ::: "memory")
#define CP_WAIT1()  asm volatile("cp.async.wait_group 1;" ::: "memory")
#define CP_WAIT0()  asm volatile("cp.async.wait_group 0;" ::: "memory")
#define SWZ128(b) ((b) ^ (((b) >> 3) & 0x70))

#define LDSM_X4(r, addr) \
    asm volatile("ldmatrix.sync.aligned.m8n8.x4.shared.b16 {%0,%1,%2,%3}, [%4];" \
        : "=r"((r)[0]), "=r"((r)[1]), "=r"((r)[2]), "=r"((r)[3]) : "r"(addr))

__device__ __forceinline__ void mma16816(float* c, const uint32_t* a, const uint32_t* b) {
    asm volatile(
        "mma.sync.aligned.m16n8k16.row.col.f32.bf16.bf16.f32 "
        "{%0,%1,%2,%3},{%4,%5,%6,%7},{%8,%9},{%0,%1,%2,%3};"
        : "+f"(c[0]), "+f"(c[1]), "+f"(c[2]), "+f"(c[3])
        : "r"(a[0]), "r"(a[1]), "r"(a[2]), "r"(a[3]), "r"(b[0]), "r"(b[1]));
}

__device__ __forceinline__ float warpReduceSum(float v) {
#pragma unroll
    for (int o = 16; o; o >>= 1) v += __shfl_xor_sync(0xffffffffu, v, o);
    return v;
}
__device__ __forceinline__ float warpReduceMax(float v) {
#pragma unroll
    for (int o = 16; o; o >>= 1) v = fmaxf(v, __shfl_xor_sync(0xffffffffu, v, o));
    return v;
}

// ---------------- rmsnorm + silu + bf16 split ----------------
__global__ __launch_bounds__(128) void rmsnorm_split(
    const float* __restrict__ x, const float* __restrict__ g,
    bf16* __restrict__ hi, bf16* __restrict__ lo, int do_silu)
{
    __shared__ float red[4];
    const int r = blockIdx.x, tid = threadIdx.x;
    const float4 v = *(const float4*)(x + (size_t)r * CCH + tid * 4);
    float ss = v.x*v.x + v.y*v.y + v.z*v.z + v.w*v.w;
    ss = warpReduceSum(ss);
    if ((tid & 31) == 0) red[tid >> 5] = ss;
    __syncthreads();
    const float tot = red[0] + red[1] + red[2] + red[3];
    const float scale = 22.62741699796952f / (sqrtf(tot) + 1e-8f);
    const float4 gg = *(const float4*)(g + tid * 4);
    float o[4];
    o[0] = v.x*scale*gg.x; o[1] = v.y*scale*gg.y; o[2] = v.z*scale*gg.z; o[3] = v.w*scale*gg.w;
    if (do_silu) {
#pragma unroll
        for (int i = 0; i < 4; i++) o[i] = o[i] / (1.0f + __expf(-o[i]));
    }
    const size_t base = (size_t)r * CCH + tid * 4;
#pragma unroll
    for (int i = 0; i < 4; i++) {
        bf16 h = __float2bfloat16(o[i]);
        hi[base + i] = h;
        lo[base + i] = __float2bfloat16(o[i] - __bfloat162float(h));
    }
}

// ---------------- plain bf16 split (layout-preserving) ----------------
__global__ __launch_bounds__(256) void split4_kernel(
    const float* __restrict__ in, bf16* __restrict__ hi, bf16* __restrict__ lo, int n4)
{
    const int i = blockIdx.x * 256 + threadIdx.x;
    if (i >= n4) return;
    const float4 v = ((const float4*)in)[i];
    float o[4] = {v.x, v.y, v.z, v.w};
    const size_t base = (size_t)i * 4;
#pragma unroll
    for (int j = 0; j < 4; j++) {
        bf16 h = __float2bfloat16(o[j]);
        hi[base + j] = h;
        lo[base + j] = __float2bfloat16(o[j] - __bfloat162float(h));
    }
}

// ---------------- transpose + split ----------------
__global__ void transpose_split(
    const float* __restrict__ in, bf16* __restrict__ hi, bf16* __restrict__ lo, int R, int Cc)
{
    __shared__ float t[32][33];
    const int c0 = blockIdx.x * 32, r0 = blockIdx.y * 32;
    const int tx = threadIdx.x;
    for (int j = threadIdx.y; j < 32; j += 8)
        t[j][tx] = in[(size_t)(r0 + j) * Cc + c0 + tx];
    __syncthreads();
    for (int j = threadIdx.y; j < 32; j += 8) {
        float v = t[tx][j];
        bf16 h = __float2bfloat16(v);
        const size_t o = (size_t)(c0 + j) * R + r0 + tx;
        hi[o] = h;
        lo[o] = __float2bfloat16(v - __bfloat162float(h));
    }
}

// ---------------- softmax -> bf16 split probs ----------------
__global__ __launch_bounds__(256) void softmax_split(
    const float* __restrict__ S, bf16* __restrict__ PHi, bf16* __restrict__ PLo)
{
    __shared__ float red[8];
    const int r = blockIdx.x, tid = threadIdx.x;
    const int cnt = (((r >> 10) + 1) << 10) >> 8;
    const float* row = S + (size_t)r * SPOS;

    float vals[32];
    float mx = -3.4e38f;
#pragma unroll
    for (int i = 0; i < 32; i++)
        if (i < cnt) { vals[i] = row[i * 256 + tid]; mx = fmaxf(mx, vals[i]); }
    mx = warpReduceMax(mx);
    if ((tid & 31) == 0) red[tid >> 5] = mx;
    __syncthreads();
    float m2 = red[0];
#pragma unroll
    for (int i = 1; i < 8; i++) m2 = fmaxf(m2, red[i]);
    __syncthreads();
    float sum = 0.0f;
#pragma unroll
    for (int i = 0; i < 32; i++)
        if (i < cnt) { vals[i] = __expf(vals[i] - m2); sum += vals[i]; }
    sum = warpReduceSum(sum);
    if ((tid & 31) == 0) red[tid >> 5] = sum;
    __syncthreads();
    float tot = 0.0f;
#pragma unroll
    for (int i = 0; i < 8; i++) tot += red[i];
    const float inv = 1.0f / tot;
    bf16* ph = PHi + (size_t)r * SPOS;
    bf16* pl = PLo + (size_t)r * SPOS;
#pragma unroll
    for (int i = 0; i < 32; i++)
        if (i < cnt) {
            float p = vals[i] * inv;
            bf16 h = __float2bfloat16(p);
            ph[i * 256 + tid] = h;
            pl[i * 256 + tid] = __float2bfloat16(p - __bfloat162float(h));
        }
}

// ---------------- HMMA split-bf16 GEMM, CTA tile BMx256, 512 threads ----------------
#define TCG_GATHER 1
#define TCG_VARK   2
#define TCG_CAUSAL 4

template<int BM>
__global__ __launch_bounds__(512) void tc_gemm(
    const bf16* __restrict__ AHi, const bf16* __restrict__ ALo, int ldA,
    const bf16* __restrict__ BHi, const bf16* __restrict__ BLo, int ldB,
    const float* __restrict__ bias, const float* __restrict__ resid,
    float* __restrict__ C, bf16* __restrict__ outHi, bf16* __restrict__ outLo,
    int ldc, int Ktot, int flags, float scale)
{
    constexpr int WN = (BM == 128) ? 8 : 16;
    constexpr int NT = 32 / WN * 2 / 2;
    constexpr int NP = (BM == 128) ? 2 : 1;
    constexpr int WNW = 256 / WN;
    constexpr int ABYTES = BM * 128;
    constexpr int STAGEB = 2 * ABYTES + 65536;

    extern __shared__ char smem[];
    int mtile = blockIdx.y;
    if (flags & TCG_VARK) mtile = gridDim.y - 1 - blockIdx.y;
    const int m0 = mtile * BM, n0 = blockIdx.x * 256;
    if (flags & TCG_CAUSAL) { if (n0 >= (((m0 >> 10) + 1) << 10)) return; }
    int Keff = Ktot;
    if (flags & TCG_VARK)   { Keff = ((m0 >> 10) + 1) << 10; }

    const uint32_t sb = smem_u32(smem);
    const uint32_t tbase = (sb + 1023) & ~1023u;
    char* tiles = smem + (tbase - sb);
    int* sBase = (int*)(tiles + 2 * STAGEB);

    const int tid = threadIdx.x, wid = tid >> 5, lid = tid & 31;
    const int wm = wid / WN, wn = wid % WN;
    const bool gather = (flags & TCG_GATHER);

    if (gather) {
        for (int i = tid; i < BM * 27; i += 512) {
            const int mloc = i / 27, tap = i - mloc * 27;
            const int m = m0 + mloc;
            const int kt = tap / 9, r9 = tap - kt * 9, kh = r9 / 3, kw = r9 - kh * 3;
            const int t = m >> 10, hw = m & 1023, h = hw >> 5, w = hw & 31;
            int tin = t + kt - 2; tin = tin < 0 ? 0 : tin;
            int hin = h + kh - 1; hin = hin < 0 ? 0 : (hin > 31 ? 31 : hin);
            int win = w + kw - 1; win = win < 0 ? 0 : (win > 31 ? 31 : win);
            sBase[i] = ((tin << 10) + (hin << 5) + win) << 9;
        }
        __syncthreads();
    }

    auto load_chunk = [&](int c, int buf) {
        const uint32_t tbu = tbase + buf * STAGEB;
        const long kkB = (long)c << 6;
        const int tap = c >> 3, c0 = (c & 7) << 6;
#pragma unroll
        for (int it = 0; it < BM / 64; it++) {
            const int i = it * 512 + tid;
            const int row = i >> 3, seg = i & 7;
            long offA;
            if (gather) offA = (long)sBase[row * 27 + tap] + c0 + (seg << 3);
            else        offA = (long)(m0 + row) * ldA + kkB + (seg << 3);
            const uint32_t d = SWZ128((uint32_t)(row * 128 + seg * 16));
            cp16(tbu + d,          AHi + offA);
            cp16(tbu + ABYTES + d, ALo + offA);
        }
#pragma unroll
        for (int it = 0; it < 4; it++) {
            const int i = it * 512 + tid;
            const int row = i >> 3, seg = i & 7;
            const long offB = (long)(n0 + row) * ldB + kkB + (seg << 3);
            const uint32_t d = SWZ128((uint32_t)(row * 128 + seg * 16));
            cp16(tbu + 2 * ABYTES + d,         BHi + offB);
            cp16(tbu + 2 * ABYTES + 32768 + d, BLo + offB);
        }
    };

    float acc[4][NT][4];
#pragma unroll
    for (int a = 0; a < 4; a++)
#pragma unroll
        for (int b = 0; b < NT; b++)
#pragma unroll
            for (int i = 0; i < 4; i++) acc[a][b][i] = 0.0f;

    const int a_r = lid & 15, a_ko = (lid >> 4) * 16;
    const int b_r = ((lid >> 4) << 3) + (lid & 7);
    const int b_ko = ((lid >> 3) & 1) * 16;

    const int nc = Keff >> 6;
    load_chunk(0, 0);
    CP_COMMIT();

    for (int c = 0; c < nc; c++) {
        if (c + 1 < nc) { load_chunk(c + 1, (c + 1) & 1); CP_COMMIT(); CP_WAIT1(); }
        else            { CP_WAIT0(); }
        __syncthreads();

        const uint32_t tbu = tbase + (c & 1) * STAGEB;
#pragma unroll
        for (int ks = 0; ks < 4; ks++) {
            const int kb = ks * 32;
            uint32_t ah[4][4], al[4][4];
#pragma unroll
            for (int mt = 0; mt < 4; mt++) {
                const int row = wm * 64 + mt * 16 + a_r;
                const uint32_t off = SWZ128((uint32_t)(row * 128 + kb + a_ko));
                LDSM_X4(ah[mt], tbu + off);
                LDSM_X4(al[mt], tbu + ABYTES + off);
            }
#pragma unroll
            for (int p = 0; p < NP; p++) {
                const int row = wn * WNW + p * 16 + b_r;
                const uint32_t off = SWZ128((uint32_t)(row * 128 + kb + b_ko));
                uint32_t rh[4], rl[4];
                LDSM_X4(rh, tbu + 2 * ABYTES + off);
                LDSM_X4(rl, tbu + 2 * ABYTES + 32768 + off);
#pragma unroll
                for (int mt = 0; mt < 4; mt++) {
                    mma16816(acc[mt][2*p],   ah[mt], rh);
                    mma16816(acc[mt][2*p],   ah[mt], rl);
                    mma16816(acc[mt][2*p],   al[mt], rh);
                    mma16816(acc[mt][2*p+1], ah[mt], rh + 2);
                    mma16816(acc[mt][2*p+1], ah[mt], rl + 2);
                    mma16816(acc[mt][2*p+1], al[mt], rh + 2);
                }
            }
        }
        __syncthreads();
    }

    const int er = lid >> 2, ec = (lid & 3) * 2;
#pragma unroll
    for (int mt = 0; mt < 4; mt++) {
#pragma unroll
        for (int nt = 0; nt < NT; nt++) {
            const int n = n0 + wn * WNW + nt * 8 + ec;
            float b0 = 0.f, b1 = 0.f;
            if (bias) { b0 = bias[n]; b1 = bias[n + 1]; }
#pragma unroll
            for (int half = 0; half < 2; half++) {
                const int m = m0 + wm * 64 + mt * 16 + er + half * 8;
                float v0 = acc[mt][nt][half * 2 + 0] * scale + b0;
                float v1 = acc[mt][nt][half * 2 + 1] * scale + b1;
                if (resid) {
                    const float2 rv = *(const float2*)(resid + (size_t)m * ldc + n);
                    v0 += rv.x; v1 += rv.y;
                }
                if (C)
                    *(float2*)(C + (size_t)m * ldc + n) = make_float2(v0, v1);
                if (outHi) {
                    bf16 h0 = __float2bfloat16(v0), h1 = __float2bfloat16(v1);
                    __nv_bfloat162 hh; hh.x = h0; hh.y = h1;
                    __nv_bfloat162 ll;
                    ll.x = __float2bfloat16(v0 - __bfloat162float(h0));
                    ll.y = __float2bfloat16(v1 - __bfloat162float(h1));
                    *(__nv_bfloat162*)(outHi + (size_t)m * ldc + n) = hh;
                    *(__nv_bfloat162*)(outLo + (size_t)m * ldc + n) = ll;
                }
            }
        }
    }
}

// ---------------- persistent balanced split-K conv GEMM (128x256, 2x4 warps) ----------------
__global__ __launch_bounds__(256) void tc_conv_ps(
    const bf16* __restrict__ AHi, const bf16* __restrict__ ALo,
    const bf16* __restrict__ BHi, const bf16* __restrict__ BLo,
    const float* __restrict__ bias, const float* __restrict__ resid,
    float* __restrict__ C, int nW)
{
    constexpr int ABYTES = 128 * 128;
    constexpr int STAGEB = 2 * ABYTES + 65536;

    extern __shared__ char smem[];
    const uint32_t sb = smem_u32(smem);
    const uint32_t tbase = (sb + 1023) & ~1023u;
    char* tiles = smem + (tbase - sb);
    int* sBase = (int*)(tiles + 2 * STAGEB);

    const int tid = threadIdx.x, wid = tid >> 5, lid = tid & 31;
    const int wm = wid >> 2, wn = wid & 3;
    const int a_r = lid & 15, a_ko = (lid >> 4) * 16;
    const int b_r = ((lid >> 4) << 3) + (lid & 7);
    const int b_ko = ((lid >> 3) & 1) * 16;
    const int er = lid >> 2, ec = (lid & 3) * 2;

    const long TC = 128L * 216;
    const long u0 = (long)blockIdx.x * TC / nW;
    const long u1 = (long)(blockIdx.x + 1) * TC / nW;
    if (u1 <= u0) return;
    const int t0 = (int)(u0 / 216), t1 = (int)((u1 - 1) / 216);

    for (int tau = t0; tau <= t1; tau++) {
        const int c0 = (tau == t0) ? (int)(u0 - (long)tau * 216) : 0;
        const int c1 = (tau == t1) ? (int)(u1 - (long)tau * 216) : 216;
        const int m0 = (tau >> 1) * 128, n0 = (tau & 1) * 256;

        for (int i = tid; i < 128 * 27; i += 256) {
            const int mloc = i / 27, tap = i - mloc * 27;
            const int m = m0 + mloc;
            const int kt = tap / 9, r9 = tap - kt * 9, kh = r9 / 3, kw = r9 - kh * 3;
            const int t = m >> 10, hw = m & 1023, h = hw >> 5, w = hw & 31;
            int tin = t + kt - 2; tin = tin < 0 ? 0 : tin;
            int hin = h + kh - 1; hin = hin < 0 ? 0 : (hin > 31 ? 31 : hin);
            int win = w + kw - 1; win = win < 0 ? 0 : (win > 31 ? 31 : win);
            sBase[i] = ((tin << 10) + (hin << 5) + win) << 9;
        }
        __syncthreads();

        auto load_chunk = [&](int c, int buf) {
            const uint32_t tbu = tbase + buf * STAGEB;
            const long kkB = (long)c << 6;
            const int tap = c >> 3, cc0 = (c & 7) << 6;
#pragma unroll
            for (int it = 0; it < 4; it++) {
                const int i = it * 256 + tid;
                const int row = i >> 3, seg = i & 7;
                const long offA = (long)sBase[row * 27 + tap] + cc0 + (seg << 3);
                const uint32_t d = SWZ128((uint32_t)(row * 128 + seg * 16));
                cp16(tbu + d,          AHi + offA);
                cp16(tbu + ABYTES + d, ALo + offA);
            }
#pragma unroll
            for (int it = 0; it < 8; it++) {
                const int i = it * 256 + tid;
                const int row = i >> 3, seg = i & 7;
                const long offB = (long)(n0 + row) * CONVK + kkB + (seg << 3);
                const uint32_t d = SWZ128((uint32_t)(row * 128 + seg * 16));
                cp16(tbu + 2 * ABYTES + d,         BHi + offB);
                cp16(tbu + 2 * ABYTES + 32768 + d, BLo + offB);
            }
        };

        float acc[4][8][4];
#pragma unroll
        for (int a = 0; a < 4; a++)
#pragma unroll
            for (int b = 0; b < 8; b++)
#pragma unroll
                for (int i = 0; i < 4; i++) acc[a][b][i] = 0.0f;

        load_chunk(c0, c0 & 1);
        CP_COMMIT();

        for (int c = c0; c < c1; c++) {
            if (c + 1 < c1) { load_chunk(c + 1, (c + 1) & 1); CP_COMMIT(); CP_WAIT1(); }
            else            { CP_WAIT0(); }
            __syncthreads();

            const uint32_t tbu = tbase + (c & 1) * STAGEB;
#pragma unroll
            for (int ks = 0; ks < 4; ks++) {
                const int kb = ks * 32;
                uint32_t ah[4][4], al[4][4];
#pragma unroll
                for (int mt = 0; mt < 4; mt++) {
                    const int row = wm * 64 + mt * 16 + a_r;
                    const uint32_t off = SWZ128((uint32_t)(row * 128 + kb + a_ko));
                    LDSM_X4(ah[mt], tbu + off);
                    LDSM_X4(al[mt], tbu + ABYTES + off);
                }
#pragma unroll
                for (int p = 0; p < 4; p++) {
                    const int row = wn * 64 + p * 16 + b_r;
                    const uint32_t off = SWZ128((uint32_t)(row * 128 + kb + b_ko));
                    uint32_t rh[4], rl[4];
                    LDSM_X4(rh, tbu + 2 * ABYTES + off);
                    LDSM_X4(rl, tbu + 2 * ABYTES + 32768 + off);
#pragma unroll
                    for (int mt = 0; mt < 4; mt++) {
                        mma16816(acc[mt][2*p],   ah[mt], rh);
                        mma16816(acc[mt][2*p],   ah[mt], rl);
                        mma16816(acc[mt][2*p],   al[mt], rh);
                        mma16816(acc[mt][2*p+1], ah[mt], rh + 2);
                        mma16816(acc[mt][2*p+1], ah[mt], rl + 2);
                        mma16816(acc[mt][2*p+1], al[mt], rh + 2);
                    }
                }
            }
            __syncthreads();
        }

        const bool lead = (c0 == 0);
#pragma unroll
        for (int mt = 0; mt < 4; mt++) {
#pragma unroll
            for (int nt = 0; nt < 8; nt++) {
                const int n = n0 + wn * 64 + nt * 8 + ec;
                float b0 = 0.f, b1 = 0.f;
                if (lead) { b0 = bias[n]; b1 = bias[n + 1]; }
#pragma unroll
                for (int half = 0; half < 2; half++) {
                    const int m = m0 + wm * 64 + mt * 16 + er + half * 8;
                    float v0 = acc[mt][nt][half * 2 + 0] + b0;
                    float v1 = acc[mt][nt][half * 2 + 1] + b1;
                    if (lead && resid) {
                        const float2 rv = *(const float2*)(resid + (size_t)m * CCH + n);
                        v0 += rv.x; v1 += rv.y;
                    }
                    atomicAdd(C + (size_t)m * CCH + n,     v0);
                    atomicAdd(C + (size_t)m * CCH + n + 1, v1);
                }
            }
        }
        __syncthreads();
    }
}

// ---------------- persistent balanced split-K A*V GEMM (varK triangular) ----------------
// Tiles: 64 m-tiles (128 rows) x 2 n-tiles; K per m-tile = (frame+1)*1024,
// frame g = mtile>>3. Group g = 16 tiles x 16(g+1) chunks; prefix P(g)=128g(g+1).
// Total units = 9216. atomicAdd partials into pre-zeroed fp32 O.
__global__ __launch_bounds__(256) void tc_av_ps(
    const bf16* __restrict__ PHi, const bf16* __restrict__ PLo,
    const bf16* __restrict__ VHi, const bf16* __restrict__ VLo,
    float* __restrict__ O, int nW)
{
    constexpr int ABYTES = 128 * 128;
    constexpr int STAGEB = 2 * ABYTES + 65536;

    extern __shared__ char smem[];
    const uint32_t sb = smem_u32(smem);
    const uint32_t tbase = (sb + 1023) & ~1023u;
    char* tiles = smem + (tbase - sb);

    const int tid = threadIdx.x, wid = tid >> 5, lid = tid & 31;
    const int wm = wid >> 2, wn = wid & 3;
    const int a_r = lid & 15, a_ko = (lid >> 4) * 16;
    const int b_r = ((lid >> 4) << 3) + (lid & 7);
    const int b_ko = ((lid >> 3) & 1) * 16;
    const int er = lid >> 2, ec = (lid & 3) * 2;

    const long TU = 9216;
    const long u0 = (long)blockIdx.x * TU / nW;
    const long u1 = (long)(blockIdx.x + 1) * TU / nW;
    long ucur = u0;

    while (ucur < u1) {
        int g = 0;
        while (g < 7 && 128L * (g + 1) * (g + 2) <= ucur) g++;
        const long Pg = 128L * g * (g + 1);
        const int L = 16 * (g + 1);
        const long rem = ucur - Pg;
        const int tl = (int)(rem / L);
        const int c0 = (int)(rem - (long)tl * L);
        int c1 = c0 + (int)(u1 - ucur);
        if (c1 > L) c1 = L;
        const int m0 = (g * 8 + (tl >> 1)) * 128;
        const int n0 = (tl & 1) * 256;

        auto load_chunk = [&](int c, int buf) {
            const uint32_t tbu = tbase + buf * STAGEB;
            const long kkB = (long)c << 6;
#pragma unroll
            for (int it = 0; it < 4; it++) {
                const int i = it * 256 + tid;
                const int row = i >> 3, seg = i & 7;
                const long offA = (long)(m0 + row) * SPOS + kkB + (seg << 3);
                const uint32_t d = SWZ128((uint32_t)(row * 128 + seg * 16));
                cp16(tbu + d,          PHi + offA);
                cp16(tbu + ABYTES + d, PLo + offA);
            }
#pragma unroll
            for (int it = 0; it < 8; it++) {
                const int i = it * 256 + tid;
                const int row = i >> 3, seg = i & 7;
                const long offB = (long)(n0 + row) * SPOS + kkB + (seg << 3);
                const uint32_t d = SWZ128((uint32_t)(row * 128 + seg * 16));
                cp16(tbu + 2 * ABYTES + d,         VHi + offB);
                cp16(tbu + 2 * ABYTES + 32768 + d, VLo + offB);
            }
        };

        float acc[4][8][4];
#pragma unroll
        for (int a = 0; a < 4; a++)
#pragma unroll
            for (int b = 0; b < 8; b++)
#pragma unroll
                for (int i = 0; i < 4; i++) acc[a][b][i] = 0.0f;

        load_chunk(c0, c0 & 1);
        CP_COMMIT();

        for (int c = c0; c < c1; c++) {
            if (c + 1 < c1) { load_chunk(c + 1, (c + 1) & 1); CP_COMMIT(); CP_WAIT1(); }
            else            { CP_WAIT0(); }
            __syncthreads();

            const uint32_t tbu = tbase + (c & 1) * STAGEB;
#pragma unroll
            for (int ks = 0; ks < 4; ks++) {
                const int kb = ks * 32;
                uint32_t ah[4][4], al[4][4];
#pragma unroll
                for (int mt = 0; mt < 4; mt++) {
                    const int row = wm * 64 + mt * 16 + a_r;
                    const uint32_t off = SWZ128((uint32_t)(row * 128 + kb + a_ko));
                    LDSM_X4(ah[mt], tbu + off);
                    LDSM_X4(al[mt], tbu + ABYTES + off);
                }
#pragma unroll
                for (int p = 0; p < 4; p++) {
                    const int row = wn * 64 + p * 16 + b_r;
                    const uint32_t off = SWZ128((uint32_t)(row * 128 + kb + b_ko));
                    uint32_t rh[4], rl[4];
                    LDSM_X4(rh, tbu + 2 * ABYTES + off);
                    LDSM_X4(rl, tbu + 2 * ABYTES + 32768 + off);
#pragma unroll
                    for (int mt = 0; mt < 4; mt++) {
                        mma16816(acc[mt][2*p],   ah[mt], rh);
                        mma16816(acc[mt][2*p],   ah[mt], rl);
                        mma16816(acc[mt][2*p],   al[mt], rh);
                        mma16816(acc[mt][2*p+1], ah[mt], rh + 2);
                        mma16816(acc[mt][2*p+1], ah[mt], rl + 2);
                        mma16816(acc[mt][2*p+1], al[mt], rh + 2);
                    }
                }
            }
            __syncthreads();
        }

#pragma unroll
        for (int mt = 0; mt < 4; mt++) {
#pragma unroll
            for (int nt = 0; nt < 8; nt++) {
                const int n = n0 + wn * 64 + nt * 8 + ec;
#pragma unroll
                for (int half = 0; half < 2; half++) {
                    const int m = m0 + wm * 64 + mt * 16 + er + half * 8;
                    atomicAdd(O + (size_t)m * CCH + n,     acc[mt][nt][half * 2 + 0]);
                    atomicAdd(O + (size_t)m * CCH + n + 1, acc[mt][nt][half * 2 + 1]);
                }
            }
        }
        __syncthreads();
        ucur += c1 - c0;
    }
}

// ---------------- host orchestration ----------------
extern "C" void kernel_launch(void* const* d_in, const int* in_sizes, int n_in,
                              void* d_out, int out_size)
{
    const float* x    = (const float*)d_in[0];
    const float* r1g1 = (const float*)d_in[1];
    const float* r1w1 = (const float*)d_in[2];
    const float* r1b1 = (const float*)d_in[3];
    const float* r1g2 = (const float*)d_in[4];
    const float* r1w2 = (const float*)d_in[5];
    const float* r1b2 = (const float*)d_in[6];
    const float* atg  = (const float*)d_in[7];
    const float* qw   = (const float*)d_in[8];
    const float* qb   = (const float*)d_in[9];
    const float* kw   = (const float*)d_in[10];
    const float* kb   = (const float*)d_in[11];
    const float* vw   = (const float*)d_in[12];
    const float* vb   = (const float*)d_in[13];
    const float* pw   = (const float*)d_in[14];
    const float* pb   = (const float*)d_in[15];
    const float* r2g1 = (const float*)d_in[16];
    const float* r2w1 = (const float*)d_in[17];
    const float* r2b1 = (const float*)d_in[18];
    const float* r2g2 = (const float*)d_in[19];
    const float* r2w2 = (const float*)d_in[20];
    const float* r2b2 = (const float*)d_in[21];
    float* out = (float*)d_out;

    bf16 *nHi, *nLo, *qHi, *qLo, *kHi, *kLo, *vtHi, *vtLo, *pHi, *pLo;
    bf16 *w1Hi, *w1Lo, *w2Hi, *w2Lo, *w3Hi, *w3Lo, *w4Hi, *w4Lo;
    bf16 *qwHi, *qwLo, *kwHi, *kwLo, *vwHi, *vwLo, *pwHi, *pwLo;
    float *s, *t, *h, *y, *o;
    cudaGetSymbolAddress((void**)&nHi, g_nHi);  cudaGetSymbolAddress((void**)&nLo, g_nLo);
    cudaGetSymbolAddress((void**)&w1Hi, g_w1Hi); cudaGetSymbolAddress((void**)&w1Lo, g_w1Lo);
    cudaGetSymbolAddress((void**)&w2Hi, g_w2Hi); cudaGetSymbolAddress((void**)&w2Lo, g_w2Lo);
    cudaGetSymbolAddress((void**)&w3Hi, g_w3Hi); cudaGetSymbolAddress((void**)&w3Lo, g_w3Lo);
    cudaGetSymbolAddress((void**)&w4Hi, g_w4Hi); cudaGetSymbolAddress((void**)&w4Lo, g_w4Lo);
    cudaGetSymbolAddress((void**)&qwHi, g_qwHi); cudaGetSymbolAddress((void**)&qwLo, g_qwLo);
    cudaGetSymbolAddress((void**)&kwHi, g_kwHi); cudaGetSymbolAddress((void**)&kwLo, g_kwLo);
    cudaGetSymbolAddress((void**)&vwHi, g_vwHi); cudaGetSymbolAddress((void**)&vwLo, g_vwLo);
    cudaGetSymbolAddress((void**)&pwHi, g_pwHi); cudaGetSymbolAddress((void**)&pwLo, g_pwLo);
    cudaGetSymbolAddress((void**)&qHi, g_qHi);  cudaGetSymbolAddress((void**)&qLo, g_qLo);
    cudaGetSymbolAddress((void**)&kHi, g_kHi);  cudaGetSymbolAddress((void**)&kLo, g_kLo);
    cudaGetSymbolAddress((void**)&vtHi, g_vtHi); cudaGetSymbolAddress((void**)&vtLo, g_vtLo);
    cudaGetSymbolAddress((void**)&pHi, g_pHi);  cudaGetSymbolAddress((void**)&pLo, g_pLo);
    cudaGetSymbolAddress((void**)&s, g_s);
    cudaGetSymbolAddress((void**)&t, g_t);
    cudaGetSymbolAddress((void**)&h, g_h);
    cudaGetSymbolAddress((void**)&y, g_y);
    cudaGetSymbolAddress((void**)&o, g_o);

    int nSM = 148;
    cudaDeviceGetAttribute(&nSM, cudaDevAttrMultiProcessorCount, 0);

    const int SMB128 = 1024 + 2 * (2 * 128 * 128 + 65536) + 128 * 27 * 4;  // 211456
    const int SMB_AV = 1024 + 2 * (2 * 128 * 128 + 65536);                 // 197632
    cudaFuncSetAttribute(tc_gemm<128>, cudaFuncAttributeMaxDynamicSharedMemorySize, SMB128);
    cudaFuncSetAttribute(tc_conv_ps,   cudaFuncAttributeMaxDynamicSharedMemorySize, SMB128);
    cudaFuncSetAttribute(tc_av_ps,     cudaFuncAttributeMaxDynamicSharedMemorySize, SMB_AV);

    const dim3 gStd(2, 64);
    const dim3 gNT(32, 64);
    const dim3 tBlk(32, 8);
    const dim3 gWT3(16, 432);
    const dim3 gWT1(16, 16);
    const dim3 gVT(16, 256);
    const float rs512 = 0.04419417382415922f;
    const size_t ZB = (size_t)SPOS * CCH * sizeof(float);
    const int n4 = SPOS * CCH / 4;

    // ---- fork weight prep onto a side stream (all input-only work) ----
    cudaStream_t s2;
    cudaStreamCreateWithFlags(&s2, cudaStreamNonBlocking);
    cudaEvent_t evFork;
    cudaEventCreateWithFlags(&evFork, cudaEventDisableTiming);
    cudaEvent_t evW[8];
    for (int i = 0; i < 8; i++) cudaEventCreateWithFlags(&evW[i], cudaEventDisableTiming);

    cudaEventRecord(evFork, 0);
    cudaStreamWaitEvent(s2, evFork, 0);
    transpose_split<<<gWT3, tBlk, 0, s2>>>(r1w1, w1Hi, w1Lo, CONVK, CCH); cudaEventRecord(evW[0], s2);
    transpose_split<<<gWT3, tBlk, 0, s2>>>(r1w2, w2Hi, w2Lo, CONVK, CCH); cudaEventRecord(evW[1], s2);
    transpose_split<<<gWT1, tBlk, 0, s2>>>(qw, qwHi, qwLo, CCH, CCH);     cudaEventRecord(evW[2], s2);
    transpose_split<<<gWT1, tBlk, 0, s2>>>(kw, kwHi, kwLo, CCH, CCH);     cudaEventRecord(evW[3], s2);
    transpose_split<<<gWT1, tBlk, 0, s2>>>(vw, vwHi, vwLo, CCH, CCH);     cudaEventRecord(evW[4], s2);
    transpose_split<<<gWT1, tBlk, 0, s2>>>(pw, pwHi, pwLo, CCH, CCH);     cudaEventRecord(evW[5], s2);
    transpose_split<<<gWT3, tBlk, 0, s2>>>(r2w1, w3Hi, w3Lo, CONVK, CCH); cudaEventRecord(evW[6], s2);
    transpose_split<<<gWT3, tBlk, 0, s2>>>(r2w2, w4Hi, w4Lo, CONVK, CCH); cudaEventRecord(evW[7], s2);

    // ---- hoisted zero-fills for accumulation targets (off critical path) ----
    cudaMemsetAsync(h, 0, ZB, 0);
    cudaMemsetAsync(y, 0, ZB, 0);
    cudaMemsetAsync(o, 0, ZB, 0);
    cudaMemsetAsync(out, 0, ZB, 0);

    // ---- resnet 1 ----
    rmsnorm_split<<<SPOS, 128>>>(x, r1g1, nHi, nLo, 1);
    cudaStreamWaitEvent(0, evW[0], 0);
    tc_conv_ps<<<nSM, 256, SMB128>>>(nHi, nLo, w1Hi, w1Lo, r1b1, nullptr, h, nSM);
    rmsnorm_split<<<SPOS, 128>>>(h, r1g2, nHi, nLo, 1);
    cudaStreamWaitEvent(0, evW[1], 0);
    tc_conv_ps<<<nSM, 256, SMB128>>>(nHi, nLo, w2Hi, w2Lo, r1b2, x, y, nSM);

    // ---- attention ----
    rmsnorm_split<<<SPOS, 128>>>(y, atg, nHi, nLo, 0);
    cudaStreamWaitEvent(0, evW[2], 0);
    tc_gemm<128><<<gStd, 512, SMB128>>>(nHi, nLo, CCH, qwHi, qwLo, CCH, qb, nullptr, nullptr, qHi, qLo, CCH, CCH, 0, 1.0f);
    cudaStreamWaitEvent(0, evW[3], 0);
    tc_gemm<128><<<gStd, 512, SMB128>>>(nHi, nLo, CCH, kwHi, kwLo, CCH, kb, nullptr, nullptr, kHi, kLo, CCH, CCH, 0, 1.0f);
    cudaStreamWaitEvent(0, evW[4], 0);
    tc_gemm<128><<<gStd, 512, SMB128>>>(nHi, nLo, CCH, vwHi, vwLo, CCH, vb, nullptr, t, nullptr, nullptr, CCH, CCH, 0, 1.0f);
    transpose_split<<<gVT, tBlk>>>(t, vtHi, vtLo, SPOS, CCH);

    tc_gemm<128><<<gNT, 512, SMB128>>>(qHi, qLo, CCH, kHi, kLo, CCH, nullptr, nullptr, s, nullptr, nullptr, SPOS, CCH, TCG_CAUSAL, rs512);
    softmax_split<<<SPOS, 256>>>(s, pHi, pLo);
    tc_av_ps<<<nSM, 256, SMB_AV>>>(pHi, pLo, vtHi, vtLo, o, nSM);
    split4_kernel<<<n4 / 256, 256>>>(o, qHi, qLo, n4);   // reuse q buffers for O split
    cudaStreamWaitEvent(0, evW[5], 0);
    tc_gemm<128><<<gStd, 512, SMB128>>>(qHi, qLo, CCH, pwHi, pwLo, CCH, pb, y, h, nullptr, nullptr, CCH, CCH, 0, 1.0f);

    // ---- resnet 2 ----
    rmsnorm_split<<<SPOS, 128>>>(h, r2g1, nHi, nLo, 1);
    cudaMemsetAsync(t, 0, ZB, 0);
    cudaStreamWaitEvent(0, evW[6], 0);
    tc_conv_ps<<<nSM, 256, SMB128>>>(nHi, nLo, w3Hi, w3Lo, r2b1, nullptr, t, nSM);
    rmsnorm_split<<<SPOS, 128>>>(t, r2g2, nHi, nLo, 1);
    cudaStreamWaitEvent(0, evW[7], 0);
    tc_conv_ps<<<nSM, 256, SMB128>>>(nHi, nLo, w4Hi, w4Lo, r2b2, h, out, nSM);
}

// round 14
// speedup vs baseline: 1.1737x; 1.0084x over previous
#include <cuda_runtime.h>
#include <cuda_bf16.h>
#include <cstdint>
#include <math.h>

#define SPOS 8192
#define CCH  512
#define CONVK 13824   // 27*512

typedef __nv_bfloat16 bf16;

// ---------------- scratch (static device memory) ----------------
__device__ __align__(256) bf16 g_nHi[SPOS*CCH], g_nLo[SPOS*CCH];
__device__ __align__(256) bf16 g_w1Hi[CCH*CONVK], g_w1Lo[CCH*CONVK];
__device__ __align__(256) bf16 g_w2Hi[CCH*CONVK], g_w2Lo[CCH*CONVK];
__device__ __align__(256) bf16 g_w3Hi[CCH*CONVK], g_w3Lo[CCH*CONVK];
__device__ __align__(256) bf16 g_w4Hi[CCH*CONVK], g_w4Lo[CCH*CONVK];
__device__ __align__(256) bf16 g_qwHi[CCH*CCH], g_qwLo[CCH*CCH];
__device__ __align__(256) bf16 g_kwHi[CCH*CCH], g_kwLo[CCH*CCH];
__device__ __align__(256) bf16 g_vwHi[CCH*CCH], g_vwLo[CCH*CCH];
__device__ __align__(256) bf16 g_pwHi[CCH*CCH], g_pwLo[CCH*CCH];
__device__ __align__(256) bf16 g_qHi[SPOS*CCH], g_qLo[SPOS*CCH];
__device__ __align__(256) bf16 g_kHi[SPOS*CCH], g_kLo[SPOS*CCH];
__device__ __align__(256) bf16 g_vtHi[SPOS*CCH], g_vtLo[SPOS*CCH];
__device__ __align__(256) bf16 g_pHi[(size_t)SPOS*SPOS], g_pLo[(size_t)SPOS*SPOS];
__device__ __align__(256) float g_s[(size_t)SPOS*SPOS];
__device__ __align__(256) float g_t[SPOS*CCH], g_h[SPOS*CCH], g_y[SPOS*CCH];
__device__ __align__(256) float g_o[SPOS*CCH];

// ---------------- helpers ----------------
__device__ __forceinline__ uint32_t smem_u32(const void* p) {
    uint32_t a;
    asm("{ .reg .u64 t; cvta.to.shared.u64 t, %1; cvt.u32.u64 %0, t; }" : "=r"(a) : "l"(p));
    return a;
}
__device__ __forceinline__ void cp16(uint32_t dst, const void* src) {
    asm volatile("cp.async.cg.shared.global [%0], [%1], 16;" :: "r"(dst), "l"(src));
}
#define CP_COMMIT() asm volatile("cp.async.commit_group;" ::: "memory")
#define CP_WAIT1()  asm volatile("cp.async.wait_group 1;" ::: "memory")
#define CP_WAIT0()  asm volatile("cp.async.wait_group 0;" ::: "memory")
#define SWZ128(b) ((b) ^ (((b) >> 3) & 0x70))

#define LDSM_X4(r, addr) \
    asm volatile("ldmatrix.sync.aligned.m8n8.x4.shared.b16 {%0,%1,%2,%3}, [%4];" \
        : "=r"((r)[0]), "=r"((r)[1]), "=r"((r)[2]), "=r"((r)[3]) : "r"(addr))

__device__ __forceinline__ void mma16816(float* c, const uint32_t* a, const uint32_t* b) {
    asm volatile(
        "mma.sync.aligned.m16n8k16.row.col.f32.bf16.bf16.f32 "
        "{%0,%1,%2,%3},{%4,%5,%6,%7},{%8,%9},{%0,%1,%2,%3};"
        : "+f"(c[0]), "+f"(c[1]), "+f"(c[2]), "+f"(c[3])
        : "r"(a[0]), "r"(a[1]), "r"(a[2]), "r"(a[3]), "r"(b[0]), "r"(b[1]));
}

__device__ __forceinline__ float warpReduceSum(float v) {
#pragma unroll
    for (int o = 16; o; o >>= 1) v += __shfl_xor_sync(0xffffffffu, v, o);
    return v;
}
__device__ __forceinline__ float warpReduceMax(float v) {
#pragma unroll
    for (int o = 16; o; o >>= 1) v = fmaxf(v, __shfl_xor_sync(0xffffffffu, v, o));
    return v;
}
__device__ __forceinline__ uint32_t pack_bf16x2(float a, float b) {
    __nv_bfloat162 h;
    h.x = __float2bfloat16(a);
    h.y = __float2bfloat16(b);
    return *(uint32_t*)&h;
}

// ---------------- rmsnorm + silu + bf16 split (packed stores) ----------------
__global__ __launch_bounds__(128) void rmsnorm_split(
    const float* __restrict__ x, const float* __restrict__ g,
    bf16* __restrict__ hi, bf16* __restrict__ lo, int do_silu)
{
    __shared__ float red[4];
    const int r = blockIdx.x, tid = threadIdx.x;
    const float4 v = *(const float4*)(x + (size_t)r * CCH + tid * 4);
    float ss = v.x*v.x + v.y*v.y + v.z*v.z + v.w*v.w;
    ss = warpReduceSum(ss);
    if ((tid & 31) == 0) red[tid >> 5] = ss;
    __syncthreads();
    const float tot = red[0] + red[1] + red[2] + red[3];
    const float scale = 22.62741699796952f / (sqrtf(tot) + 1e-8f);
    const float4 gg = *(const float4*)(g + tid * 4);
    float o[4];
    o[0] = v.x*scale*gg.x; o[1] = v.y*scale*gg.y; o[2] = v.z*scale*gg.z; o[3] = v.w*scale*gg.w;
    if (do_silu) {
#pragma unroll
        for (int i = 0; i < 4; i++) o[i] = o[i] / (1.0f + __expf(-o[i]));
    }
    const size_t base = (size_t)r * CCH + tid * 4;
    float l[4];
#pragma unroll
    for (int i = 0; i < 4; i++) {
        bf16 h = __float2bfloat16(o[i]);
        l[i] = o[i] - __bfloat162float(h);
    }
    *(uint2*)(hi + base) = make_uint2(pack_bf16x2(o[0], o[1]), pack_bf16x2(o[2], o[3]));
    *(uint2*)(lo + base) = make_uint2(pack_bf16x2(l[0], l[1]), pack_bf16x2(l[2], l[3]));
}

// ---------------- plain bf16 split (packed stores) ----------------
__global__ __launch_bounds__(256) void split4_kernel(
    const float* __restrict__ in, bf16* __restrict__ hi, bf16* __restrict__ lo, int n4)
{
    const int i = blockIdx.x * 256 + threadIdx.x;
    if (i >= n4) return;
    const float4 v = ((const float4*)in)[i];
    float o[4] = {v.x, v.y, v.z, v.w};
    float l[4];
#pragma unroll
    for (int j = 0; j < 4; j++) {
        bf16 h = __float2bfloat16(o[j]);
        l[j] = o[j] - __bfloat162float(h);
    }
    const size_t base = (size_t)i * 4;
    *(uint2*)(hi + base) = make_uint2(pack_bf16x2(o[0], o[1]), pack_bf16x2(o[2], o[3]));
    *(uint2*)(lo + base) = make_uint2(pack_bf16x2(l[0], l[1]), pack_bf16x2(l[2], l[3]));
}

// ---------------- transpose + split ----------------
__global__ void transpose_split(
    const float* __restrict__ in, bf16* __restrict__ hi, bf16* __restrict__ lo, int R, int Cc)
{
    __shared__ float t[32][33];
    const int c0 = blockIdx.x * 32, r0 = blockIdx.y * 32;
    const int tx = threadIdx.x;
    for (int j = threadIdx.y; j < 32; j += 8)
        t[j][tx] = in[(size_t)(r0 + j) * Cc + c0 + tx];
    __syncthreads();
    for (int j = threadIdx.y; j < 32; j += 8) {
        float v = t[tx][j];
        bf16 h = __float2bfloat16(v);
        const size_t o = (size_t)(c0 + j) * R + r0 + tx;
        hi[o] = h;
        lo[o] = __float2bfloat16(v - __bfloat162float(h));
    }
}

// ---------------- softmax -> bf16 split probs (vectorized, 2 cols/thread) ----------------
__global__ __launch_bounds__(256) void softmax_split(
    const float* __restrict__ S, bf16* __restrict__ PHi, bf16* __restrict__ PLo)
{
    __shared__ float red[8];
    const int r = blockIdx.x, tid = threadIdx.x;
    const int cnt = ((r >> 10) + 1) * 2;             // iterations of 512 cols
    const float* row = S + (size_t)r * SPOS;

    float2 vals[16];
    float mx = -3.4e38f;
#pragma unroll
    for (int i = 0; i < 16; i++)
        if (i < cnt) {
            vals[i] = *(const float2*)(row + i * 512 + 2 * tid);
            mx = fmaxf(mx, fmaxf(vals[i].x, vals[i].y));
        }
    mx = warpReduceMax(mx);
    if ((tid & 31) == 0) red[tid >> 5] = mx;
    __syncthreads();
    float m2 = red[0];
#pragma unroll
    for (int i = 1; i < 8; i++) m2 = fmaxf(m2, red[i]);
    __syncthreads();
    float sum = 0.0f;
#pragma unroll
    for (int i = 0; i < 16; i++)
        if (i < cnt) {
            vals[i].x = __expf(vals[i].x - m2);
            vals[i].y = __expf(vals[i].y - m2);
            sum += vals[i].x + vals[i].y;
        }
    sum = warpReduceSum(sum);
    if ((tid & 31) == 0) red[tid >> 5] = sum;
    __syncthreads();
    float tot = 0.0f;
#pragma unroll
    for (int i = 0; i < 8; i++) tot += red[i];
    const float inv = 1.0f / tot;
    bf16* ph = PHi + (size_t)r * SPOS;
    bf16* pl = PLo + (size_t)r * SPOS;
#pragma unroll
    for (int i = 0; i < 16; i++)
        if (i < cnt) {
            const float p0 = vals[i].x * inv, p1 = vals[i].y * inv;
            const bf16 h0 = __float2bfloat16(p0), h1 = __float2bfloat16(p1);
            const float l0 = p0 - __bfloat162float(h0), l1 = p1 - __bfloat162float(h1);
            __nv_bfloat162 hh; hh.x = h0; hh.y = h1;
            *(__nv_bfloat162*)(ph + i * 512 + 2 * tid) = hh;
            *(uint32_t*)(pl + i * 512 + 2 * tid) = pack_bf16x2(l0, l1);
        }
}

// ---------------- HMMA split-bf16 GEMM, CTA tile BMx256, 512 threads ----------------
#define TCG_GATHER 1
#define TCG_VARK   2
#define TCG_CAUSAL 4

template<int BM>
__global__ __launch_bounds__(512) void tc_gemm(
    const bf16* __restrict__ AHi, const bf16* __restrict__ ALo, int ldA,
    const bf16* __restrict__ BHi, const bf16* __restrict__ BLo, int ldB,
    const float* __restrict__ bias, const float* __restrict__ resid,
    float* __restrict__ C, bf16* __restrict__ outHi, bf16* __restrict__ outLo,
    int ldc, int Ktot, int flags, float scale)
{
    constexpr int WN = (BM == 128) ? 8 : 16;
    constexpr int NT = 32 / WN * 2 / 2;
    constexpr int NP = (BM == 128) ? 2 : 1;
    constexpr int WNW = 256 / WN;
    constexpr int ABYTES = BM * 128;
    constexpr int STAGEB = 2 * ABYTES + 65536;

    extern __shared__ char smem[];
    int mtile = blockIdx.y;
    if (flags & TCG_VARK) mtile = gridDim.y - 1 - blockIdx.y;
    const int m0 = mtile * BM, n0 = blockIdx.x * 256;
    if (flags & TCG_CAUSAL) { if (n0 >= (((m0 >> 10) + 1) << 10)) return; }
    int Keff = Ktot;
    if (flags & TCG_VARK)   { Keff = ((m0 >> 10) + 1) << 10; }

    const uint32_t sb = smem_u32(smem);
    const uint32_t tbase = (sb + 1023) & ~1023u;
    char* tiles = smem + (tbase - sb);
    int* sBase = (int*)(tiles + 2 * STAGEB);

    const int tid = threadIdx.x, wid = tid >> 5, lid = tid & 31;
    const int wm = wid / WN, wn = wid % WN;
    const bool gather = (flags & TCG_GATHER);

    if (gather) {
        for (int i = tid; i < BM * 27; i += 512) {
            const int mloc = i / 27, tap = i - mloc * 27;
            const int m = m0 + mloc;
            const int kt = tap / 9, r9 = tap - kt * 9, kh = r9 / 3, kw = r9 - kh * 3;
            const int t = m >> 10, hw = m & 1023, h = hw >> 5, w = hw & 31;
            int tin = t + kt - 2; tin = tin < 0 ? 0 : tin;
            int hin = h + kh - 1; hin = hin < 0 ? 0 : (hin > 31 ? 31 : hin);
            int win = w + kw - 1; win = win < 0 ? 0 : (win > 31 ? 31 : win);
            sBase[i] = ((tin << 10) + (hin << 5) + win) << 9;
        }
        __syncthreads();
    }

    auto load_chunk = [&](int c, int buf) {
        const uint32_t tbu = tbase + buf * STAGEB;
        const long kkB = (long)c << 6;
        const int tap = c >> 3, c0 = (c & 7) << 6;
#pragma unroll
        for (int it = 0; it < BM / 64; it++) {
            const int i = it * 512 + tid;
            const int row = i >> 3, seg = i & 7;
            long offA;
            if (gather) offA = (long)sBase[row * 27 + tap] + c0 + (seg << 3);
            else        offA = (long)(m0 + row) * ldA + kkB + (seg << 3);
            const uint32_t d = SWZ128((uint32_t)(row * 128 + seg * 16));
            cp16(tbu + d,          AHi + offA);
            cp16(tbu + ABYTES + d, ALo + offA);
        }
#pragma unroll
        for (int it = 0; it < 4; it++) {
            const int i = it * 512 + tid;
            const int row = i >> 3, seg = i & 7;
            const long offB = (long)(n0 + row) * ldB + kkB + (seg << 3);
            const uint32_t d = SWZ128((uint32_t)(row * 128 + seg * 16));
            cp16(tbu + 2 * ABYTES + d,         BHi + offB);
            cp16(tbu + 2 * ABYTES + 32768 + d, BLo + offB);
        }
    };

    float acc[4][NT][4];
#pragma unroll
    for (int a = 0; a < 4; a++)
#pragma unroll
        for (int b = 0; b < NT; b++)
#pragma unroll
            for (int i = 0; i < 4; i++) acc[a][b][i] = 0.0f;

    const int a_r = lid & 15, a_ko = (lid >> 4) * 16;
    const int b_r = ((lid >> 4) << 3) + (lid & 7);
    const int b_ko = ((lid >> 3) & 1) * 16;

    const int nc = Keff >> 6;
    load_chunk(0, 0);
    CP_COMMIT();

    for (int c = 0; c < nc; c++) {
        if (c + 1 < nc) { load_chunk(c + 1, (c + 1) & 1); CP_COMMIT(); CP_WAIT1(); }
        else            { CP_WAIT0(); }
        __syncthreads();

        const uint32_t tbu = tbase + (c & 1) * STAGEB;
#pragma unroll
        for (int ks = 0; ks < 4; ks++) {
            const int kb = ks * 32;
            uint32_t ah[4][4], al[4][4];
#pragma unroll
            for (int mt = 0; mt < 4; mt++) {
                const int row = wm * 64 + mt * 16 + a_r;
                const uint32_t off = SWZ128((uint32_t)(row * 128 + kb + a_ko));
                LDSM_X4(ah[mt], tbu + off);
                LDSM_X4(al[mt], tbu + ABYTES + off);
            }
#pragma unroll
            for (int p = 0; p < NP; p++) {
                const int row = wn * WNW + p * 16 + b_r;
                const uint32_t off = SWZ128((uint32_t)(row * 128 + kb + b_ko));
                uint32_t rh[4], rl[4];
                LDSM_X4(rh, tbu + 2 * ABYTES + off);
                LDSM_X4(rl, tbu + 2 * ABYTES + 32768 + off);
#pragma unroll
                for (int mt = 0; mt < 4; mt++) {
                    mma16816(acc[mt][2*p],   ah[mt], rh);
                    mma16816(acc[mt][2*p],   ah[mt], rl);
                    mma16816(acc[mt][2*p],   al[mt], rh);
                    mma16816(acc[mt][2*p+1], ah[mt], rh + 2);
                    mma16816(acc[mt][2*p+1], ah[mt], rl + 2);
                    mma16816(acc[mt][2*p+1], al[mt], rh + 2);
                }
            }
        }
        __syncthreads();
    }

    const int er = lid >> 2, ec = (lid & 3) * 2;
#pragma unroll
    for (int mt = 0; mt < 4; mt++) {
#pragma unroll
        for (int nt = 0; nt < NT; nt++) {
            const int n = n0 + wn * WNW + nt * 8 + ec;
            float b0 = 0.f, b1 = 0.f;
            if (bias) { b0 = bias[n]; b1 = bias[n + 1]; }
#pragma unroll
            for (int half = 0; half < 2; half++) {
                const int m = m0 + wm * 64 + mt * 16 + er + half * 8;
                float v0 = acc[mt][nt][half * 2 + 0] * scale + b0;
                float v1 = acc[mt][nt][half * 2 + 1] * scale + b1;
                if (resid) {
                    const float2 rv = *(const float2*)(resid + (size_t)m * ldc + n);
                    v0 += rv.x; v1 += rv.y;
                }
                if (C)
                    *(float2*)(C + (size_t)m * ldc + n) = make_float2(v0, v1);
                if (outHi) {
                    bf16 h0 = __float2bfloat16(v0), h1 = __float2bfloat16(v1);
                    __nv_bfloat162 hh; hh.x = h0; hh.y = h1;
                    __nv_bfloat162 ll;
                    ll.x = __float2bfloat16(v0 - __bfloat162float(h0));
                    ll.y = __float2bfloat16(v1 - __bfloat162float(h1));
                    *(__nv_bfloat162*)(outHi + (size_t)m * ldc + n) = hh;
                    *(__nv_bfloat162*)(outLo + (size_t)m * ldc + n) = ll;
                }
            }
        }
    }
}

// ---------------- persistent balanced split-K conv GEMM (128x256, 2x4 warps) ----------------
__global__ __launch_bounds__(256) void tc_conv_ps(
    const bf16* __restrict__ AHi, const bf16* __restrict__ ALo,
    const bf16* __restrict__ BHi, const bf16* __restrict__ BLo,
    const float* __restrict__ bias, const float* __restrict__ resid,
    float* __restrict__ C, int nW)
{
    constexpr int ABYTES = 128 * 128;
    constexpr int STAGEB = 2 * ABYTES + 65536;

    extern __shared__ char smem[];
    const uint32_t sb = smem_u32(smem);
    const uint32_t tbase = (sb + 1023) & ~1023u;
    char* tiles = smem + (tbase - sb);
    int* sBase = (int*)(tiles + 2 * STAGEB);

    const int tid = threadIdx.x, wid = tid >> 5, lid = tid & 31;
    const int wm = wid >> 2, wn = wid & 3;
    const int a_r = lid & 15, a_ko = (lid >> 4) * 16;
    const int b_r = ((lid >> 4) << 3) + (lid & 7);
    const int b_ko = ((lid >> 3) & 1) * 16;
    const int er = lid >> 2, ec = (lid & 3) * 2;

    const long TC = 128L * 216;
    const long u0 = (long)blockIdx.x * TC / nW;
    const long u1 = (long)(blockIdx.x + 1) * TC / nW;
    if (u1 <= u0) return;
    const int t0 = (int)(u0 / 216), t1 = (int)((u1 - 1) / 216);

    for (int tau = t0; tau <= t1; tau++) {
        const int c0 = (tau == t0) ? (int)(u0 - (long)tau * 216) : 0;
        const int c1 = (tau == t1) ? (int)(u1 - (long)tau * 216) : 216;
        const int m0 = (tau >> 1) * 128, n0 = (tau & 1) * 256;

        for (int i = tid; i < 128 * 27; i += 256) {
            const int mloc = i / 27, tap = i - mloc * 27;
            const int m = m0 + mloc;
            const int kt = tap / 9, r9 = tap - kt * 9, kh = r9 / 3, kw = r9 - kh * 3;
            const int t = m >> 10, hw = m & 1023, h = hw >> 5, w = hw & 31;
            int tin = t + kt - 2; tin = tin < 0 ? 0 : tin;
            int hin = h + kh - 1; hin = hin < 0 ? 0 : (hin > 31 ? 31 : hin);
            int win = w + kw - 1; win = win < 0 ? 0 : (win > 31 ? 31 : win);
            sBase[i] = ((tin << 10) + (hin << 5) + win) << 9;
        }
        __syncthreads();

        auto load_chunk = [&](int c, int buf) {
            const uint32_t tbu = tbase + buf * STAGEB;
            const long kkB = (long)c << 6;
            const int tap = c >> 3, cc0 = (c & 7) << 6;
#pragma unroll
            for (int it = 0; it < 4; it++) {
                const int i = it * 256 + tid;
                const int row = i >> 3, seg = i & 7;
                const long offA = (long)sBase[row * 27 + tap] + cc0 + (seg << 3);
                const uint32_t d = SWZ128((uint32_t)(row * 128 + seg * 16));
                cp16(tbu + d,          AHi + offA);
                cp16(tbu + ABYTES + d, ALo + offA);
            }
#pragma unroll
            for (int it = 0; it < 8; it++) {
                const int i = it * 256 + tid;
                const int row = i >> 3, seg = i & 7;
                const long offB = (long)(n0 + row) * CONVK + kkB + (seg << 3);
                const uint32_t d = SWZ128((uint32_t)(row * 128 + seg * 16));
                cp16(tbu + 2 * ABYTES + d,         BHi + offB);
                cp16(tbu + 2 * ABYTES + 32768 + d, BLo + offB);
            }
        };

        float acc[4][8][4];
#pragma unroll
        for (int a = 0; a < 4; a++)
#pragma unroll
            for (int b = 0; b < 8; b++)
#pragma unroll
                for (int i = 0; i < 4; i++) acc[a][b][i] = 0.0f;

        load_chunk(c0, c0 & 1);
        CP_COMMIT();

        for (int c = c0; c < c1; c++) {
            if (c + 1 < c1) { load_chunk(c + 1, (c + 1) & 1); CP_COMMIT(); CP_WAIT1(); }
            else            { CP_WAIT0(); }
            __syncthreads();

            const uint32_t tbu = tbase + (c & 1) * STAGEB;
#pragma unroll
            for (int ks = 0; ks < 4; ks++) {
                const int kb = ks * 32;
                uint32_t ah[4][4], al[4][4];
#pragma unroll
                for (int mt = 0; mt < 4; mt++) {
                    const int row = wm * 64 + mt * 16 + a_r;
                    const uint32_t off = SWZ128((uint32_t)(row * 128 + kb + a_ko));
                    LDSM_X4(ah[mt], tbu + off);
                    LDSM_X4(al[mt], tbu + ABYTES + off);
                }
#pragma unroll
                for (int p = 0; p < 4; p++) {
                    const int row = wn * 64 + p * 16 + b_r;
                    const uint32_t off = SWZ128((uint32_t)(row * 128 + kb + b_ko));
                    uint32_t rh[4], rl[4];
                    LDSM_X4(rh, tbu + 2 * ABYTES + off);
                    LDSM_X4(rl, tbu + 2 * ABYTES + 32768 + off);
#pragma unroll
                    for (int mt = 0; mt < 4; mt++) {
                        mma16816(acc[mt][2*p],   ah[mt], rh);
                        mma16816(acc[mt][2*p],   ah[mt], rl);
                        mma16816(acc[mt][2*p],   al[mt], rh);
                        mma16816(acc[mt][2*p+1], ah[mt], rh + 2);
                        mma16816(acc[mt][2*p+1], ah[mt], rl + 2);
                        mma16816(acc[mt][2*p+1], al[mt], rh + 2);
                    }
                }
            }
            __syncthreads();
        }

        const bool lead = (c0 == 0);
#pragma unroll
        for (int mt = 0; mt < 4; mt++) {
#pragma unroll
            for (int nt = 0; nt < 8; nt++) {
                const int n = n0 + wn * 64 + nt * 8 + ec;
                float b0 = 0.f, b1 = 0.f;
                if (lead) { b0 = bias[n]; b1 = bias[n + 1]; }
#pragma unroll
                for (int half = 0; half < 2; half++) {
                    const int m = m0 + wm * 64 + mt * 16 + er + half * 8;
                    float v0 = acc[mt][nt][half * 2 + 0] + b0;
                    float v1 = acc[mt][nt][half * 2 + 1] + b1;
                    if (lead && resid) {
                        const float2 rv = *(const float2*)(resid + (size_t)m * CCH + n);
                        v0 += rv.x; v1 += rv.y;
                    }
                    atomicAdd(C + (size_t)m * CCH + n,     v0);
                    atomicAdd(C + (size_t)m * CCH + n + 1, v1);
                }
            }
        }
        __syncthreads();
    }
}

// ---------------- persistent balanced split-K A*V GEMM (varK triangular) ----------------
__global__ __launch_bounds__(256) void tc_av_ps(
    const bf16* __restrict__ PHi, const bf16* __restrict__ PLo,
    const bf16* __restrict__ VHi, const bf16* __restrict__ VLo,
    float* __restrict__ O, int nW)
{
    constexpr int ABYTES = 128 * 128;
    constexpr int STAGEB = 2 * ABYTES + 65536;

    extern __shared__ char smem[];
    const uint32_t sb = smem_u32(smem);
    const uint32_t tbase = (sb + 1023) & ~1023u;
    char* tiles = smem + (tbase - sb);

    const int tid = threadIdx.x, wid = tid >> 5, lid = tid & 31;
    const int wm = wid >> 2, wn = wid & 3;
    const int a_r = lid & 15, a_ko = (lid >> 4) * 16;
    const int b_r = ((lid >> 4) << 3) + (lid & 7);
    const int b_ko = ((lid >> 3) & 1) * 16;
    const int er = lid >> 2, ec = (lid & 3) * 2;

    const long TU = 9216;
    const long u0 = (long)blockIdx.x * TU / nW;
    const long u1 = (long)(blockIdx.x + 1) * TU / nW;
    long ucur = u0;

    while (ucur < u1) {
        int g = 0;
        while (g < 7 && 128L * (g + 1) * (g + 2) <= ucur) g++;
        const long Pg = 128L * g * (g + 1);
        const int L = 16 * (g + 1);
        const long rem = ucur - Pg;
        const int tl = (int)(rem / L);
        const int c0 = (int)(rem - (long)tl * L);
        int c1 = c0 + (int)(u1 - ucur);
        if (c1 > L) c1 = L;
        const int m0 = (g * 8 + (tl >> 1)) * 128;
        const int n0 = (tl & 1) * 256;

        auto load_chunk = [&](int c, int buf) {
            const uint32_t tbu = tbase + buf * STAGEB;
            const long kkB = (long)c << 6;
#pragma unroll
            for (int it = 0; it < 4; it++) {
                const int i = it * 256 + tid;
                const int row = i >> 3, seg = i & 7;
                const long offA = (long)(m0 + row) * SPOS + kkB + (seg << 3);
                const uint32_t d = SWZ128((uint32_t)(row * 128 + seg * 16));
                cp16(tbu + d,          PHi + offA);
                cp16(tbu + ABYTES + d, PLo + offA);
            }
#pragma unroll
            for (int it = 0; it < 8; it++) {
                const int i = it * 256 + tid;
                const int row = i >> 3, seg = i & 7;
                const long offB = (long)(n0 + row) * SPOS + kkB + (seg << 3);
                const uint32_t d = SWZ128((uint32_t)(row * 128 + seg * 16));
                cp16(tbu + 2 * ABYTES + d,         VHi + offB);
                cp16(tbu + 2 * ABYTES + 32768 + d, VLo + offB);
            }
        };

        float acc[4][8][4];
#pragma unroll
        for (int a = 0; a < 4; a++)
#pragma unroll
            for (int b = 0; b < 8; b++)
#pragma unroll
                for (int i = 0; i < 4; i++) acc[a][b][i] = 0.0f;

        load_chunk(c0, c0 & 1);
        CP_COMMIT();

        for (int c = c0; c < c1; c++) {
            if (c + 1 < c1) { load_chunk(c + 1, (c + 1) & 1); CP_COMMIT(); CP_WAIT1(); }
            else            { CP_WAIT0(); }
            __syncthreads();

            const uint32_t tbu = tbase + (c & 1) * STAGEB;
#pragma unroll
            for (int ks = 0; ks < 4; ks++) {
                const int kb = ks * 32;
                uint32_t ah[4][4], al[4][4];
#pragma unroll
                for (int mt = 0; mt < 4; mt++) {
                    const int row = wm * 64 + mt * 16 + a_r;
                    const uint32_t off = SWZ128((uint32_t)(row * 128 + kb + a_ko));
                    LDSM_X4(ah[mt], tbu + off);
                    LDSM_X4(al[mt], tbu + ABYTES + off);
                }
#pragma unroll
                for (int p = 0; p < 4; p++) {
                    const int row = wn * 64 + p * 16 + b_r;
                    const uint32_t off = SWZ128((uint32_t)(row * 128 + kb + b_ko));
                    uint32_t rh[4], rl[4];
                    LDSM_X4(rh, tbu + 2 * ABYTES + off);
                    LDSM_X4(rl, tbu + 2 * ABYTES + 32768 + off);
#pragma unroll
                    for (int mt = 0; mt < 4; mt++) {
                        mma16816(acc[mt][2*p],   ah[mt], rh);
                        mma16816(acc[mt][2*p],   ah[mt], rl);
                        mma16816(acc[mt][2*p],   al[mt], rh);
                        mma16816(acc[mt][2*p+1], ah[mt], rh + 2);
                        mma16816(acc[mt][2*p+1], ah[mt], rl + 2);
                        mma16816(acc[mt][2*p+1], al[mt], rh + 2);
                    }
                }
            }
            __syncthreads();
        }

#pragma unroll
        for (int mt = 0; mt < 4; mt++) {
#pragma unroll
            for (int nt = 0; nt < 8; nt++) {
                const int n = n0 + wn * 64 + nt * 8 + ec;
#pragma unroll
                for (int half = 0; half < 2; half++) {
                    const int m = m0 + wm * 64 + mt * 16 + er + half * 8;
                    atomicAdd(O + (size_t)m * CCH + n,     acc[mt][nt][half * 2 + 0]);
                    atomicAdd(O + (size_t)m * CCH + n + 1, acc[mt][nt][half * 2 + 1]);
                }
            }
        }
        __syncthreads();
        ucur += c1 - c0;
    }
}

// ---------------- host orchestration ----------------
extern "C" void kernel_launch(void* const* d_in, const int* in_sizes, int n_in,
                              void* d_out, int out_size)
{
    const float* x    = (const float*)d_in[0];
    const float* r1g1 = (const float*)d_in[1];
    const float* r1w1 = (const float*)d_in[2];
    const float* r1b1 = (const float*)d_in[3];
    const float* r1g2 = (const float*)d_in[4];
    const float* r1w2 = (const float*)d_in[5];
    const float* r1b2 = (const float*)d_in[6];
    const float* atg  = (const float*)d_in[7];
    const float* qw   = (const float*)d_in[8];
    const float* qb   = (const float*)d_in[9];
    const float* kw   = (const float*)d_in[10];
    const float* kb   = (const float*)d_in[11];
    const float* vw   = (const float*)d_in[12];
    const float* vb   = (const float*)d_in[13];
    const float* pw   = (const float*)d_in[14];
    const float* pb   = (const float*)d_in[15];
    const float* r2g1 = (const float*)d_in[16];
    const float* r2w1 = (const float*)d_in[17];
    const float* r2b1 = (const float*)d_in[18];
    const float* r2g2 = (const float*)d_in[19];
    const float* r2w2 = (const float*)d_in[20];
    const float* r2b2 = (const float*)d_in[21];
    float* out = (float*)d_out;

    bf16 *nHi, *nLo, *qHi, *qLo, *kHi, *kLo, *vtHi, *vtLo, *pHi, *pLo;
    bf16 *w1Hi, *w1Lo, *w2Hi, *w2Lo, *w3Hi, *w3Lo, *w4Hi, *w4Lo;
    bf16 *qwHi, *qwLo, *kwHi, *kwLo, *vwHi, *vwLo, *pwHi, *pwLo;
    float *s, *t, *h, *y, *o;
    cudaGetSymbolAddress((void**)&nHi, g_nHi);  cudaGetSymbolAddress((void**)&nLo, g_nLo);
    cudaGetSymbolAddress((void**)&w1Hi, g_w1Hi); cudaGetSymbolAddress((void**)&w1Lo, g_w1Lo);
    cudaGetSymbolAddress((void**)&w2Hi, g_w2Hi); cudaGetSymbolAddress((void**)&w2Lo, g_w2Lo);
    cudaGetSymbolAddress((void**)&w3Hi, g_w3Hi); cudaGetSymbolAddress((void**)&w3Lo, g_w3Lo);
    cudaGetSymbolAddress((void**)&w4Hi, g_w4Hi); cudaGetSymbolAddress((void**)&w4Lo, g_w4Lo);
    cudaGetSymbolAddress((void**)&qwHi, g_qwHi); cudaGetSymbolAddress((void**)&qwLo, g_qwLo);
    cudaGetSymbolAddress((void**)&kwHi, g_kwHi); cudaGetSymbolAddress((void**)&kwLo, g_kwLo);
    cudaGetSymbolAddress((void**)&vwHi, g_vwHi); cudaGetSymbolAddress((void**)&vwLo, g_vwLo);
    cudaGetSymbolAddress((void**)&pwHi, g_pwHi); cudaGetSymbolAddress((void**)&pwLo, g_pwLo);
    cudaGetSymbolAddress((void**)&qHi, g_qHi);  cudaGetSymbolAddress((void**)&qLo, g_qLo);
    cudaGetSymbolAddress((void**)&kHi, g_kHi);  cudaGetSymbolAddress((void**)&kLo, g_kLo);
    cudaGetSymbolAddress((void**)&vtHi, g_vtHi); cudaGetSymbolAddress((void**)&vtLo, g_vtLo);
    cudaGetSymbolAddress((void**)&pHi, g_pHi);  cudaGetSymbolAddress((void**)&pLo, g_pLo);
    cudaGetSymbolAddress((void**)&s, g_s);
    cudaGetSymbolAddress((void**)&t, g_t);
    cudaGetSymbolAddress((void**)&h, g_h);
    cudaGetSymbolAddress((void**)&y, g_y);
    cudaGetSymbolAddress((void**)&o, g_o);

    int nSM = 148;
    cudaDeviceGetAttribute(&nSM, cudaDevAttrMultiProcessorCount, 0);

    const int SMB128 = 1024 + 2 * (2 * 128 * 128 + 65536) + 128 * 27 * 4;  // 211456
    const int SMB_AV = 1024 + 2 * (2 * 128 * 128 + 65536);                 // 197632
    cudaFuncSetAttribute(tc_gemm<128>, cudaFuncAttributeMaxDynamicSharedMemorySize, SMB128);
    cudaFuncSetAttribute(tc_conv_ps,   cudaFuncAttributeMaxDynamicSharedMemorySize, SMB128);
    cudaFuncSetAttribute(tc_av_ps,     cudaFuncAttributeMaxDynamicSharedMemorySize, SMB_AV);

    const dim3 gStd(2, 64);
    const dim3 gNT(32, 64);
    const dim3 tBlk(32, 8);
    const dim3 gWT3(16, 432);
    const dim3 gWT1(16, 16);
    const dim3 gVT(16, 256);
    const float rs512 = 0.04419417382415922f;
    const size_t ZB = (size_t)SPOS * CCH * sizeof(float);
    const int n4 = SPOS * CCH / 4;

    // ---- fork weight prep onto a side stream (all input-only work) ----
    cudaStream_t s2;
    cudaStreamCreateWithFlags(&s2, cudaStreamNonBlocking);
    cudaEvent_t evFork;
    cudaEventCreateWithFlags(&evFork, cudaEventDisableTiming);
    cudaEvent_t evW[8];
    for (int i = 0; i < 8; i++) cudaEventCreateWithFlags(&evW[i], cudaEventDisableTiming);

    cudaEventRecord(evFork, 0);
    cudaStreamWaitEvent(s2, evFork, 0);
    transpose_split<<<gWT3, tBlk, 0, s2>>>(r1w1, w1Hi, w1Lo, CONVK, CCH); cudaEventRecord(evW[0], s2);
    transpose_split<<<gWT3, tBlk, 0, s2>>>(r1w2, w2Hi, w2Lo, CONVK, CCH); cudaEventRecord(evW[1], s2);
    transpose_split<<<gWT1, tBlk, 0, s2>>>(qw, qwHi, qwLo, CCH, CCH);     cudaEventRecord(evW[2], s2);
    transpose_split<<<gWT1, tBlk, 0, s2>>>(kw, kwHi, kwLo, CCH, CCH);     cudaEventRecord(evW[3], s2);
    transpose_split<<<gWT1, tBlk, 0, s2>>>(vw, vwHi, vwLo, CCH, CCH);     cudaEventRecord(evW[4], s2);
    transpose_split<<<gWT1, tBlk, 0, s2>>>(pw, pwHi, pwLo, CCH, CCH);     cudaEventRecord(evW[5], s2);
    transpose_split<<<gWT3, tBlk, 0, s2>>>(r2w1, w3Hi, w3Lo, CONVK, CCH); cudaEventRecord(evW[6], s2);
    transpose_split<<<gWT3, tBlk, 0, s2>>>(r2w2, w4Hi, w4Lo, CONVK, CCH); cudaEventRecord(evW[7], s2);

    // ---- hoisted zero-fills for accumulation targets (off critical path) ----
    cudaMemsetAsync(h, 0, ZB, 0);
    cudaMemsetAsync(y, 0, ZB, 0);
    cudaMemsetAsync(o, 0, ZB, 0);
    cudaMemsetAsync(out, 0, ZB, 0);

    // ---- resnet 1 ----
    rmsnorm_split<<<SPOS, 128>>>(x, r1g1, nHi, nLo, 1);
    cudaStreamWaitEvent(0, evW[0], 0);
    tc_conv_ps<<<nSM, 256, SMB128>>>(nHi, nLo, w1Hi, w1Lo, r1b1, nullptr, h, nSM);
    rmsnorm_split<<<SPOS, 128>>>(h, r1g2, nHi, nLo, 1);
    cudaStreamWaitEvent(0, evW[1], 0);
    tc_conv_ps<<<nSM, 256, SMB128>>>(nHi, nLo, w2Hi, w2Lo, r1b2, x, y, nSM);

    // ---- attention ----
    rmsnorm_split<<<SPOS, 128>>>(y, atg, nHi, nLo, 0);
    cudaStreamWaitEvent(0, evW[2], 0);
    tc_gemm<128><<<gStd, 512, SMB128>>>(nHi, nLo, CCH, qwHi, qwLo, CCH, qb, nullptr, nullptr, qHi, qLo, CCH, CCH, 0, 1.0f);
    cudaStreamWaitEvent(0, evW[3], 0);
    tc_gemm<128><<<gStd, 512, SMB128>>>(nHi, nLo, CCH, kwHi, kwLo, CCH, kb, nullptr, nullptr, kHi, kLo, CCH, CCH, 0, 1.0f);
    cudaStreamWaitEvent(0, evW[4], 0);
    tc_gemm<128><<<gStd, 512, SMB128>>>(nHi, nLo, CCH, vwHi, vwLo, CCH, vb, nullptr, t, nullptr, nullptr, CCH, CCH, 0, 1.0f);
    transpose_split<<<gVT, tBlk>>>(t, vtHi, vtLo, SPOS, CCH);

    tc_gemm<128><<<gNT, 512, SMB128>>>(qHi, qLo, CCH, kHi, kLo, CCH, nullptr, nullptr, s, nullptr, nullptr, SPOS, CCH, TCG_CAUSAL, rs512);
    softmax_split<<<SPOS, 256>>>(s, pHi, pLo);
    tc_av_ps<<<nSM, 256, SMB_AV>>>(pHi, pLo, vtHi, vtLo, o, nSM);
    split4_kernel<<<n4 / 256, 256>>>(o, qHi, qLo, n4);   // reuse q buffers for O split
    cudaStreamWaitEvent(0, evW[5], 0);
    tc_gemm<128><<<gStd, 512, SMB128>>>(qHi, qLo, CCH, pwHi, pwLo, CCH, pb, y, h, nullptr, nullptr, CCH, CCH, 0, 1.0f);

    // ---- resnet 2 ----
    rmsnorm_split<<<SPOS, 128>>>(h, r2g1, nHi, nLo, 1);
    cudaMemsetAsync(t, 0, ZB, 0);
    cudaStreamWaitEvent(0, evW[6], 0);
    tc_conv_ps<<<nSM, 256, SMB128>>>(nHi, nLo, w3Hi, w3Lo, r2b1, nullptr, t, nSM);
    rmsnorm_split<<<SPOS, 128>>>(t, r2g2, nHi, nLo, 1);
    cudaStreamWaitEvent(0, evW[7], 0);
    tc_conv_ps<<<nSM, 256, SMB128>>>(nHi, nLo, w4Hi, w4Lo, r2b2, h, out, nSM);
}

// round 15
// speedup vs baseline: 1.1747x; 1.0009x over previous
#include <cuda_runtime.h>
#include <cuda_bf16.h>
#include <cstdint>
#include <math.h>

#define SPOS 8192
#define CCH  512
#define CONVK 13824   // 27*512

typedef __nv_bfloat16 bf16;

// ---------------- scratch (static device memory) ----------------
__device__ __align__(256) bf16 g_nHi[SPOS*CCH], g_nLo[SPOS*CCH];
__device__ __align__(256) bf16 g_w1Hi[CCH*CONVK], g_w1Lo[CCH*CONVK];
__device__ __align__(256) bf16 g_w2Hi[CCH*CONVK], g_w2Lo[CCH*CONVK];
__device__ __align__(256) bf16 g_w3Hi[CCH*CONVK], g_w3Lo[CCH*CONVK];
__device__ __align__(256) bf16 g_w4Hi[CCH*CONVK], g_w4Lo[CCH*CONVK];
__device__ __align__(256) bf16 g_qwHi[CCH*CCH], g_qwLo[CCH*CCH];
__device__ __align__(256) bf16 g_kwHi[CCH*CCH], g_kwLo[CCH*CCH];
__device__ __align__(256) bf16 g_vwHi[CCH*CCH], g_vwLo[CCH*CCH];
__device__ __align__(256) bf16 g_pwHi[CCH*CCH], g_pwLo[CCH*CCH];
__device__ __align__(256) bf16 g_qHi[SPOS*CCH], g_qLo[SPOS*CCH];
__device__ __align__(256) bf16 g_kHi[SPOS*CCH], g_kLo[SPOS*CCH];
__device__ __align__(256) bf16 g_vtHi[SPOS*CCH], g_vtLo[SPOS*CCH];
__device__ __align__(256) bf16 g_pHi[(size_t)SPOS*SPOS], g_pLo[(size_t)SPOS*SPOS];
__device__ __align__(256) float g_s[(size_t)SPOS*SPOS];
__device__ __align__(256) float g_t[SPOS*CCH], g_h[SPOS*CCH], g_y[SPOS*CCH];
__device__ __align__(256) float g_o[SPOS*CCH];

// ---------------- helpers ----------------
__device__ __forceinline__ uint32_t smem_u32(const void* p) {
    uint32_t a;
    asm("{ .reg .u64 t; cvta.to.shared.u64 t, %1; cvt.u32.u64 %0, t; }" : "=r"(a) : "l"(p));
    return a;
}
__device__ __forceinline__ void cp16(uint32_t dst, const void* src) {
    asm volatile("cp.async.cg.shared.global [%0], [%1], 16;" :: "r"(dst), "l"(src));
}
#define CP_COMMIT() asm volatile("cp.async.commit_group;" ::: "memory")
#define CP_WAIT1()  asm volatile("cp.async.wait_group 1;" ::: "memory")
#define CP_WAIT0()  asm volatile("cp.async.wait_group 0;" ::: "memory")
#define SWZ128(b) ((b) ^ (((b) >> 3) & 0x70))

#define LDSM_X4(r, addr) \
    asm volatile("ldmatrix.sync.aligned.m8n8.x4.shared.b16 {%0,%1,%2,%3}, [%4];" \
        : "=r"((r)[0]), "=r"((r)[1]), "=r"((r)[2]), "=r"((r)[3]) : "r"(addr))

__device__ __forceinline__ void mma16816(float* c, const uint32_t* a, const uint32_t* b) {
    asm volatile(
        "mma.sync.aligned.m16n8k16.row.col.f32.bf16.bf16.f32 "
        "{%0,%1,%2,%3},{%4,%5,%6,%7},{%8,%9},{%0,%1,%2,%3};"
        : "+f"(c[0]), "+f"(c[1]), "+f"(c[2]), "+f"(c[3])
        : "r"(a[0]), "r"(a[1]), "r"(a[2]), "r"(a[3]), "r"(b[0]), "r"(b[1]));
}

__device__ __forceinline__ float warpReduceSum(float v) {
#pragma unroll
    for (int o = 16; o; o >>= 1) v += __shfl_xor_sync(0xffffffffu, v, o);
    return v;
}
__device__ __forceinline__ float warpReduceMax(float v) {
#pragma unroll
    for (int o = 16; o; o >>= 1) v = fmaxf(v, __shfl_xor_sync(0xffffffffu, v, o));
    return v;
}
__device__ __forceinline__ uint32_t pack_bf16x2(float a, float b) {
    __nv_bfloat162 h;
    h.x = __float2bfloat16(a);
    h.y = __float2bfloat16(b);
    return *(uint32_t*)&h;
}

// ---------------- rmsnorm + silu + bf16 split (warp-per-row, no block barrier) ----------------
__global__ __launch_bounds__(256) void rmsnorm_split(
    const float* __restrict__ x, const float* __restrict__ g,
    bf16* __restrict__ hi, bf16* __restrict__ lo, int do_silu)
{
    const int wid = threadIdx.x >> 5, lid = threadIdx.x & 31;
    const int r = blockIdx.x * 8 + wid;
    const float* xr = x + (size_t)r * CCH;

    float v[16];
    float ss = 0.0f;
#pragma unroll
    for (int i = 0; i < 4; i++) {
        const float4 t = *(const float4*)(xr + i * 128 + lid * 4);
        v[4*i+0] = t.x; v[4*i+1] = t.y; v[4*i+2] = t.z; v[4*i+3] = t.w;
        ss += t.x*t.x + t.y*t.y + t.z*t.z + t.w*t.w;
    }
    ss = warpReduceSum(ss);
    const float scale = 22.62741699796952f / (sqrtf(ss) + 1e-8f);

#pragma unroll
    for (int i = 0; i < 4; i++) {
        const float4 gg = *(const float4*)(g + i * 128 + lid * 4);
        float o[4];
        o[0] = v[4*i+0]*scale*gg.x; o[1] = v[4*i+1]*scale*gg.y;
        o[2] = v[4*i+2]*scale*gg.z; o[3] = v[4*i+3]*scale*gg.w;
        if (do_silu) {
#pragma unroll
            for (int j = 0; j < 4; j++) o[j] = o[j] / (1.0f + __expf(-o[j]));
        }
        float l[4];
#pragma unroll
        for (int j = 0; j < 4; j++) {
            bf16 h = __float2bfloat16(o[j]);
            l[j] = o[j] - __bfloat162float(h);
        }
        const size_t base = (size_t)r * CCH + i * 128 + lid * 4;
        *(uint2*)(hi + base) = make_uint2(pack_bf16x2(o[0], o[1]), pack_bf16x2(o[2], o[3]));
        *(uint2*)(lo + base) = make_uint2(pack_bf16x2(l[0], l[1]), pack_bf16x2(l[2], l[3]));
    }
}

// ---------------- plain bf16 split (packed stores) ----------------
__global__ __launch_bounds__(256) void split4_kernel(
    const float* __restrict__ in, bf16* __restrict__ hi, bf16* __restrict__ lo, int n4)
{
    const int i = blockIdx.x * 256 + threadIdx.x;
    if (i >= n4) return;
    const float4 v = ((const float4*)in)[i];
    float o[4] = {v.x, v.y, v.z, v.w};
    float l[4];
#pragma unroll
    for (int j = 0; j < 4; j++) {
        bf16 h = __float2bfloat16(o[j]);
        l[j] = o[j] - __bfloat162float(h);
    }
    const size_t base = (size_t)i * 4;
    *(uint2*)(hi + base) = make_uint2(pack_bf16x2(o[0], o[1]), pack_bf16x2(o[2], o[3]));
    *(uint2*)(lo + base) = make_uint2(pack_bf16x2(l[0], l[1]), pack_bf16x2(l[2], l[3]));
}

// ---------------- transpose + split ----------------
__global__ void transpose_split(
    const float* __restrict__ in, bf16* __restrict__ hi, bf16* __restrict__ lo, int R, int Cc)
{
    __shared__ float t[32][33];
    const int c0 = blockIdx.x * 32, r0 = blockIdx.y * 32;
    const int tx = threadIdx.x;
    for (int j = threadIdx.y; j < 32; j += 8)
        t[j][tx] = in[(size_t)(r0 + j) * Cc + c0 + tx];
    __syncthreads();
    for (int j = threadIdx.y; j < 32; j += 8) {
        float v = t[tx][j];
        bf16 h = __float2bfloat16(v);
        const size_t o = (size_t)(c0 + j) * R + r0 + tx;
        hi[o] = h;
        lo[o] = __float2bfloat16(v - __bfloat162float(h));
    }
}

// ---------------- softmax -> bf16 split probs (vectorized, 2 cols/thread) ----------------
__global__ __launch_bounds__(256) void softmax_split(
    const float* __restrict__ S, bf16* __restrict__ PHi, bf16* __restrict__ PLo)
{
    __shared__ float red[8];
    const int r = blockIdx.x, tid = threadIdx.x;
    const int cnt = ((r >> 10) + 1) * 2;             // iterations of 512 cols
    const float* row = S + (size_t)r * SPOS;

    float2 vals[16];
    float mx = -3.4e38f;
#pragma unroll
    for (int i = 0; i < 16; i++)
        if (i < cnt) {
            vals[i] = *(const float2*)(row + i * 512 + 2 * tid);
            mx = fmaxf(mx, fmaxf(vals[i].x, vals[i].y));
        }
    mx = warpReduceMax(mx);
    if ((tid & 31) == 0) red[tid >> 5] = mx;
    __syncthreads();
    float m2 = red[0];
#pragma unroll
    for (int i = 1; i < 8; i++) m2 = fmaxf(m2, red[i]);
    __syncthreads();
    float sum = 0.0f;
#pragma unroll
    for (int i = 0; i < 16; i++)
        if (i < cnt) {
            vals[i].x = __expf(vals[i].x - m2);
            vals[i].y = __expf(vals[i].y - m2);
            sum += vals[i].x + vals[i].y;
        }
    sum = warpReduceSum(sum);
    if ((tid & 31) == 0) red[tid >> 5] = sum;
    __syncthreads();
    float tot = 0.0f;
#pragma unroll
    for (int i = 0; i < 8; i++) tot += red[i];
    const float inv = 1.0f / tot;
    bf16* ph = PHi + (size_t)r * SPOS;
    bf16* pl = PLo + (size_t)r * SPOS;
#pragma unroll
    for (int i = 0; i < 16; i++)
        if (i < cnt) {
            const float p0 = vals[i].x * inv, p1 = vals[i].y * inv;
            const bf16 h0 = __float2bfloat16(p0), h1 = __float2bfloat16(p1);
            const float l0 = p0 - __bfloat162float(h0), l1 = p1 - __bfloat162float(h1);
            __nv_bfloat162 hh; hh.x = h0; hh.y = h1;
            *(__nv_bfloat162*)(ph + i * 512 + 2 * tid) = hh;
            *(uint32_t*)(pl + i * 512 + 2 * tid) = pack_bf16x2(l0, l1);
        }
}

// ---------------- HMMA split-bf16 GEMM, CTA tile BMx256, 512 threads ----------------
#define TCG_GATHER 1
#define TCG_VARK   2
#define TCG_CAUSAL 4

template<int BM>
__global__ __launch_bounds__(512) void tc_gemm(
    const bf16* __restrict__ AHi, const bf16* __restrict__ ALo, int ldA,
    const bf16* __restrict__ BHi, const bf16* __restrict__ BLo, int ldB,
    const float* __restrict__ bias, const float* __restrict__ resid,
    float* __restrict__ C, bf16* __restrict__ outHi, bf16* __restrict__ outLo,
    int ldc, int Ktot, int flags, float scale)
{
    constexpr int WN = (BM == 128) ? 8 : 16;
    constexpr int NT = 32 / WN * 2 / 2;
    constexpr int NP = (BM == 128) ? 2 : 1;
    constexpr int WNW = 256 / WN;
    constexpr int ABYTES = BM * 128;
    constexpr int STAGEB = 2 * ABYTES + 65536;

    extern __shared__ char smem[];
    int mtile = blockIdx.y;
    if (flags & TCG_VARK) mtile = gridDim.y - 1 - blockIdx.y;
    const int m0 = mtile * BM, n0 = blockIdx.x * 256;
    if (flags & TCG_CAUSAL) { if (n0 >= (((m0 >> 10) + 1) << 10)) return; }
    int Keff = Ktot;
    if (flags & TCG_VARK)   { Keff = ((m0 >> 10) + 1) << 10; }

    const uint32_t sb = smem_u32(smem);
    const uint32_t tbase = (sb + 1023) & ~1023u;
    char* tiles = smem + (tbase - sb);
    int* sBase = (int*)(tiles + 2 * STAGEB);

    const int tid = threadIdx.x, wid = tid >> 5, lid = tid & 31;
    const int wm = wid / WN, wn = wid % WN;
    const bool gather = (flags & TCG_GATHER);

    if (gather) {
        for (int i = tid; i < BM * 27; i += 512) {
            const int mloc = i / 27, tap = i - mloc * 27;
            const int m = m0 + mloc;
            const int kt = tap / 9, r9 = tap - kt * 9, kh = r9 / 3, kw = r9 - kh * 3;
            const int t = m >> 10, hw = m & 1023, h = hw >> 5, w = hw & 31;
            int tin = t + kt - 2; tin = tin < 0 ? 0 : tin;
            int hin = h + kh - 1; hin = hin < 0 ? 0 : (hin > 31 ? 31 : hin);
            int win = w + kw - 1; win = win < 0 ? 0 : (win > 31 ? 31 : win);
            sBase[i] = ((tin << 10) + (hin << 5) + win) << 9;
        }
        __syncthreads();
    }

    auto load_chunk = [&](int c, int buf) {
        const uint32_t tbu = tbase + buf * STAGEB;
        const long kkB = (long)c << 6;
        const int tap = c >> 3, c0 = (c & 7) << 6;
#pragma unroll
        for (int it = 0; it < BM / 64; it++) {
            const int i = it * 512 + tid;
            const int row = i >> 3, seg = i & 7;
            long offA;
            if (gather) offA = (long)sBase[row * 27 + tap] + c0 + (seg << 3);
            else        offA = (long)(m0 + row) * ldA + kkB + (seg << 3);
            const uint32_t d = SWZ128((uint32_t)(row * 128 + seg * 16));
            cp16(tbu + d,          AHi + offA);
            cp16(tbu + ABYTES + d, ALo + offA);
        }
#pragma unroll
        for (int it = 0; it < 4; it++) {
            const int i = it * 512 + tid;
            const int row = i >> 3, seg = i & 7;
            const long offB = (long)(n0 + row) * ldB + kkB + (seg << 3);
            const uint32_t d = SWZ128((uint32_t)(row * 128 + seg * 16));
            cp16(tbu + 2 * ABYTES + d,         BHi + offB);
            cp16(tbu + 2 * ABYTES + 32768 + d, BLo + offB);
        }
    };

    float acc[4][NT][4];
#pragma unroll
    for (int a = 0; a < 4; a++)
#pragma unroll
        for (int b = 0; b < NT; b++)
#pragma unroll
            for (int i = 0; i < 4; i++) acc[a][b][i] = 0.0f;

    const int a_r = lid & 15, a_ko = (lid >> 4) * 16;
    const int b_r = ((lid >> 4) << 3) + (lid & 7);
    const int b_ko = ((lid >> 3) & 1) * 16;

    const int nc = Keff >> 6;
    load_chunk(0, 0);
    CP_COMMIT();

    for (int c = 0; c < nc; c++) {
        if (c + 1 < nc) { load_chunk(c + 1, (c + 1) & 1); CP_COMMIT(); CP_WAIT1(); }
        else            { CP_WAIT0(); }
        __syncthreads();

        const uint32_t tbu = tbase + (c & 1) * STAGEB;
#pragma unroll
        for (int ks = 0; ks < 4; ks++) {
            const int kb = ks * 32;
            uint32_t ah[4][4], al[4][4];
#pragma unroll
            for (int mt = 0; mt < 4; mt++) {
                const int row = wm * 64 + mt * 16 + a_r;
                const uint32_t off = SWZ128((uint32_t)(row * 128 + kb + a_ko));
                LDSM_X4(ah[mt], tbu + off);
                LDSM_X4(al[mt], tbu + ABYTES + off);
            }
#pragma unroll
            for (int p = 0; p < NP; p++) {
                const int row = wn * WNW + p * 16 + b_r;
                const uint32_t off = SWZ128((uint32_t)(row * 128 + kb + b_ko));
                uint32_t rh[4], rl[4];
                LDSM_X4(rh, tbu + 2 * ABYTES + off);
                LDSM_X4(rl, tbu + 2 * ABYTES + 32768 + off);
#pragma unroll
                for (int mt = 0; mt < 4; mt++) {
                    mma16816(acc[mt][2*p],   ah[mt], rh);
                    mma16816(acc[mt][2*p],   ah[mt], rl);
                    mma16816(acc[mt][2*p],   al[mt], rh);
                    mma16816(acc[mt][2*p+1], ah[mt], rh + 2);
                    mma16816(acc[mt][2*p+1], ah[mt], rl + 2);
                    mma16816(acc[mt][2*p+1], al[mt], rh + 2);
                }
            }
        }
        __syncthreads();
    }

    const int er = lid >> 2, ec = (lid & 3) * 2;
#pragma unroll
    for (int mt = 0; mt < 4; mt++) {
#pragma unroll
        for (int nt = 0; nt < NT; nt++) {
            const int n = n0 + wn * WNW + nt * 8 + ec;
            float b0 = 0.f, b1 = 0.f;
            if (bias) { b0 = bias[n]; b1 = bias[n + 1]; }
#pragma unroll
            for (int half = 0; half < 2; half++) {
                const int m = m0 + wm * 64 + mt * 16 + er + half * 8;
                float v0 = acc[mt][nt][half * 2 + 0] * scale + b0;
                float v1 = acc[mt][nt][half * 2 + 1] * scale + b1;
                if (resid) {
                    const float2 rv = *(const float2*)(resid + (size_t)m * ldc + n);
                    v0 += rv.x; v1 += rv.y;
                }
                if (C)
                    *(float2*)(C + (size_t)m * ldc + n) = make_float2(v0, v1);
                if (outHi) {
                    bf16 h0 = __float2bfloat16(v0), h1 = __float2bfloat16(v1);
                    __nv_bfloat162 hh; hh.x = h0; hh.y = h1;
                    __nv_bfloat162 ll;
                    ll.x = __float2bfloat16(v0 - __bfloat162float(h0));
                    ll.y = __float2bfloat16(v1 - __bfloat162float(h1));
                    *(__nv_bfloat162*)(outHi + (size_t)m * ldc + n) = hh;
                    *(__nv_bfloat162*)(outLo + (size_t)m * ldc + n) = ll;
                }
            }
        }
    }
}

// ---------------- persistent balanced split-K conv GEMM (128x256, 2x4 warps) ----------------
__global__ __launch_bounds__(256) void tc_conv_ps(
    const bf16* __restrict__ AHi, const bf16* __restrict__ ALo,
    const bf16* __restrict__ BHi, const bf16* __restrict__ BLo,
    const float* __restrict__ bias, const float* __restrict__ resid,
    float* __restrict__ C, int nW)
{
    constexpr int ABYTES = 128 * 128;
    constexpr int STAGEB = 2 * ABYTES + 65536;

    extern __shared__ char smem[];
    const uint32_t sb = smem_u32(smem);
    const uint32_t tbase = (sb + 1023) & ~1023u;
    char* tiles = smem + (tbase - sb);
    int* sBase = (int*)(tiles + 2 * STAGEB);

    const int tid = threadIdx.x, wid = tid >> 5, lid = tid & 31;
    const int wm = wid >> 2, wn = wid & 3;
    const int a_r = lid & 15, a_ko = (lid >> 4) * 16;
    const int b_r = ((lid >> 4) << 3) + (lid & 7);
    const int b_ko = ((lid >> 3) & 1) * 16;
    const int er = lid >> 2, ec = (lid & 3) * 2;

    const long TC = 128L * 216;
    const long u0 = (long)blockIdx.x * TC / nW;
    const long u1 = (long)(blockIdx.x + 1) * TC / nW;
    if (u1 <= u0) return;
    const int t0 = (int)(u0 / 216), t1 = (int)((u1 - 1) / 216);

    for (int tau = t0; tau <= t1; tau++) {
        const int c0 = (tau == t0) ? (int)(u0 - (long)tau * 216) : 0;
        const int c1 = (tau == t1) ? (int)(u1 - (long)tau * 216) : 216;
        const int m0 = (tau >> 1) * 128, n0 = (tau & 1) * 256;

        for (int i = tid; i < 128 * 27; i += 256) {
            const int mloc = i / 27, tap = i - mloc * 27;
            const int m = m0 + mloc;
            const int kt = tap / 9, r9 = tap - kt * 9, kh = r9 / 3, kw = r9 - kh * 3;
            const int t = m >> 10, hw = m & 1023, h = hw >> 5, w = hw & 31;
            int tin = t + kt - 2; tin = tin < 0 ? 0 : tin;
            int hin = h + kh - 1; hin = hin < 0 ? 0 : (hin > 31 ? 31 : hin);
            int win = w + kw - 1; win = win < 0 ? 0 : (win > 31 ? 31 : win);
            sBase[i] = ((tin << 10) + (hin << 5) + win) << 9;
        }
        __syncthreads();

        auto load_chunk = [&](int c, int buf) {
            const uint32_t tbu = tbase + buf * STAGEB;
            const long kkB = (long)c << 6;
            const int tap = c >> 3, cc0 = (c & 7) << 6;
#pragma unroll
            for (int it = 0; it < 4; it++) {
                const int i = it * 256 + tid;
                const int row = i >> 3, seg = i & 7;
                const long offA = (long)sBase[row * 27 + tap] + cc0 + (seg << 3);
                const uint32_t d = SWZ128((uint32_t)(row * 128 + seg * 16));
                cp16(tbu + d,          AHi + offA);
                cp16(tbu + ABYTES + d, ALo + offA);
            }
#pragma unroll
            for (int it = 0; it < 8; it++) {
                const int i = it * 256 + tid;
                const int row = i >> 3, seg = i & 7;
                const long offB = (long)(n0 + row) * CONVK + kkB + (seg << 3);
                const uint32_t d = SWZ128((uint32_t)(row * 128 + seg * 16));
                cp16(tbu + 2 * ABYTES + d,         BHi + offB);
                cp16(tbu + 2 * ABYTES + 32768 + d, BLo + offB);
            }
        };

        float acc[4][8][4];
#pragma unroll
        for (int a = 0; a < 4; a++)
#pragma unroll
            for (int b = 0; b < 8; b++)
#pragma unroll
                for (int i = 0; i < 4; i++) acc[a][b][i] = 0.0f;

        load_chunk(c0, c0 & 1);
        CP_COMMIT();

        for (int c = c0; c < c1; c++) {
            if (c + 1 < c1) { load_chunk(c + 1, (c + 1) & 1); CP_COMMIT(); CP_WAIT1(); }
            else            { CP_WAIT0(); }
            __syncthreads();

            const uint32_t tbu = tbase + (c & 1) * STAGEB;
#pragma unroll
            for (int ks = 0; ks < 4; ks++) {
                const int kb = ks * 32;
                uint32_t ah[4][4], al[4][4];
#pragma unroll
                for (int mt = 0; mt < 4; mt++) {
                    const int row = wm * 64 + mt * 16 + a_r;
                    const uint32_t off = SWZ128((uint32_t)(row * 128 + kb + a_ko));
                    LDSM_X4(ah[mt], tbu + off);
                    LDSM_X4(al[mt], tbu + ABYTES + off);
                }
#pragma unroll
                for (int p = 0; p < 4; p++) {
                    const int row = wn * 64 + p * 16 + b_r;
                    const uint32_t off = SWZ128((uint32_t)(row * 128 + kb + b_ko));
                    uint32_t rh[4], rl[4];
                    LDSM_X4(rh, tbu + 2 * ABYTES + off);
                    LDSM_X4(rl, tbu + 2 * ABYTES + 32768 + off);
#pragma unroll
                    for (int mt = 0; mt < 4; mt++) {
                        mma16816(acc[mt][2*p],   ah[mt], rh);
                        mma16816(acc[mt][2*p],   ah[mt], rl);
                        mma16816(acc[mt][2*p],   al[mt], rh);
                        mma16816(acc[mt][2*p+1], ah[mt], rh + 2);
                        mma16816(acc[mt][2*p+1], ah[mt], rl + 2);
                        mma16816(acc[mt][2*p+1], al[mt], rh + 2);
                    }
                }
            }
            __syncthreads();
        }

        const bool lead = (c0 == 0);
#pragma unroll
        for (int mt = 0; mt < 4; mt++) {
#pragma unroll
            for (int nt = 0; nt < 8; nt++) {
                const int n = n0 + wn * 64 + nt * 8 + ec;
                float b0 = 0.f, b1 = 0.f;
                if (lead) { b0 = bias[n]; b1 = bias[n + 1]; }
#pragma unroll
                for (int half = 0; half < 2; half++) {
                    const int m = m0 + wm * 64 + mt * 16 + er + half * 8;
                    float v0 = acc[mt][nt][half * 2 + 0] + b0;
                    float v1 = acc[mt][nt][half * 2 + 1] + b1;
                    if (lead && resid) {
                        const float2 rv = *(const float2*)(resid + (size_t)m * CCH + n);
                        v0 += rv.x; v1 += rv.y;
                    }
                    atomicAdd(C + (size_t)m * CCH + n,     v0);
                    atomicAdd(C + (size_t)m * CCH + n + 1, v1);
                }
            }
        }
        __syncthreads();
    }
}

// ---------------- persistent balanced split-K A*V GEMM (varK triangular) ----------------
__global__ __launch_bounds__(256) void tc_av_ps(
    const bf16* __restrict__ PHi, const bf16* __restrict__ PLo,
    const bf16* __restrict__ VHi, const bf16* __restrict__ VLo,
    float* __restrict__ O, int nW)
{
    constexpr int ABYTES = 128 * 128;
    constexpr int STAGEB = 2 * ABYTES + 65536;

    extern __shared__ char smem[];
    const uint32_t sb = smem_u32(smem);
    const uint32_t tbase = (sb + 1023) & ~1023u;
    char* tiles = smem + (tbase - sb);

    const int tid = threadIdx.x, wid = tid >> 5, lid = tid & 31;
    const int wm = wid >> 2, wn = wid & 3;
    const int a_r = lid & 15, a_ko = (lid >> 4) * 16;
    const int b_r = ((lid >> 4) << 3) + (lid & 7);
    const int b_ko = ((lid >> 3) & 1) * 16;
    const int er = lid >> 2, ec = (lid & 3) * 2;

    const long TU = 9216;
    const long u0 = (long)blockIdx.x * TU / nW;
    const long u1 = (long)(blockIdx.x + 1) * TU / nW;
    long ucur = u0;

    while (ucur < u1) {
        int g = 0;
        while (g < 7 && 128L * (g + 1) * (g + 2) <= ucur) g++;
        const long Pg = 128L * g * (g + 1);
        const int L = 16 * (g + 1);
        const long rem = ucur - Pg;
        const int tl = (int)(rem / L);
        const int c0 = (int)(rem - (long)tl * L);
        int c1 = c0 + (int)(u1 - ucur);
        if (c1 > L) c1 = L;
        const int m0 = (g * 8 + (tl >> 1)) * 128;
        const int n0 = (tl & 1) * 256;

        auto load_chunk = [&](int c, int buf) {
            const uint32_t tbu = tbase + buf * STAGEB;
            const long kkB = (long)c << 6;
#pragma unroll
            for (int it = 0; it < 4; it++) {
                const int i = it * 256 + tid;
                const int row = i >> 3, seg = i & 7;
                const long offA = (long)(m0 + row) * SPOS + kkB + (seg << 3);
                const uint32_t d = SWZ128((uint32_t)(row * 128 + seg * 16));
                cp16(tbu + d,          PHi + offA);
                cp16(tbu + ABYTES + d, PLo + offA);
            }
#pragma unroll
            for (int it = 0; it < 8; it++) {
                const int i = it * 256 + tid;
                const int row = i >> 3, seg = i & 7;
                const long offB = (long)(n0 + row) * SPOS + kkB + (seg << 3);
                const uint32_t d = SWZ128((uint32_t)(row * 128 + seg * 16));
                cp16(tbu + 2 * ABYTES + d,         VHi + offB);
                cp16(tbu + 2 * ABYTES + 32768 + d, VLo + offB);
            }
        };

        float acc[4][8][4];
#pragma unroll
        for (int a = 0; a < 4; a++)
#pragma unroll
            for (int b = 0; b < 8; b++)
#pragma unroll
                for (int i = 0; i < 4; i++) acc[a][b][i] = 0.0f;

        load_chunk(c0, c0 & 1);
        CP_COMMIT();

        for (int c = c0; c < c1; c++) {
            if (c + 1 < c1) { load_chunk(c + 1, (c + 1) & 1); CP_COMMIT(); CP_WAIT1(); }
            else            { CP_WAIT0(); }
            __syncthreads();

            const uint32_t tbu = tbase + (c & 1) * STAGEB;
#pragma unroll
            for (int ks = 0; ks < 4; ks++) {
                const int kb = ks * 32;
                uint32_t ah[4][4], al[4][4];
#pragma unroll
                for (int mt = 0; mt < 4; mt++) {
                    const int row = wm * 64 + mt * 16 + a_r;
                    const uint32_t off = SWZ128((uint32_t)(row * 128 + kb + a_ko));
                    LDSM_X4(ah[mt], tbu + off);
                    LDSM_X4(al[mt], tbu + ABYTES + off);
                }
#pragma unroll
                for (int p = 0; p < 4; p++) {
                    const int row = wn * 64 + p * 16 + b_r;
                    const uint32_t off = SWZ128((uint32_t)(row * 128 + kb + b_ko));
                    uint32_t rh[4], rl[4];
                    LDSM_X4(rh, tbu + 2 * ABYTES + off);
                    LDSM_X4(rl, tbu + 2 * ABYTES + 32768 + off);
#pragma unroll
                    for (int mt = 0; mt < 4; mt++) {
                        mma16816(acc[mt][2*p],   ah[mt], rh);
                        mma16816(acc[mt][2*p],   ah[mt], rl);
                        mma16816(acc[mt][2*p],   al[mt], rh);
                        mma16816(acc[mt][2*p+1], ah[mt], rh + 2);
                        mma16816(acc[mt][2*p+1], ah[mt], rl + 2);
                        mma16816(acc[mt][2*p+1], al[mt], rh + 2);
                    }
                }
            }
            __syncthreads();
        }

#pragma unroll
        for (int mt = 0; mt < 4; mt++) {
#pragma unroll
            for (int nt = 0; nt < 8; nt++) {
                const int n = n0 + wn * 64 + nt * 8 + ec;
#pragma unroll
                for (int half = 0; half < 2; half++) {
                    const int m = m0 + wm * 64 + mt * 16 + er + half * 8;
                    atomicAdd(O + (size_t)m * CCH + n,     acc[mt][nt][half * 2 + 0]);
                    atomicAdd(O + (size_t)m * CCH + n + 1, acc[mt][nt][half * 2 + 1]);
                }
            }
        }
        __syncthreads();
        ucur += c1 - c0;
    }
}

// ---------------- host orchestration ----------------
extern "C" void kernel_launch(void* const* d_in, const int* in_sizes, int n_in,
                              void* d_out, int out_size)
{
    const float* x    = (const float*)d_in[0];
    const float* r1g1 = (const float*)d_in[1];
    const float* r1w1 = (const float*)d_in[2];
    const float* r1b1 = (const float*)d_in[3];
    const float* r1g2 = (const float*)d_in[4];
    const float* r1w2 = (const float*)d_in[5];
    const float* r1b2 = (const float*)d_in[6];
    const float* atg  = (const float*)d_in[7];
    const float* qw   = (const float*)d_in[8];
    const float* qb   = (const float*)d_in[9];
    const float* kw   = (const float*)d_in[10];
    const float* kb   = (const float*)d_in[11];
    const float* vw   = (const float*)d_in[12];
    const float* vb   = (const float*)d_in[13];
    const float* pw   = (const float*)d_in[14];
    const float* pb   = (const float*)d_in[15];
    const float* r2g1 = (const float*)d_in[16];
    const float* r2w1 = (const float*)d_in[17];
    const float* r2b1 = (const float*)d_in[18];
    const float* r2g2 = (const float*)d_in[19];
    const float* r2w2 = (const float*)d_in[20];
    const float* r2b2 = (const float*)d_in[21];
    float* out = (float*)d_out;

    bf16 *nHi, *nLo, *qHi, *qLo, *kHi, *kLo, *vtHi, *vtLo, *pHi, *pLo;
    bf16 *w1Hi, *w1Lo, *w2Hi, *w2Lo, *w3Hi, *w3Lo, *w4Hi, *w4Lo;
    bf16 *qwHi, *qwLo, *kwHi, *kwLo, *vwHi, *vwLo, *pwHi, *pwLo;
    float *s, *t, *h, *y, *o;
    cudaGetSymbolAddress((void**)&nHi, g_nHi);  cudaGetSymbolAddress((void**)&nLo, g_nLo);
    cudaGetSymbolAddress((void**)&w1Hi, g_w1Hi); cudaGetSymbolAddress((void**)&w1Lo, g_w1Lo);
    cudaGetSymbolAddress((void**)&w2Hi, g_w2Hi); cudaGetSymbolAddress((void**)&w2Lo, g_w2Lo);
    cudaGetSymbolAddress((void**)&w3Hi, g_w3Hi); cudaGetSymbolAddress((void**)&w3Lo, g_w3Lo);
    cudaGetSymbolAddress((void**)&w4Hi, g_w4Hi); cudaGetSymbolAddress((void**)&w4Lo, g_w4Lo);
    cudaGetSymbolAddress((void**)&qwHi, g_qwHi); cudaGetSymbolAddress((void**)&qwLo, g_qwLo);
    cudaGetSymbolAddress((void**)&kwHi, g_kwHi); cudaGetSymbolAddress((void**)&kwLo, g_kwLo);
    cudaGetSymbolAddress((void**)&vwHi, g_vwHi); cudaGetSymbolAddress((void**)&vwLo, g_vwLo);
    cudaGetSymbolAddress((void**)&pwHi, g_pwHi); cudaGetSymbolAddress((void**)&pwLo, g_pwLo);
    cudaGetSymbolAddress((void**)&qHi, g_qHi);  cudaGetSymbolAddress((void**)&qLo, g_qLo);
    cudaGetSymbolAddress((void**)&kHi, g_kHi);  cudaGetSymbolAddress((void**)&kLo, g_kLo);
    cudaGetSymbolAddress((void**)&vtHi, g_vtHi); cudaGetSymbolAddress((void**)&vtLo, g_vtLo);
    cudaGetSymbolAddress((void**)&pHi, g_pHi);  cudaGetSymbolAddress((void**)&pLo, g_pLo);
    cudaGetSymbolAddress((void**)&s, g_s);
    cudaGetSymbolAddress((void**)&t, g_t);
    cudaGetSymbolAddress((void**)&h, g_h);
    cudaGetSymbolAddress((void**)&y, g_y);
    cudaGetSymbolAddress((void**)&o, g_o);

    int nSM = 148;
    cudaDeviceGetAttribute(&nSM, cudaDevAttrMultiProcessorCount, 0);

    const int SMB128 = 1024 + 2 * (2 * 128 * 128 + 65536) + 128 * 27 * 4;  // 211456
    const int SMB_AV = 1024 + 2 * (2 * 128 * 128 + 65536);                 // 197632
    cudaFuncSetAttribute(tc_gemm<128>, cudaFuncAttributeMaxDynamicSharedMemorySize, SMB128);
    cudaFuncSetAttribute(tc_conv_ps,   cudaFuncAttributeMaxDynamicSharedMemorySize, SMB128);
    cudaFuncSetAttribute(tc_av_ps,     cudaFuncAttributeMaxDynamicSharedMemorySize, SMB_AV);

    const dim3 gStd(2, 64);
    const dim3 gNT(32, 64);
    const dim3 tBlk(32, 8);
    const dim3 gWT3(16, 432);
    const dim3 gWT1(16, 16);
    const dim3 gVT(16, 256);
    const float rs512 = 0.04419417382415922f;
    const size_t ZB = (size_t)SPOS * CCH * sizeof(float);
    const int n4 = SPOS * CCH / 4;

    // ---- fork weight prep onto a side stream (all input-only work) ----
    cudaStream_t s2;
    cudaStreamCreateWithFlags(&s2, cudaStreamNonBlocking);
    cudaEvent_t evFork;
    cudaEventCreateWithFlags(&evFork, cudaEventDisableTiming);
    cudaEvent_t evW[8];
    for (int i = 0; i < 8; i++) cudaEventCreateWithFlags(&evW[i], cudaEventDisableTiming);

    cudaEventRecord(evFork, 0);
    cudaStreamWaitEvent(s2, evFork, 0);
    transpose_split<<<gWT3, tBlk, 0, s2>>>(r1w1, w1Hi, w1Lo, CONVK, CCH); cudaEventRecord(evW[0], s2);
    transpose_split<<<gWT3, tBlk, 0, s2>>>(r1w2, w2Hi, w2Lo, CONVK, CCH); cudaEventRecord(evW[1], s2);
    transpose_split<<<gWT1, tBlk, 0, s2>>>(qw, qwHi, qwLo, CCH, CCH);     cudaEventRecord(evW[2], s2);
    transpose_split<<<gWT1, tBlk, 0, s2>>>(kw, kwHi, kwLo, CCH, CCH);     cudaEventRecord(evW[3], s2);
    transpose_split<<<gWT1, tBlk, 0, s2>>>(vw, vwHi, vwLo, CCH, CCH);     cudaEventRecord(evW[4], s2);
    transpose_split<<<gWT1, tBlk, 0, s2>>>(pw, pwHi, pwLo, CCH, CCH);     cudaEventRecord(evW[5], s2);
    transpose_split<<<gWT3, tBlk, 0, s2>>>(r2w1, w3Hi, w3Lo, CONVK, CCH); cudaEventRecord(evW[6], s2);
    transpose_split<<<gWT3, tBlk, 0, s2>>>(r2w2, w4Hi, w4Lo, CONVK, CCH); cudaEventRecord(evW[7], s2);

    // ---- hoisted zero-fills for accumulation targets (off critical path) ----
    cudaMemsetAsync(h, 0, ZB, 0);
    cudaMemsetAsync(y, 0, ZB, 0);
    cudaMemsetAsync(o, 0, ZB, 0);
    cudaMemsetAsync(out, 0, ZB, 0);

    // ---- resnet 1 ----
    rmsnorm_split<<<SPOS / 8, 256>>>(x, r1g1, nHi, nLo, 1);
    cudaStreamWaitEvent(0, evW[0], 0);
    tc_conv_ps<<<nSM, 256, SMB128>>>(nHi, nLo, w1Hi, w1Lo, r1b1, nullptr, h, nSM);
    rmsnorm_split<<<SPOS / 8, 256>>>(h, r1g2, nHi, nLo, 1);
    cudaStreamWaitEvent(0, evW[1], 0);
    tc_conv_ps<<<nSM, 256, SMB128>>>(nHi, nLo, w2Hi, w2Lo, r1b2, x, y, nSM);

    // ---- attention ----
    rmsnorm_split<<<SPOS / 8, 256>>>(y, atg, nHi, nLo, 0);
    cudaStreamWaitEvent(0, evW[2], 0);
    tc_gemm<128><<<gStd, 512, SMB128>>>(nHi, nLo, CCH, qwHi, qwLo, CCH, qb, nullptr, nullptr, qHi, qLo, CCH, CCH, 0, 1.0f);
    cudaStreamWaitEvent(0, evW[3], 0);
    tc_gemm<128><<<gStd, 512, SMB128>>>(nHi, nLo, CCH, kwHi, kwLo, CCH, kb, nullptr, nullptr, kHi, kLo, CCH, CCH, 0, 1.0f);
    cudaStreamWaitEvent(0, evW[4], 0);
    tc_gemm<128><<<gStd, 512, SMB128>>>(nHi, nLo, CCH, vwHi, vwLo, CCH, vb, nullptr, t, nullptr, nullptr, CCH, CCH, 0, 1.0f);
    transpose_split<<<gVT, tBlk>>>(t, vtHi, vtLo, SPOS, CCH);

    tc_gemm<128><<<gNT, 512, SMB128>>>(qHi, qLo, CCH, kHi, kLo, CCH, nullptr, nullptr, s, nullptr, nullptr, SPOS, CCH, TCG_CAUSAL, rs512);
    softmax_split<<<SPOS, 256>>>(s, pHi, pLo);
    tc_av_ps<<<nSM, 256, SMB_AV>>>(pHi, pLo, vtHi, vtLo, o, nSM);
    split4_kernel<<<n4 / 256, 256>>>(o, qHi, qLo, n4);   // reuse q buffers for O split
    cudaStreamWaitEvent(0, evW[5], 0);
    tc_gemm<128><<<gStd, 512, SMB128>>>(qHi, qLo, CCH, pwHi, pwLo, CCH, pb, y, h, nullptr, nullptr, CCH, CCH, 0, 1.0f);

    // ---- resnet 2 ----
    rmsnorm_split<<<SPOS / 8, 256>>>(h, r2g1, nHi, nLo, 1);
    cudaMemsetAsync(t, 0, ZB, 0);
    cudaStreamWaitEvent(0, evW[6], 0);
    tc_conv_ps<<<nSM, 256, SMB128>>>(nHi, nLo, w3Hi, w3Lo, r2b1, nullptr, t, nSM);
    rmsnorm_split<<<SPOS / 8, 256>>>(t, r2g2, nHi, nLo, 1);
    cudaStreamWaitEvent(0, evW[7], 0);
    tc_conv_ps<<<nSM, 256, SMB128>>>(nHi, nLo, w4Hi, w4Lo, r2b2, h, out, nSM);
}

// round 16
// speedup vs baseline: 1.1754x; 1.0006x over previous
#include <cuda_runtime.h>
#include <cuda_bf16.h>
#include <cstdint>
#include <math.h>

#define SPOS 8192
#define CCH  512
#define CONVK 13824   // 27*512

typedef __nv_bfloat16 bf16;

// ---------------- scratch (static device memory) ----------------
__device__ __align__(256) bf16 g_nHi[SPOS*CCH], g_nLo[SPOS*CCH];
__device__ __align__(256) bf16 g_w1Hi[CCH*CONVK], g_w1Lo[CCH*CONVK];
__device__ __align__(256) bf16 g_w2Hi[CCH*CONVK], g_w2Lo[CCH*CONVK];
__device__ __align__(256) bf16 g_w3Hi[CCH*CONVK], g_w3Lo[CCH*CONVK];
__device__ __align__(256) bf16 g_w4Hi[CCH*CONVK], g_w4Lo[CCH*CONVK];
__device__ __align__(256) bf16 g_qwHi[CCH*CCH], g_qwLo[CCH*CCH];
__device__ __align__(256) bf16 g_kwHi[CCH*CCH], g_kwLo[CCH*CCH];
__device__ __align__(256) bf16 g_vwHi[CCH*CCH], g_vwLo[CCH*CCH];
__device__ __align__(256) bf16 g_pwHi[CCH*CCH], g_pwLo[CCH*CCH];
__device__ __align__(256) bf16 g_qHi[SPOS*CCH], g_qLo[SPOS*CCH];
__device__ __align__(256) bf16 g_kHi[SPOS*CCH], g_kLo[SPOS*CCH];
__device__ __align__(256) bf16 g_vtHi[SPOS*CCH], g_vtLo[SPOS*CCH];
__device__ __align__(256) bf16 g_pHi[(size_t)SPOS*SPOS], g_pLo[(size_t)SPOS*SPOS];
__device__ __align__(256) float g_s[(size_t)SPOS*SPOS];
__device__ __align__(256) float g_t[SPOS*CCH], g_h[SPOS*CCH], g_y[SPOS*CCH];
__device__ __align__(256) float g_o[SPOS*CCH];

// ---------------- helpers ----------------
__device__ __forceinline__ uint32_t smem_u32(const void* p) {
    uint32_t a;
    asm("{ .reg .u64 t; cvta.to.shared.u64 t, %1; cvt.u32.u64 %0, t; }" : "=r"(a) : "l"(p));
    return a;
}
__device__ __forceinline__ void cp16(uint32_t dst, const void* src) {
    asm volatile("cp.async.cg.shared.global [%0], [%1], 16;" :: "r"(dst), "l"(src));
}
#define CP_COMMIT() asm volatile("cp.async.commit_group;" ::: "memory")
#define CP_WAIT1()  asm volatile("cp.async.wait_group 1;" ::: "memory")
#define CP_WAIT0()  asm volatile("cp.async.wait_group 0;" ::: "memory")
#define SWZ128(b) ((b) ^ (((b) >> 3) & 0x70))

#define LDSM_X4(r, addr) \
    asm volatile("ldmatrix.sync.aligned.m8n8.x4.shared.b16 {%0,%1,%2,%3}, [%4];" \
        : "=r"((r)[0]), "=r"((r)[1]), "=r"((r)[2]), "=r"((r)[3]) : "r"(addr))

__device__ __forceinline__ void mma16816(float* c, const uint32_t* a, const uint32_t* b) {
    asm volatile(
        "mma.sync.aligned.m16n8k16.row.col.f32.bf16.bf16.f32 "
        "{%0,%1,%2,%3},{%4,%5,%6,%7},{%8,%9},{%0,%1,%2,%3};"
        : "+f"(c[0]), "+f"(c[1]), "+f"(c[2]), "+f"(c[3])
        : "r"(a[0]), "r"(a[1]), "r"(a[2]), "r"(a[3]), "r"(b[0]), "r"(b[1]));
}

__device__ __forceinline__ float warpReduceSum(float v) {
#pragma unroll
    for (int o = 16; o; o >>= 1) v += __shfl_xor_sync(0xffffffffu, v, o);
    return v;
}
__device__ __forceinline__ float warpReduceMax(float v) {
#pragma unroll
    for (int o = 16; o; o >>= 1) v = fmaxf(v, __shfl_xor_sync(0xffffffffu, v, o));
    return v;
}
__device__ __forceinline__ uint32_t pack_bf16x2(float a, float b) {
    __nv_bfloat162 h;
    h.x = __float2bfloat16(a);
    h.y = __float2bfloat16(b);
    return *(uint32_t*)&h;
}

// ---------------- rmsnorm + silu + bf16 split (warp-per-row) ----------------
__global__ __launch_bounds__(256) void rmsnorm_split(
    const float* __restrict__ x, const float* __restrict__ g,
    bf16* __restrict__ hi, bf16* __restrict__ lo, int do_silu)
{
    const int wid = threadIdx.x >> 5, lid = threadIdx.x & 31;
    const int r = blockIdx.x * 8 + wid;
    const float* xr = x + (size_t)r * CCH;

    float v[16];
    float ss = 0.0f;
#pragma unroll
    for (int i = 0; i < 4; i++) {
        const float4 t = *(const float4*)(xr + i * 128 + lid * 4);
        v[4*i+0] = t.x; v[4*i+1] = t.y; v[4*i+2] = t.z; v[4*i+3] = t.w;
        ss += t.x*t.x + t.y*t.y + t.z*t.z + t.w*t.w;
    }
    ss = warpReduceSum(ss);
    const float scale = 22.62741699796952f / (sqrtf(ss) + 1e-8f);

#pragma unroll
    for (int i = 0; i < 4; i++) {
        const float4 gg = *(const float4*)(g + i * 128 + lid * 4);
        float o[4];
        o[0] = v[4*i+0]*scale*gg.x; o[1] = v[4*i+1]*scale*gg.y;
        o[2] = v[4*i+2]*scale*gg.z; o[3] = v[4*i+3]*scale*gg.w;
        if (do_silu) {
#pragma unroll
            for (int j = 0; j < 4; j++) o[j] = o[j] / (1.0f + __expf(-o[j]));
        }
        float l[4];
#pragma unroll
        for (int j = 0; j < 4; j++) {
            bf16 h = __float2bfloat16(o[j]);
            l[j] = o[j] - __bfloat162float(h);
        }
        const size_t base = (size_t)r * CCH + i * 128 + lid * 4;
        *(uint2*)(hi + base) = make_uint2(pack_bf16x2(o[0], o[1]), pack_bf16x2(o[2], o[3]));
        *(uint2*)(lo + base) = make_uint2(pack_bf16x2(l[0], l[1]), pack_bf16x2(l[2], l[3]));
    }
}

// ---------------- plain bf16 split (packed stores) ----------------
__global__ __launch_bounds__(256) void split4_kernel(
    const float* __restrict__ in, bf16* __restrict__ hi, bf16* __restrict__ lo, int n4)
{
    const int i = blockIdx.x * 256 + threadIdx.x;
    if (i >= n4) return;
    const float4 v = ((const float4*)in)[i];
    float o[4] = {v.x, v.y, v.z, v.w};
    float l[4];
#pragma unroll
    for (int j = 0; j < 4; j++) {
        bf16 h = __float2bfloat16(o[j]);
        l[j] = o[j] - __bfloat162float(h);
    }
    const size_t base = (size_t)i * 4;
    *(uint2*)(hi + base) = make_uint2(pack_bf16x2(o[0], o[1]), pack_bf16x2(o[2], o[3]));
    *(uint2*)(lo + base) = make_uint2(pack_bf16x2(l[0], l[1]), pack_bf16x2(l[2], l[3]));
}

// ---------------- transpose + split ----------------
__global__ void transpose_split(
    const float* __restrict__ in, bf16* __restrict__ hi, bf16* __restrict__ lo, int R, int Cc)
{
    __shared__ float t[32][33];
    const int c0 = blockIdx.x * 32, r0 = blockIdx.y * 32;
    const int tx = threadIdx.x;
    for (int j = threadIdx.y; j < 32; j += 8)
        t[j][tx] = in[(size_t)(r0 + j) * Cc + c0 + tx];
    __syncthreads();
    for (int j = threadIdx.y; j < 32; j += 8) {
        float v = t[tx][j];
        bf16 h = __float2bfloat16(v);
        const size_t o = (size_t)(c0 + j) * R + r0 + tx;
        hi[o] = h;
        lo[o] = __float2bfloat16(v - __bfloat162float(h));
    }
}

// ---------------- softmax -> bf16 split probs (vectorized) ----------------
__global__ __launch_bounds__(256) void softmax_split(
    const float* __restrict__ S, bf16* __restrict__ PHi, bf16* __restrict__ PLo)
{
    __shared__ float red[8];
    const int r = blockIdx.x, tid = threadIdx.x;
    const int cnt = ((r >> 10) + 1) * 2;
    const float* row = S + (size_t)r * SPOS;

    float2 vals[16];
    float mx = -3.4e38f;
#pragma unroll
    for (int i = 0; i < 16; i++)
        if (i < cnt) {
            vals[i] = *(const float2*)(row + i * 512 + 2 * tid);
            mx = fmaxf(mx, fmaxf(vals[i].x, vals[i].y));
        }
    mx = warpReduceMax(mx);
    if ((tid & 31) == 0) red[tid >> 5] = mx;
    __syncthreads();
    float m2 = red[0];
#pragma unroll
    for (int i = 1; i < 8; i++) m2 = fmaxf(m2, red[i]);
    __syncthreads();
    float sum = 0.0f;
#pragma unroll
    for (int i = 0; i < 16; i++)
        if (i < cnt) {
            vals[i].x = __expf(vals[i].x - m2);
            vals[i].y = __expf(vals[i].y - m2);
            sum += vals[i].x + vals[i].y;
        }
    sum = warpReduceSum(sum);
    if ((tid & 31) == 0) red[tid >> 5] = sum;
    __syncthreads();
    float tot = 0.0f;
#pragma unroll
    for (int i = 0; i < 8; i++) tot += red[i];
    const float inv = 1.0f / tot;
    bf16* ph = PHi + (size_t)r * SPOS;
    bf16* pl = PLo + (size_t)r * SPOS;
#pragma unroll
    for (int i = 0; i < 16; i++)
        if (i < cnt) {
            const float p0 = vals[i].x * inv, p1 = vals[i].y * inv;
            const bf16 h0 = __float2bfloat16(p0), h1 = __float2bfloat16(p1);
            const float l0 = p0 - __bfloat162float(h0), l1 = p1 - __bfloat162float(h1);
            __nv_bfloat162 hh; hh.x = h0; hh.y = h1;
            *(__nv_bfloat162*)(ph + i * 512 + 2 * tid) = hh;
            *(uint32_t*)(pl + i * 512 + 2 * tid) = pack_bf16x2(l0, l1);
        }
}

// ---------------- HMMA split-bf16 GEMM, CTA tile 128x256, 512 threads ----------------
#define TCG_GATHER 1
#define TCG_VARK   2
#define TCG_CAUSAL 4

template<int BM>
__global__ __launch_bounds__(512) void tc_gemm(
    const bf16* __restrict__ AHi, const bf16* __restrict__ ALo, int ldA,
    const bf16* __restrict__ BHi, const bf16* __restrict__ BLo, int ldB,
    const float* __restrict__ bias, const float* __restrict__ resid,
    float* __restrict__ C, bf16* __restrict__ outHi, bf16* __restrict__ outLo,
    int ldc, int Ktot, int flags, float scale)
{
    constexpr int WN = (BM == 128) ? 8 : 16;
    constexpr int NT = 32 / WN * 2 / 2;
    constexpr int NP = (BM == 128) ? 2 : 1;
    constexpr int WNW = 256 / WN;
    constexpr int ABYTES = BM * 128;
    constexpr int STAGEB = 2 * ABYTES + 65536;

    extern __shared__ char smem[];
    int mtile = blockIdx.y;
    if (flags & TCG_VARK) mtile = gridDim.y - 1 - blockIdx.y;
    const int m0 = mtile * BM, n0 = blockIdx.x * 256;
    if (flags & TCG_CAUSAL) { if (n0 >= (((m0 >> 10) + 1) << 10)) return; }
    int Keff = Ktot;
    if (flags & TCG_VARK)   { Keff = ((m0 >> 10) + 1) << 10; }

    const uint32_t sb = smem_u32(smem);
    const uint32_t tbase = (sb + 1023) & ~1023u;
    char* tiles = smem + (tbase - sb);
    int* sBase = (int*)(tiles + 2 * STAGEB);

    const int tid = threadIdx.x, wid = tid >> 5, lid = tid & 31;
    const int wm = wid / WN, wn = wid % WN;
    const bool gather = (flags & TCG_GATHER);

    if (gather) {
        for (int i = tid; i < BM * 27; i += 512) {
            const int mloc = i / 27, tap = i - mloc * 27;
            const int m = m0 + mloc;
            const int kt = tap / 9, r9 = tap - kt * 9, kh = r9 / 3, kw = r9 - kh * 3;
            const int t = m >> 10, hw = m & 1023, h = hw >> 5, w = hw & 31;
            int tin = t + kt - 2; tin = tin < 0 ? 0 : tin;
            int hin = h + kh - 1; hin = hin < 0 ? 0 : (hin > 31 ? 31 : hin);
            int win = w + kw - 1; win = win < 0 ? 0 : (win > 31 ? 31 : win);
            sBase[i] = ((tin << 10) + (hin << 5) + win) << 9;
        }
        __syncthreads();
    }

    auto load_chunk = [&](int c, int buf) {
        const uint32_t tbu = tbase + buf * STAGEB;
        const long kkB = (long)c << 6;
        const int tap = c >> 3, c0 = (c & 7) << 6;
#pragma unroll
        for (int it = 0; it < BM / 64; it++) {
            const int i = it * 512 + tid;
            const int row = i >> 3, seg = i & 7;
            long offA;
            if (gather) offA = (long)sBase[row * 27 + tap] + c0 + (seg << 3);
            else        offA = (long)(m0 + row) * ldA + kkB + (seg << 3);
            const uint32_t d = SWZ128((uint32_t)(row * 128 + seg * 16));
            cp16(tbu + d,          AHi + offA);
            cp16(tbu + ABYTES + d, ALo + offA);
        }
#pragma unroll
        for (int it = 0; it < 4; it++) {
            const int i = it * 512 + tid;
            const int row = i >> 3, seg = i & 7;
            const long offB = (long)(n0 + row) * ldB + kkB + (seg << 3);
            const uint32_t d = SWZ128((uint32_t)(row * 128 + seg * 16));
            cp16(tbu + 2 * ABYTES + d,         BHi + offB);
            cp16(tbu + 2 * ABYTES + 32768 + d, BLo + offB);
        }
    };

    float acc[4][NT][4];
#pragma unroll
    for (int a = 0; a < 4; a++)
#pragma unroll
        for (int b = 0; b < NT; b++)
#pragma unroll
            for (int i = 0; i < 4; i++) acc[a][b][i] = 0.0f;

    const int a_r = lid & 15, a_ko = (lid >> 4) * 16;
    const int b_r = ((lid >> 4) << 3) + (lid & 7);
    const int b_ko = ((lid >> 3) & 1) * 16;

    const int nc = Keff >> 6;
    load_chunk(0, 0);
    CP_COMMIT();

    for (int c = 0; c < nc; c++) {
        if (c + 1 < nc) { load_chunk(c + 1, (c + 1) & 1); CP_COMMIT(); CP_WAIT1(); }
        else            { CP_WAIT0(); }
        __syncthreads();

        const uint32_t tbu = tbase + (c & 1) * STAGEB;
#pragma unroll
        for (int ks = 0; ks < 4; ks++) {
            const int kb = ks * 32;
            uint32_t ah[4][4], al[4][4];
#pragma unroll
            for (int mt = 0; mt < 4; mt++) {
                const int row = wm * 64 + mt * 16 + a_r;
                const uint32_t off = SWZ128((uint32_t)(row * 128 + kb + a_ko));
                LDSM_X4(ah[mt], tbu + off);
                LDSM_X4(al[mt], tbu + ABYTES + off);
            }
#pragma unroll
            for (int p = 0; p < NP; p++) {
                const int row = wn * WNW + p * 16 + b_r;
                const uint32_t off = SWZ128((uint32_t)(row * 128 + kb + b_ko));
                uint32_t rh[4], rl[4];
                LDSM_X4(rh, tbu + 2 * ABYTES + off);
                LDSM_X4(rl, tbu + 2 * ABYTES + 32768 + off);
#pragma unroll
                for (int mt = 0; mt < 4; mt++) {
                    mma16816(acc[mt][2*p],   ah[mt], rh);
                    mma16816(acc[mt][2*p],   ah[mt], rl);
                    mma16816(acc[mt][2*p],   al[mt], rh);
                    mma16816(acc[mt][2*p+1], ah[mt], rh + 2);
                    mma16816(acc[mt][2*p+1], ah[mt], rl + 2);
                    mma16816(acc[mt][2*p+1], al[mt], rh + 2);
                }
            }
        }
        __syncthreads();
    }

    const int er = lid >> 2, ec = (lid & 3) * 2;
#pragma unroll
    for (int mt = 0; mt < 4; mt++) {
#pragma unroll
        for (int nt = 0; nt < NT; nt++) {
            const int n = n0 + wn * WNW + nt * 8 + ec;
            float b0 = 0.f, b1 = 0.f;
            if (bias) { b0 = bias[n]; b1 = bias[n + 1]; }
#pragma unroll
            for (int half = 0; half < 2; half++) {
                const int m = m0 + wm * 64 + mt * 16 + er + half * 8;
                float v0 = acc[mt][nt][half * 2 + 0] * scale + b0;
                float v1 = acc[mt][nt][half * 2 + 1] * scale + b1;
                if (resid) {
                    const float2 rv = *(const float2*)(resid + (size_t)m * ldc + n);
                    v0 += rv.x; v1 += rv.y;
                }
                if (C)
                    *(float2*)(C + (size_t)m * ldc + n) = make_float2(v0, v1);
                if (outHi) {
                    bf16 h0 = __float2bfloat16(v0), h1 = __float2bfloat16(v1);
                    __nv_bfloat162 hh; hh.x = h0; hh.y = h1;
                    __nv_bfloat162 ll;
                    ll.x = __float2bfloat16(v0 - __bfloat162float(h0));
                    ll.y = __float2bfloat16(v1 - __bfloat162float(h1));
                    *(__nv_bfloat162*)(outHi + (size_t)m * ldc + n) = hh;
                    *(__nv_bfloat162*)(outLo + (size_t)m * ldc + n) = ll;
                }
            }
        }
    }
}

// ---------------- fused Q/K/V projection: grid (2, 192); sel = blockIdx.y>>6 ----------------
__global__ __launch_bounds__(512) void tc_qkv(
    const bf16* __restrict__ AHi, const bf16* __restrict__ ALo,
    const bf16* __restrict__ qwHi, const bf16* __restrict__ qwLo,
    const bf16* __restrict__ kwHi, const bf16* __restrict__ kwLo,
    const bf16* __restrict__ vwHi, const bf16* __restrict__ vwLo,
    const float* __restrict__ qb, const float* __restrict__ kb, const float* __restrict__ vb,
    bf16* __restrict__ qHi, bf16* __restrict__ qLo,
    bf16* __restrict__ kHi, bf16* __restrict__ kLo,
    float* __restrict__ vOut)
{
    constexpr int ABYTES = 128 * 128;
    constexpr int STAGEB = 2 * ABYTES + 65536;

    extern __shared__ char smem[];
    const int sel = blockIdx.y >> 6;
    const int m0 = (blockIdx.y & 63) * 128, n0 = blockIdx.x * 256;

    const bf16* BHi = (sel == 0) ? qwHi : (sel == 1) ? kwHi : vwHi;
    const bf16* BLo = (sel == 0) ? qwLo : (sel == 1) ? kwLo : vwLo;
    const float* bias = (sel == 0) ? qb : (sel == 1) ? kb : vb;

    const uint32_t sb = smem_u32(smem);
    const uint32_t tbase = (sb + 1023) & ~1023u;

    const int tid = threadIdx.x, wid = tid >> 5, lid = tid & 31;
    const int wm = wid >> 3, wn = wid & 7;
    const int a_r = lid & 15, a_ko = (lid >> 4) * 16;
    const int b_r = ((lid >> 4) << 3) + (lid & 7);
    const int b_ko = ((lid >> 3) & 1) * 16;

    auto load_chunk = [&](int c, int buf) {
        const uint32_t tbu = tbase + buf * STAGEB;
        const long kkB = (long)c << 6;
#pragma unroll
        for (int it = 0; it < 2; it++) {
            const int i = it * 512 + tid;
            const int row = i >> 3, seg = i & 7;
            const long offA = (long)(m0 + row) * CCH + kkB + (seg << 3);
            const uint32_t d = SWZ128((uint32_t)(row * 128 + seg * 16));
            cp16(tbu + d,          AHi + offA);
            cp16(tbu + ABYTES + d, ALo + offA);
        }
#pragma unroll
        for (int it = 0; it < 4; it++) {
            const int i = it * 512 + tid;
            const int row = i >> 3, seg = i & 7;
            const long offB = (long)(n0 + row) * CCH + kkB + (seg << 3);
            const uint32_t d = SWZ128((uint32_t)(row * 128 + seg * 16));
            cp16(tbu + 2 * ABYTES + d,         BHi + offB);
            cp16(tbu + 2 * ABYTES + 32768 + d, BLo + offB);
        }
    };

    float acc[4][4][4];
#pragma unroll
    for (int a = 0; a < 4; a++)
#pragma unroll
        for (int b = 0; b < 4; b++)
#pragma unroll
            for (int i = 0; i < 4; i++) acc[a][b][i] = 0.0f;

    load_chunk(0, 0);
    CP_COMMIT();

    for (int c = 0; c < 8; c++) {
        if (c + 1 < 8) { load_chunk(c + 1, (c + 1) & 1); CP_COMMIT(); CP_WAIT1(); }
        else           { CP_WAIT0(); }
        __syncthreads();

        const uint32_t tbu = tbase + (c & 1) * STAGEB;
#pragma unroll
        for (int ks = 0; ks < 4; ks++) {
            const int kb = ks * 32;
            uint32_t ah[4][4], al[4][4];
#pragma unroll
            for (int mt = 0; mt < 4; mt++) {
                const int row = wm * 64 + mt * 16 + a_r;
                const uint32_t off = SWZ128((uint32_t)(row * 128 + kb + a_ko));
                LDSM_X4(ah[mt], tbu + off);
                LDSM_X4(al[mt], tbu + ABYTES + off);
            }
#pragma unroll
            for (int p = 0; p < 2; p++) {
                const int row = wn * 32 + p * 16 + b_r;
                const uint32_t off = SWZ128((uint32_t)(row * 128 + kb + b_ko));
                uint32_t rh[4], rl[4];
                LDSM_X4(rh, tbu + 2 * ABYTES + off);
                LDSM_X4(rl, tbu + 2 * ABYTES + 32768 + off);
#pragma unroll
                for (int mt = 0; mt < 4; mt++) {
                    mma16816(acc[mt][2*p],   ah[mt], rh);
                    mma16816(acc[mt][2*p],   ah[mt], rl);
                    mma16816(acc[mt][2*p],   al[mt], rh);
                    mma16816(acc[mt][2*p+1], ah[mt], rh + 2);
                    mma16816(acc[mt][2*p+1], ah[mt], rl + 2);
                    mma16816(acc[mt][2*p+1], al[mt], rh + 2);
                }
            }
        }
        __syncthreads();
    }

    bf16* outHi = (sel == 0) ? qHi : (sel == 1) ? kHi : nullptr;
    bf16* outLo = (sel == 0) ? qLo : (sel == 1) ? kLo : nullptr;

    const int er = lid >> 2, ec = (lid & 3) * 2;
#pragma unroll
    for (int mt = 0; mt < 4; mt++) {
#pragma unroll
        for (int nt = 0; nt < 4; nt++) {
            const int n = n0 + wn * 32 + nt * 8 + ec;
            const float b0 = bias[n], b1 = bias[n + 1];
#pragma unroll
            for (int half = 0; half < 2; half++) {
                const int m = m0 + wm * 64 + mt * 16 + er + half * 8;
                const float v0 = acc[mt][nt][half * 2 + 0] + b0;
                const float v1 = acc[mt][nt][half * 2 + 1] + b1;
                if (sel == 2) {
                    *(float2*)(vOut + (size_t)m * CCH + n) = make_float2(v0, v1);
                } else {
                    bf16 h0 = __float2bfloat16(v0), h1 = __float2bfloat16(v1);
                    __nv_bfloat162 hh; hh.x = h0; hh.y = h1;
                    __nv_bfloat162 ll;
                    ll.x = __float2bfloat16(v0 - __bfloat162float(h0));
                    ll.y = __float2bfloat16(v1 - __bfloat162float(h1));
                    *(__nv_bfloat162*)(outHi + (size_t)m * CCH + n) = hh;
                    *(__nv_bfloat162*)(outLo + (size_t)m * CCH + n) = ll;
                }
            }
        }
    }
}

// ---------------- persistent balanced split-K conv GEMM (128x256, 2x4 warps) ----------------
__global__ __launch_bounds__(256) void tc_conv_ps(
    const bf16* __restrict__ AHi, const bf16* __restrict__ ALo,
    const bf16* __restrict__ BHi, const bf16* __restrict__ BLo,
    const float* __restrict__ bias, const float* __restrict__ resid,
    float* __restrict__ C, int nW)
{
    constexpr int ABYTES = 128 * 128;
    constexpr int STAGEB = 2 * ABYTES + 65536;

    extern __shared__ char smem[];
    const uint32_t sb = smem_u32(smem);
    const uint32_t tbase = (sb + 1023) & ~1023u;
    char* tiles = smem + (tbase - sb);
    int* sBase = (int*)(tiles + 2 * STAGEB);

    const int tid = threadIdx.x, wid = tid >> 5, lid = tid & 31;
    const int wm = wid >> 2, wn = wid & 3;
    const int a_r = lid & 15, a_ko = (lid >> 4) * 16;
    const int b_r = ((lid >> 4) << 3) + (lid & 7);
    const int b_ko = ((lid >> 3) & 1) * 16;
    const int er = lid >> 2, ec = (lid & 3) * 2;

    const long TC = 128L * 216;
    const long u0 = (long)blockIdx.x * TC / nW;
    const long u1 = (long)(blockIdx.x + 1) * TC / nW;
    if (u1 <= u0) return;
    const int t0 = (int)(u0 / 216), t1 = (int)((u1 - 1) / 216);

    for (int tau = t0; tau <= t1; tau++) {
        const int c0 = (tau == t0) ? (int)(u0 - (long)tau * 216) : 0;
        const int c1 = (tau == t1) ? (int)(u1 - (long)tau * 216) : 216;
        const int m0 = (tau >> 1) * 128, n0 = (tau & 1) * 256;

        for (int i = tid; i < 128 * 27; i += 256) {
            const int mloc = i / 27, tap = i - mloc * 27;
            const int m = m0 + mloc;
            const int kt = tap / 9, r9 = tap - kt * 9, kh = r9 / 3, kw = r9 - kh * 3;
            const int t = m >> 10, hw = m & 1023, h = hw >> 5, w = hw & 31;
            int tin = t + kt - 2; tin = tin < 0 ? 0 : tin;
            int hin = h + kh - 1; hin = hin < 0 ? 0 : (hin > 31 ? 31 : hin);
            int win = w + kw - 1; win = win < 0 ? 0 : (win > 31 ? 31 : win);
            sBase[i] = ((tin << 10) + (hin << 5) + win) << 9;
        }
        __syncthreads();

        auto load_chunk = [&](int c, int buf) {
            const uint32_t tbu = tbase + buf * STAGEB;
            const long kkB = (long)c << 6;
            const int tap = c >> 3, cc0 = (c & 7) << 6;
#pragma unroll
            for (int it = 0; it < 4; it++) {
                const int i = it * 256 + tid;
                const int row = i >> 3, seg = i & 7;
                const long offA = (long)sBase[row * 27 + tap] + cc0 + (seg << 3);
                const uint32_t d = SWZ128((uint32_t)(row * 128 + seg * 16));
                cp16(tbu + d,          AHi + offA);
                cp16(tbu + ABYTES + d, ALo + offA);
            }
#pragma unroll
            for (int it = 0; it < 8; it++) {
                const int i = it * 256 + tid;
                const int row = i >> 3, seg = i & 7;
                const long offB = (long)(n0 + row) * CONVK + kkB + (seg << 3);
                const uint32_t d = SWZ128((uint32_t)(row * 128 + seg * 16));
                cp16(tbu + 2 * ABYTES + d,         BHi + offB);
                cp16(tbu + 2 * ABYTES + 32768 + d, BLo + offB);
            }
        };

        float acc[4][8][4];
#pragma unroll
        for (int a = 0; a < 4; a++)
#pragma unroll
            for (int b = 0; b < 8; b++)
#pragma unroll
                for (int i = 0; i < 4; i++) acc[a][b][i] = 0.0f;

        load_chunk(c0, c0 & 1);
        CP_COMMIT();

        for (int c = c0; c < c1; c++) {
            if (c + 1 < c1) { load_chunk(c + 1, (c + 1) & 1); CP_COMMIT(); CP_WAIT1(); }
            else            { CP_WAIT0(); }
            __syncthreads();

            const uint32_t tbu = tbase + (c & 1) * STAGEB;
#pragma unroll
            for (int ks = 0; ks < 4; ks++) {
                const int kb = ks * 32;
                uint32_t ah[4][4], al[4][4];
#pragma unroll
                for (int mt = 0; mt < 4; mt++) {
                    const int row = wm * 64 + mt * 16 + a_r;
                    const uint32_t off = SWZ128((uint32_t)(row * 128 + kb + a_ko));
                    LDSM_X4(ah[mt], tbu + off);
                    LDSM_X4(al[mt], tbu + ABYTES + off);
                }
#pragma unroll
                for (int p = 0; p < 4; p++) {
                    const int row = wn * 64 + p * 16 + b_r;
                    const uint32_t off = SWZ128((uint32_t)(row * 128 + kb + b_ko));
                    uint32_t rh[4], rl[4];
                    LDSM_X4(rh, tbu + 2 * ABYTES + off);
                    LDSM_X4(rl, tbu + 2 * ABYTES + 32768 + off);
#pragma unroll
                    for (int mt = 0; mt < 4; mt++) {
                        mma16816(acc[mt][2*p],   ah[mt], rh);
                        mma16816(acc[mt][2*p],   ah[mt], rl);
                        mma16816(acc[mt][2*p],   al[mt], rh);
                        mma16816(acc[mt][2*p+1], ah[mt], rh + 2);
                        mma16816(acc[mt][2*p+1], ah[mt], rl + 2);
                        mma16816(acc[mt][2*p+1], al[mt], rh + 2);
                    }
                }
            }
            __syncthreads();
        }

        const bool lead = (c0 == 0);
#pragma unroll
        for (int mt = 0; mt < 4; mt++) {
#pragma unroll
            for (int nt = 0; nt < 8; nt++) {
                const int n = n0 + wn * 64 + nt * 8 + ec;
                float b0 = 0.f, b1 = 0.f;
                if (lead) { b0 = bias[n]; b1 = bias[n + 1]; }
#pragma unroll
                for (int half = 0; half < 2; half++) {
                    const int m = m0 + wm * 64 + mt * 16 + er + half * 8;
                    float v0 = acc[mt][nt][half * 2 + 0] + b0;
                    float v1 = acc[mt][nt][half * 2 + 1] + b1;
                    if (lead && resid) {
                        const float2 rv = *(const float2*)(resid + (size_t)m * CCH + n);
                        v0 += rv.x; v1 += rv.y;
                    }
                    atomicAdd(C + (size_t)m * CCH + n,     v0);
                    atomicAdd(C + (size_t)m * CCH + n + 1, v1);
                }
            }
        }
        __syncthreads();
    }
}

// ---------------- persistent balanced split-K A*V GEMM (varK triangular) ----------------
__global__ __launch_bounds__(256) void tc_av_ps(
    const bf16* __restrict__ PHi, const bf16* __restrict__ PLo,
    const bf16* __restrict__ VHi, const bf16* __restrict__ VLo,
    float* __restrict__ O, int nW)
{
    constexpr int ABYTES = 128 * 128;
    constexpr int STAGEB = 2 * ABYTES + 65536;

    extern __shared__ char smem[];
    const uint32_t sb = smem_u32(smem);
    const uint32_t tbase = (sb + 1023) & ~1023u;
    char* tiles = smem + (tbase - sb);

    const int tid = threadIdx.x, wid = tid >> 5, lid = tid & 31;
    const int wm = wid >> 2, wn = wid & 3;
    const int a_r = lid & 15, a_ko = (lid >> 4) * 16;
    const int b_r = ((lid >> 4) << 3) + (lid & 7);
    const int b_ko = ((lid >> 3) & 1) * 16;
    const int er = lid >> 2, ec = (lid & 3) * 2;

    const long TU = 9216;
    const long u0 = (long)blockIdx.x * TU / nW;
    const long u1 = (long)(blockIdx.x + 1) * TU / nW;
    long ucur = u0;

    while (ucur < u1) {
        int g = 0;
        while (g < 7 && 128L * (g + 1) * (g + 2) <= ucur) g++;
        const long Pg = 128L * g * (g + 1);
        const int L = 16 * (g + 1);
        const long rem = ucur - Pg;
        const int tl = (int)(rem / L);
        const int c0 = (int)(rem - (long)tl * L);
        int c1 = c0 + (int)(u1 - ucur);
        if (c1 > L) c1 = L;
        const int m0 = (g * 8 + (tl >> 1)) * 128;
        const int n0 = (tl & 1) * 256;

        auto load_chunk = [&](int c, int buf) {
            const uint32_t tbu = tbase + buf * STAGEB;
            const long kkB = (long)c << 6;
#pragma unroll
            for (int it = 0; it < 4; it++) {
                const int i = it * 256 + tid;
                const int row = i >> 3, seg = i & 7;
                const long offA = (long)(m0 + row) * SPOS + kkB + (seg << 3);
                const uint32_t d = SWZ128((uint32_t)(row * 128 + seg * 16));
                cp16(tbu + d,          PHi + offA);
                cp16(tbu + ABYTES + d, PLo + offA);
            }
#pragma unroll
            for (int it = 0; it < 8; it++) {
                const int i = it * 256 + tid;
                const int row = i >> 3, seg = i & 7;
                const long offB = (long)(n0 + row) * SPOS + kkB + (seg << 3);
                const uint32_t d = SWZ128((uint32_t)(row * 128 + seg * 16));
                cp16(tbu + 2 * ABYTES + d,         VHi + offB);
                cp16(tbu + 2 * ABYTES + 32768 + d, VLo + offB);
            }
        };

        float acc[4][8][4];
#pragma unroll
        for (int a = 0; a < 4; a++)
#pragma unroll
            for (int b = 0; b < 8; b++)
#pragma unroll
                for (int i = 0; i < 4; i++) acc[a][b][i] = 0.0f;

        load_chunk(c0, c0 & 1);
        CP_COMMIT();

        for (int c = c0; c < c1; c++) {
            if (c + 1 < c1) { load_chunk(c + 1, (c + 1) & 1); CP_COMMIT(); CP_WAIT1(); }
            else            { CP_WAIT0(); }
            __syncthreads();

            const uint32_t tbu = tbase + (c & 1) * STAGEB;
#pragma unroll
            for (int ks = 0; ks < 4; ks++) {
                const int kb = ks * 32;
                uint32_t ah[4][4], al[4][4];
#pragma unroll
                for (int mt = 0; mt < 4; mt++) {
                    const int row = wm * 64 + mt * 16 + a_r;
                    const uint32_t off = SWZ128((uint32_t)(row * 128 + kb + a_ko));
                    LDSM_X4(ah[mt], tbu + off);
                    LDSM_X4(al[mt], tbu + ABYTES + off);
                }
#pragma unroll
                for (int p = 0; p < 4; p++) {
                    const int row = wn * 64 + p * 16 + b_r;
                    const uint32_t off = SWZ128((uint32_t)(row * 128 + kb + b_ko));
                    uint32_t rh[4], rl[4];
                    LDSM_X4(rh, tbu + 2 * ABYTES + off);
                    LDSM_X4(rl, tbu + 2 * ABYTES + 32768 + off);
#pragma unroll
                    for (int mt = 0; mt < 4; mt++) {
                        mma16816(acc[mt][2*p],   ah[mt], rh);
                        mma16816(acc[mt][2*p],   ah[mt], rl);
                        mma16816(acc[mt][2*p],   al[mt], rh);
                        mma16816(acc[mt][2*p+1], ah[mt], rh + 2);
                        mma16816(acc[mt][2*p+1], ah[mt], rl + 2);
                        mma16816(acc[mt][2*p+1], al[mt], rh + 2);
                    }
                }
            }
            __syncthreads();
        }

#pragma unroll
        for (int mt = 0; mt < 4; mt++) {
#pragma unroll
            for (int nt = 0; nt < 8; nt++) {
                const int n = n0 + wn * 64 + nt * 8 + ec;
#pragma unroll
                for (int half = 0; half < 2; half++) {
                    const int m = m0 + wm * 64 + mt * 16 + er + half * 8;
                    atomicAdd(O + (size_t)m * CCH + n,     acc[mt][nt][half * 2 + 0]);
                    atomicAdd(O + (size_t)m * CCH + n + 1, acc[mt][nt][half * 2 + 1]);
                }
            }
        }
        __syncthreads();
        ucur += c1 - c0;
    }
}

// ---------------- host orchestration ----------------
extern "C" void kernel_launch(void* const* d_in, const int* in_sizes, int n_in,
                              void* d_out, int out_size)
{
    const float* x    = (const float*)d_in[0];
    const float* r1g1 = (const float*)d_in[1];
    const float* r1w1 = (const float*)d_in[2];
    const float* r1b1 = (const float*)d_in[3];
    const float* r1g2 = (const float*)d_in[4];
    const float* r1w2 = (const float*)d_in[5];
    const float* r1b2 = (const float*)d_in[6];
    const float* atg  = (const float*)d_in[7];
    const float* qw   = (const float*)d_in[8];
    const float* qb   = (const float*)d_in[9];
    const float* kw   = (const float*)d_in[10];
    const float* kb   = (const float*)d_in[11];
    const float* vw   = (const float*)d_in[12];
    const float* vb   = (const float*)d_in[13];
    const float* pw   = (const float*)d_in[14];
    const float* pb   = (const float*)d_in[15];
    const float* r2g1 = (const float*)d_in[16];
    const float* r2w1 = (const float*)d_in[17];
    const float* r2b1 = (const float*)d_in[18];
    const float* r2g2 = (const float*)d_in[19];
    const float* r2w2 = (const float*)d_in[20];
    const float* r2b2 = (const float*)d_in[21];
    float* out = (float*)d_out;

    bf16 *nHi, *nLo, *qHi, *qLo, *kHi, *kLo, *vtHi, *vtLo, *pHi, *pLo;
    bf16 *w1Hi, *w1Lo, *w2Hi, *w2Lo, *w3Hi, *w3Lo, *w4Hi, *w4Lo;
    bf16 *qwHi, *qwLo, *kwHi, *kwLo, *vwHi, *vwLo, *pwHi, *pwLo;
    float *s, *t, *h, *y, *o;
    cudaGetSymbolAddress((void**)&nHi, g_nHi);  cudaGetSymbolAddress((void**)&nLo, g_nLo);
    cudaGetSymbolAddress((void**)&w1Hi, g_w1Hi); cudaGetSymbolAddress((void**)&w1Lo, g_w1Lo);
    cudaGetSymbolAddress((void**)&w2Hi, g_w2Hi); cudaGetSymbolAddress((void**)&w2Lo, g_w2Lo);
    cudaGetSymbolAddress((void**)&w3Hi, g_w3Hi); cudaGetSymbolAddress((void**)&w3Lo, g_w3Lo);
    cudaGetSymbolAddress((void**)&w4Hi, g_w4Hi); cudaGetSymbolAddress((void**)&w4Lo, g_w4Lo);
    cudaGetSymbolAddress((void**)&qwHi, g_qwHi); cudaGetSymbolAddress((void**)&qwLo, g_qwLo);
    cudaGetSymbolAddress((void**)&kwHi, g_kwHi); cudaGetSymbolAddress((void**)&kwLo, g_kwLo);
    cudaGetSymbolAddress((void**)&vwHi, g_vwHi); cudaGetSymbolAddress((void**)&vwLo, g_vwLo);
    cudaGetSymbolAddress((void**)&pwHi, g_pwHi); cudaGetSymbolAddress((void**)&pwLo, g_pwLo);
    cudaGetSymbolAddress((void**)&qHi, g_qHi);  cudaGetSymbolAddress((void**)&qLo, g_qLo);
    cudaGetSymbolAddress((void**)&kHi, g_kHi);  cudaGetSymbolAddress((void**)&kLo, g_kLo);
    cudaGetSymbolAddress((void**)&vtHi, g_vtHi); cudaGetSymbolAddress((void**)&vtLo, g_vtLo);
    cudaGetSymbolAddress((void**)&pHi, g_pHi);  cudaGetSymbolAddress((void**)&pLo, g_pLo);
    cudaGetSymbolAddress((void**)&s, g_s);
    cudaGetSymbolAddress((void**)&t, g_t);
    cudaGetSymbolAddress((void**)&h, g_h);
    cudaGetSymbolAddress((void**)&y, g_y);
    cudaGetSymbolAddress((void**)&o, g_o);

    int nSM = 148;
    cudaDeviceGetAttribute(&nSM, cudaDevAttrMultiProcessorCount, 0);

    const int SMB128 = 1024 + 2 * (2 * 128 * 128 + 65536) + 128 * 27 * 4;  // 211456
    const int SMB_AV = 1024 + 2 * (2 * 128 * 128 + 65536);                 // 197632
    cudaFuncSetAttribute(tc_gemm<128>, cudaFuncAttributeMaxDynamicSharedMemorySize, SMB128);
    cudaFuncSetAttribute(tc_qkv,       cudaFuncAttributeMaxDynamicSharedMemorySize, SMB_AV);
    cudaFuncSetAttribute(tc_conv_ps,   cudaFuncAttributeMaxDynamicSharedMemorySize, SMB128);
    cudaFuncSetAttribute(tc_av_ps,     cudaFuncAttributeMaxDynamicSharedMemorySize, SMB_AV);

    const dim3 gStd(2, 64);
    const dim3 gQKV(2, 192);
    const dim3 gNT(32, 64);
    const dim3 tBlk(32, 8);
    const dim3 gWT3(16, 432);
    const dim3 gWT1(16, 16);
    const dim3 gVT(16, 256);
    const float rs512 = 0.04419417382415922f;
    const size_t ZB = (size_t)SPOS * CCH * sizeof(float);
    const int n4 = SPOS * CCH / 4;

    // ---- fork weight prep onto a side stream (all input-only work) ----
    cudaStream_t s2;
    cudaStreamCreateWithFlags(&s2, cudaStreamNonBlocking);
    cudaEvent_t evFork;
    cudaEventCreateWithFlags(&evFork, cudaEventDisableTiming);
    cudaEvent_t evW[8];
    for (int i = 0; i < 8; i++) cudaEventCreateWithFlags(&evW[i], cudaEventDisableTiming);

    cudaEventRecord(evFork, 0);
    cudaStreamWaitEvent(s2, evFork, 0);
    transpose_split<<<gWT3, tBlk, 0, s2>>>(r1w1, w1Hi, w1Lo, CONVK, CCH); cudaEventRecord(evW[0], s2);
    transpose_split<<<gWT3, tBlk, 0, s2>>>(r1w2, w2Hi, w2Lo, CONVK, CCH); cudaEventRecord(evW[1], s2);
    transpose_split<<<gWT1, tBlk, 0, s2>>>(qw, qwHi, qwLo, CCH, CCH);
    transpose_split<<<gWT1, tBlk, 0, s2>>>(kw, kwHi, kwLo, CCH, CCH);
    transpose_split<<<gWT1, tBlk, 0, s2>>>(vw, vwHi, vwLo, CCH, CCH);     cudaEventRecord(evW[2], s2);
    transpose_split<<<gWT1, tBlk, 0, s2>>>(pw, pwHi, pwLo, CCH, CCH);     cudaEventRecord(evW[5], s2);
    transpose_split<<<gWT3, tBlk, 0, s2>>>(r2w1, w3Hi, w3Lo, CONVK, CCH); cudaEventRecord(evW[6], s2);
    transpose_split<<<gWT3, tBlk, 0, s2>>>(r2w2, w4Hi, w4Lo, CONVK, CCH); cudaEventRecord(evW[7], s2);

    // ---- hoisted zero-fills for accumulation targets (off critical path) ----
    cudaMemsetAsync(h, 0, ZB, 0);
    cudaMemsetAsync(y, 0, ZB, 0);
    cudaMemsetAsync(o, 0, ZB, 0);
    cudaMemsetAsync(out, 0, ZB, 0);

    // ---- resnet 1 ----
    rmsnorm_split<<<SPOS / 8, 256>>>(x, r1g1, nHi, nLo, 1);
    cudaStreamWaitEvent(0, evW[0], 0);
    tc_conv_ps<<<nSM, 256, SMB128>>>(nHi, nLo, w1Hi, w1Lo, r1b1, nullptr, h, nSM);
    rmsnorm_split<<<SPOS / 8, 256>>>(h, r1g2, nHi, nLo, 1);
    cudaStreamWaitEvent(0, evW[1], 0);
    tc_conv_ps<<<nSM, 256, SMB128>>>(nHi, nLo, w2Hi, w2Lo, r1b2, x, y, nSM);

    // ---- attention ----
    rmsnorm_split<<<SPOS / 8, 256>>>(y, atg, nHi, nLo, 0);
    cudaStreamWaitEvent(0, evW[2], 0);
    tc_qkv<<<gQKV, 512, SMB_AV>>>(nHi, nLo, qwHi, qwLo, kwHi, kwLo, vwHi, vwLo,
                                  qb, kb, vb, qHi, qLo, kHi, kLo, t);
    transpose_split<<<gVT, tBlk>>>(t, vtHi, vtLo, SPOS, CCH);
    cudaMemsetAsync(t, 0, ZB, 0);   // conv3 target; overlaps attention tail

    tc_gemm<128><<<gNT, 512, SMB128>>>(qHi, qLo, CCH, kHi, kLo, CCH, nullptr, nullptr, s, nullptr, nullptr, SPOS, CCH, TCG_CAUSAL, rs512);
    softmax_split<<<SPOS, 256>>>(s, pHi, pLo);
    tc_av_ps<<<nSM, 256, SMB_AV>>>(pHi, pLo, vtHi, vtLo, o, nSM);
    split4_kernel<<<n4 / 256, 256>>>(o, qHi, qLo, n4);   // reuse q buffers for O split
    cudaStreamWaitEvent(0, evW[5], 0);
    tc_gemm<128><<<gStd, 512, SMB128>>>(qHi, qLo, CCH, pwHi, pwLo, CCH, pb, y, h, nullptr, nullptr, CCH, CCH, 0, 1.0f);

    // ---- resnet 2 ----
    rmsnorm_split<<<SPOS / 8, 256>>>(h, r2g1, nHi, nLo, 1);
    cudaStreamWaitEvent(0, evW[6], 0);
    tc_conv_ps<<<nSM, 256, SMB128>>>(nHi, nLo, w3Hi, w3Lo, r2b1, nullptr, t, nSM);
    rmsnorm_split<<<SPOS / 8, 256>>>(t, r2g2, nHi, nLo, 1);
    cudaStreamWaitEvent(0, evW[7], 0);
    tc_conv_ps<<<nSM, 256, SMB128>>>(nHi, nLo, w4Hi, w4Lo, r2b2, h, out, nSM);
}

// round 17
// speedup vs baseline: 1.5466x; 1.3159x over previous
#include <cuda_runtime.h>
#include <cuda_bf16.h>
#include <cuda_fp16.h>
#include <cstdint>
#include <math.h>

#define SPOS 8192
#define CCH  512
#define CONVK 13824   // 27*512

typedef __nv_bfloat16 bf16;

// ---------------- scratch (static device memory) ----------------
__device__ __align__(256) bf16 g_nHi[SPOS*CCH], g_nLo[SPOS*CCH];
__device__ __align__(256) bf16 g_w1Hi[CCH*CONVK], g_w1Lo[CCH*CONVK];
__device__ __align__(256) bf16 g_w2Hi[CCH*CONVK], g_w2Lo[CCH*CONVK];
__device__ __align__(256) bf16 g_w3Hi[CCH*CONVK], g_w3Lo[CCH*CONVK];
__device__ __align__(256) bf16 g_w4Hi[CCH*CONVK], g_w4Lo[CCH*CONVK];
__device__ __align__(256) bf16 g_qwHi[CCH*CCH], g_qwLo[CCH*CCH];
__device__ __align__(256) bf16 g_kwHi[CCH*CCH], g_kwLo[CCH*CCH];
__device__ __align__(256) bf16 g_vwHi[CCH*CCH], g_vwLo[CCH*CCH];
__device__ __align__(256) bf16 g_pwHi[CCH*CCH], g_pwLo[CCH*CCH];
__device__ __align__(256) bf16 g_qHi[SPOS*CCH], g_qLo[SPOS*CCH];
__device__ __align__(256) bf16 g_kHi[SPOS*CCH], g_kLo[SPOS*CCH];
__device__ __align__(256) bf16 g_vtHi[SPOS*CCH], g_vtLo[SPOS*CCH];
__device__ __align__(256) bf16 g_pHi[(size_t)SPOS*SPOS], g_pLo[(size_t)SPOS*SPOS];
__device__ __align__(256) float g_s[(size_t)SPOS*SPOS];
__device__ __align__(256) float g_t[SPOS*CCH], g_h[SPOS*CCH], g_y[SPOS*CCH];
__device__ __align__(256) float g_o[SPOS*CCH];

// ---------------- helpers ----------------
__device__ __forceinline__ uint32_t smem_u32(const void* p) {
    uint32_t a;
    asm("{ .reg .u64 t; cvta.to.shared.u64 t, %1; cvt.u32.u64 %0, t; }" : "=r"(a) : "l"(p));
    return a;
}
__device__ __forceinline__ void cp16(uint32_t dst, const void* src) {
    asm volatile("cp.async.cg.shared.global [%0], [%1], 16;" :: "r"(dst), "l"(src));
}
#define CP_COMMIT() asm volatile("cp.async.commit_group;" ::: "memory")
#define CP_WAIT1()  asm volatile("cp.async.wait_group 1;" ::: "memory")
#define CP_WAIT0()  asm volatile("cp.async.wait_group 0;" ::: "memory")
#define SWZ128(b) ((b) ^ (((b) >> 3) & 0x70))

#define LDSM_X4(r, addr) \
    asm volatile("ldmatrix.sync.aligned.m8n8.x4.shared.b16 {%0,%1,%2,%3}, [%4];" \
        : "=r"((r)[0]), "=r"((r)[1]), "=r"((r)[2]), "=r"((r)[3]) : "r"(addr))

__device__ __forceinline__ void mma16816(float* c, const uint32_t* a, const uint32_t* b) {
    asm volatile(
        "mma.sync.aligned.m16n8k16.row.col.f32.bf16.bf16.f32 "
        "{%0,%1,%2,%3},{%4,%5,%6,%7},{%8,%9},{%0,%1,%2,%3};"
        : "+f"(c[0]), "+f"(c[1]), "+f"(c[2]), "+f"(c[3])
        : "r"(a[0]), "r"(a[1]), "r"(a[2]), "r"(a[3]), "r"(b[0]), "r"(b[1]));
}
__device__ __forceinline__ void mma16816h(float* c, const uint32_t* a, const uint32_t* b) {
    asm volatile(
        "mma.sync.aligned.m16n8k16.row.col.f32.f16.f16.f32 "
        "{%0,%1,%2,%3},{%4,%5,%6,%7},{%8,%9},{%0,%1,%2,%3};"
        : "+f"(c[0]), "+f"(c[1]), "+f"(c[2]), "+f"(c[3])
        : "r"(a[0]), "r"(a[1]), "r"(a[2]), "r"(a[3]), "r"(b[0]), "r"(b[1]));
}

__device__ __forceinline__ float warpReduceSum(float v) {
#pragma unroll
    for (int o = 16; o; o >>= 1) v += __shfl_xor_sync(0xffffffffu, v, o);
    return v;
}
__device__ __forceinline__ float warpReduceMax(float v) {
#pragma unroll
    for (int o = 16; o; o >>= 1) v = fmaxf(v, __shfl_xor_sync(0xffffffffu, v, o));
    return v;
}
__device__ __forceinline__ uint32_t pack_bf16x2(float a, float b) {
    __nv_bfloat162 h;
    h.x = __float2bfloat16(a);
    h.y = __float2bfloat16(b);
    return *(uint32_t*)&h;
}
__device__ __forceinline__ uint32_t pack_h16x2(float a, float b) {
    __half2 h = __floats2half2_rn(a, b);
    return *(uint32_t*)&h;
}

// ---------------- rmsnorm + silu + split (warp-per-row; fp16 or bf16 out) ----------------
__global__ __launch_bounds__(256) void rmsnorm_split(
    const float* __restrict__ x, const float* __restrict__ g,
    bf16* __restrict__ hi, bf16* __restrict__ lo, int do_silu, int h16)
{
    const int wid = threadIdx.x >> 5, lid = threadIdx.x & 31;
    const int r = blockIdx.x * 8 + wid;
    const float* xr = x + (size_t)r * CCH;

    float v[16];
    float ss = 0.0f;
#pragma unroll
    for (int i = 0; i < 4; i++) {
        const float4 t = *(const float4*)(xr + i * 128 + lid * 4);
        v[4*i+0] = t.x; v[4*i+1] = t.y; v[4*i+2] = t.z; v[4*i+3] = t.w;
        ss += t.x*t.x + t.y*t.y + t.z*t.z + t.w*t.w;
    }
    ss = warpReduceSum(ss);
    const float scale = 22.62741699796952f / (sqrtf(ss) + 1e-8f);

#pragma unroll
    for (int i = 0; i < 4; i++) {
        const float4 gg = *(const float4*)(g + i * 128 + lid * 4);
        float o[4];
        o[0] = v[4*i+0]*scale*gg.x; o[1] = v[4*i+1]*scale*gg.y;
        o[2] = v[4*i+2]*scale*gg.z; o[3] = v[4*i+3]*scale*gg.w;
        if (do_silu) {
#pragma unroll
            for (int j = 0; j < 4; j++) o[j] = o[j] / (1.0f + __expf(-o[j]));
        }
        float l[4];
        const size_t base = (size_t)r * CCH + i * 128 + lid * 4;
        if (h16) {
#pragma unroll
            for (int j = 0; j < 4; j++) {
                __half h = __float2half_rn(o[j]);
                l[j] = o[j] - __half2float(h);
            }
            *(uint2*)(hi + base) = make_uint2(pack_h16x2(o[0], o[1]), pack_h16x2(o[2], o[3]));
            *(uint2*)(lo + base) = make_uint2(pack_h16x2(l[0], l[1]), pack_h16x2(l[2], l[3]));
        } else {
#pragma unroll
            for (int j = 0; j < 4; j++) {
                bf16 h = __float2bfloat16(o[j]);
                l[j] = o[j] - __bfloat162float(h);
            }
            *(uint2*)(hi + base) = make_uint2(pack_bf16x2(o[0], o[1]), pack_bf16x2(o[2], o[3]));
            *(uint2*)(lo + base) = make_uint2(pack_bf16x2(l[0], l[1]), pack_bf16x2(l[2], l[3]));
        }
    }
}

// ---------------- plain bf16 split (packed stores) ----------------
__global__ __launch_bounds__(256) void split4_kernel(
    const float* __restrict__ in, bf16* __restrict__ hi, bf16* __restrict__ lo, int n4)
{
    const int i = blockIdx.x * 256 + threadIdx.x;
    if (i >= n4) return;
    const float4 v = ((const float4*)in)[i];
    float o[4] = {v.x, v.y, v.z, v.w};
    float l[4];
#pragma unroll
    for (int j = 0; j < 4; j++) {
        bf16 h = __float2bfloat16(o[j]);
        l[j] = o[j] - __bfloat162float(h);
    }
    const size_t base = (size_t)i * 4;
    *(uint2*)(hi + base) = make_uint2(pack_bf16x2(o[0], o[1]), pack_bf16x2(o[2], o[3]));
    *(uint2*)(lo + base) = make_uint2(pack_bf16x2(l[0], l[1]), pack_bf16x2(l[2], l[3]));
}

// ---------------- transpose + split (fp16 or bf16 out) ----------------
__global__ void transpose_split(
    const float* __restrict__ in, bf16* __restrict__ hi, bf16* __restrict__ lo,
    int R, int Cc, int h16)
{
    __shared__ float t[32][33];
    const int c0 = blockIdx.x * 32, r0 = blockIdx.y * 32;
    const int tx = threadIdx.x;
    for (int j = threadIdx.y; j < 32; j += 8)
        t[j][tx] = in[(size_t)(r0 + j) * Cc + c0 + tx];
    __syncthreads();
    for (int j = threadIdx.y; j < 32; j += 8) {
        float v = t[tx][j];
        const size_t o = (size_t)(c0 + j) * R + r0 + tx;
        if (h16) {
            __half h = __float2half_rn(v);
            ((uint16_t*)hi)[o] = *(uint16_t*)&h;
            __half lw = __float2half_rn(v - __half2float(h));
            ((uint16_t*)lo)[o] = *(uint16_t*)&lw;
        } else {
            bf16 h = __float2bfloat16(v);
            hi[o] = h;
            lo[o] = __float2bfloat16(v - __bfloat162float(h));
        }
    }
}

// ---------------- softmax -> bf16 split probs (vectorized) ----------------
__global__ __launch_bounds__(256) void softmax_split(
    const float* __restrict__ S, bf16* __restrict__ PHi, bf16* __restrict__ PLo)
{
    __shared__ float red[8];
    const int r = blockIdx.x, tid = threadIdx.x;
    const int cnt = ((r >> 10) + 1) * 2;
    const float* row = S + (size_t)r * SPOS;

    float2 vals[16];
    float mx = -3.4e38f;
#pragma unroll
    for (int i = 0; i < 16; i++)
        if (i < cnt) {
            vals[i] = *(const float2*)(row + i * 512 + 2 * tid);
            mx = fmaxf(mx, fmaxf(vals[i].x, vals[i].y));
        }
    mx = warpReduceMax(mx);
    if ((tid & 31) == 0) red[tid >> 5] = mx;
    __syncthreads();
    float m2 = red[0];
#pragma unroll
    for (int i = 1; i < 8; i++) m2 = fmaxf(m2, red[i]);
    __syncthreads();
    float sum = 0.0f;
#pragma unroll
    for (int i = 0; i < 16; i++)
        if (i < cnt) {
            vals[i].x = __expf(vals[i].x - m2);
            vals[i].y = __expf(vals[i].y - m2);
            sum += vals[i].x + vals[i].y;
        }
    sum = warpReduceSum(sum);
    if ((tid & 31) == 0) red[tid >> 5] = sum;
    __syncthreads();
    float tot = 0.0f;
#pragma unroll
    for (int i = 0; i < 8; i++) tot += red[i];
    const float inv = 1.0f / tot;
    bf16* ph = PHi + (size_t)r * SPOS;
    bf16* pl = PLo + (size_t)r * SPOS;
#pragma unroll
    for (int i = 0; i < 16; i++)
        if (i < cnt) {
            const float p0 = vals[i].x * inv, p1 = vals[i].y * inv;
            const bf16 h0 = __float2bfloat16(p0), h1 = __float2bfloat16(p1);
            const float l0 = p0 - __bfloat162float(h0), l1 = p1 - __bfloat162float(h1);
            __nv_bfloat162 hh; hh.x = h0; hh.y = h1;
            *(__nv_bfloat162*)(ph + i * 512 + 2 * tid) = hh;
            *(uint32_t*)(pl + i * 512 + 2 * tid) = pack_bf16x2(l0, l1);
        }
}

// ---------------- HMMA split-bf16 GEMM, CTA tile 128x256, 512 threads ----------------
#define TCG_GATHER 1
#define TCG_VARK   2
#define TCG_CAUSAL 4

template<int BM>
__global__ __launch_bounds__(512) void tc_gemm(
    const bf16* __restrict__ AHi, const bf16* __restrict__ ALo, int ldA,
    const bf16* __restrict__ BHi, const bf16* __restrict__ BLo, int ldB,
    const float* __restrict__ bias, const float* __restrict__ resid,
    float* __restrict__ C, bf16* __restrict__ outHi, bf16* __restrict__ outLo,
    int ldc, int Ktot, int flags, float scale)
{
    constexpr int WN = (BM == 128) ? 8 : 16;
    constexpr int NT = 32 / WN * 2 / 2;
    constexpr int NP = (BM == 128) ? 2 : 1;
    constexpr int WNW = 256 / WN;
    constexpr int ABYTES = BM * 128;
    constexpr int STAGEB = 2 * ABYTES + 65536;

    extern __shared__ char smem[];
    int mtile = blockIdx.y;
    if (flags & TCG_VARK) mtile = gridDim.y - 1 - blockIdx.y;
    const int m0 = mtile * BM, n0 = blockIdx.x * 256;
    if (flags & TCG_CAUSAL) { if (n0 >= (((m0 >> 10) + 1) << 10)) return; }
    int Keff = Ktot;
    if (flags & TCG_VARK)   { Keff = ((m0 >> 10) + 1) << 10; }

    const uint32_t sb = smem_u32(smem);
    const uint32_t tbase = (sb + 1023) & ~1023u;
    char* tiles = smem + (tbase - sb);
    int* sBase = (int*)(tiles + 2 * STAGEB);

    const int tid = threadIdx.x, wid = tid >> 5, lid = tid & 31;
    const int wm = wid / WN, wn = wid % WN;
    const bool gather = (flags & TCG_GATHER);

    if (gather) {
        for (int i = tid; i < BM * 27; i += 512) {
            const int mloc = i / 27, tap = i - mloc * 27;
            const int m = m0 + mloc;
            const int kt = tap / 9, r9 = tap - kt * 9, kh = r9 / 3, kw = r9 - kh * 3;
            const int t = m >> 10, hw = m & 1023, h = hw >> 5, w = hw & 31;
            int tin = t + kt - 2; tin = tin < 0 ? 0 : tin;
            int hin = h + kh - 1; hin = hin < 0 ? 0 : (hin > 31 ? 31 : hin);
            int win = w + kw - 1; win = win < 0 ? 0 : (win > 31 ? 31 : win);
            sBase[i] = ((tin << 10) + (hin << 5) + win) << 9;
        }
        __syncthreads();
    }

    auto load_chunk = [&](int c, int buf) {
        const uint32_t tbu = tbase + buf * STAGEB;
        const long kkB = (long)c << 6;
        const int tap = c >> 3, c0 = (c & 7) << 6;
#pragma unroll
        for (int it = 0; it < BM / 64; it++) {
            const int i = it * 512 + tid;
            const int row = i >> 3, seg = i & 7;
            long offA;
            if (gather) offA = (long)sBase[row * 27 + tap] + c0 + (seg << 3);
            else        offA = (long)(m0 + row) * ldA + kkB + (seg << 3);
            const uint32_t d = SWZ128((uint32_t)(row * 128 + seg * 16));
            cp16(tbu + d,          AHi + offA);
            cp16(tbu + ABYTES + d, ALo + offA);
        }
#pragma unroll
        for (int it = 0; it < 4; it++) {
            const int i = it * 512 + tid;
            const int row = i >> 3, seg = i & 7;
            const long offB = (long)(n0 + row) * ldB + kkB + (seg << 3);
            const uint32_t d = SWZ128((uint32_t)(row * 128 + seg * 16));
            cp16(tbu + 2 * ABYTES + d,         BHi + offB);
            cp16(tbu + 2 * ABYTES + 32768 + d, BLo + offB);
        }
    };

    float acc[4][NT][4];
#pragma unroll
    for (int a = 0; a < 4; a++)
#pragma unroll
        for (int b = 0; b < NT; b++)
#pragma unroll
            for (int i = 0; i < 4; i++) acc[a][b][i] = 0.0f;

    const int a_r = lid & 15, a_ko = (lid >> 4) * 16;
    const int b_r = ((lid >> 4) << 3) + (lid & 7);
    const int b_ko = ((lid >> 3) & 1) * 16;

    const int nc = Keff >> 6;
    load_chunk(0, 0);
    CP_COMMIT();

    for (int c = 0; c < nc; c++) {
        if (c + 1 < nc) { load_chunk(c + 1, (c + 1) & 1); CP_COMMIT(); CP_WAIT1(); }
        else            { CP_WAIT0(); }
        __syncthreads();

        const uint32_t tbu = tbase + (c & 1) * STAGEB;
#pragma unroll
        for (int ks = 0; ks < 4; ks++) {
            const int kb = ks * 32;
            uint32_t ah[4][4], al[4][4];
#pragma unroll
            for (int mt = 0; mt < 4; mt++) {
                const int row = wm * 64 + mt * 16 + a_r;
                const uint32_t off = SWZ128((uint32_t)(row * 128 + kb + a_ko));
                LDSM_X4(ah[mt], tbu + off);
                LDSM_X4(al[mt], tbu + ABYTES + off);
            }
#pragma unroll
            for (int p = 0; p < NP; p++) {
                const int row = wn * WNW + p * 16 + b_r;
                const uint32_t off = SWZ128((uint32_t)(row * 128 + kb + b_ko));
                uint32_t rh[4], rl[4];
                LDSM_X4(rh, tbu + 2 * ABYTES + off);
                LDSM_X4(rl, tbu + 2 * ABYTES + 32768 + off);
#pragma unroll
                for (int mt = 0; mt < 4; mt++) {
                    mma16816(acc[mt][2*p],   ah[mt], rh);
                    mma16816(acc[mt][2*p],   ah[mt], rl);
                    mma16816(acc[mt][2*p],   al[mt], rh);
                    mma16816(acc[mt][2*p+1], ah[mt], rh + 2);
                    mma16816(acc[mt][2*p+1], ah[mt], rl + 2);
                    mma16816(acc[mt][2*p+1], al[mt], rh + 2);
                }
            }
        }
        __syncthreads();
    }

    const int er = lid >> 2, ec = (lid & 3) * 2;
#pragma unroll
    for (int mt = 0; mt < 4; mt++) {
#pragma unroll
        for (int nt = 0; nt < NT; nt++) {
            const int n = n0 + wn * WNW + nt * 8 + ec;
            float b0 = 0.f, b1 = 0.f;
            if (bias) { b0 = bias[n]; b1 = bias[n + 1]; }
#pragma unroll
            for (int half = 0; half < 2; half++) {
                const int m = m0 + wm * 64 + mt * 16 + er + half * 8;
                float v0 = acc[mt][nt][half * 2 + 0] * scale + b0;
                float v1 = acc[mt][nt][half * 2 + 1] * scale + b1;
                if (resid) {
                    const float2 rv = *(const float2*)(resid + (size_t)m * ldc + n);
                    v0 += rv.x; v1 += rv.y;
                }
                if (C)
                    *(float2*)(C + (size_t)m * ldc + n) = make_float2(v0, v1);
                if (outHi) {
                    bf16 h0 = __float2bfloat16(v0), h1 = __float2bfloat16(v1);
                    __nv_bfloat162 hh; hh.x = h0; hh.y = h1;
                    __nv_bfloat162 ll;
                    ll.x = __float2bfloat16(v0 - __bfloat162float(h0));
                    ll.y = __float2bfloat16(v1 - __bfloat162float(h1));
                    *(__nv_bfloat162*)(outHi + (size_t)m * ldc + n) = hh;
                    *(__nv_bfloat162*)(outLo + (size_t)m * ldc + n) = ll;
                }
            }
        }
    }
}

// ---------------- fused Q/K/V projection: grid (2, 192); sel = blockIdx.y>>6 ----------------
__global__ __launch_bounds__(512) void tc_qkv(
    const bf16* __restrict__ AHi, const bf16* __restrict__ ALo,
    const bf16* __restrict__ qwHi, const bf16* __restrict__ qwLo,
    const bf16* __restrict__ kwHi, const bf16* __restrict__ kwLo,
    const bf16* __restrict__ vwHi, const bf16* __restrict__ vwLo,
    const float* __restrict__ qb, const float* __restrict__ kb, const float* __restrict__ vb,
    bf16* __restrict__ qHi, bf16* __restrict__ qLo,
    bf16* __restrict__ kHi, bf16* __restrict__ kLo,
    float* __restrict__ vOut)
{
    constexpr int ABYTES = 128 * 128;
    constexpr int STAGEB = 2 * ABYTES + 65536;

    extern __shared__ char smem[];
    const int sel = blockIdx.y >> 6;
    const int m0 = (blockIdx.y & 63) * 128, n0 = blockIdx.x * 256;

    const bf16* BHi = (sel == 0) ? qwHi : (sel == 1) ? kwHi : vwHi;
    const bf16* BLo = (sel == 0) ? qwLo : (sel == 1) ? kwLo : vwLo;
    const float* bias = (sel == 0) ? qb : (sel == 1) ? kb : vb;

    const uint32_t sb = smem_u32(smem);
    const uint32_t tbase = (sb + 1023) & ~1023u;

    const int tid = threadIdx.x, wid = tid >> 5, lid = tid & 31;
    const int wm = wid >> 3, wn = wid & 7;
    const int a_r = lid & 15, a_ko = (lid >> 4) * 16;
    const int b_r = ((lid >> 4) << 3) + (lid & 7);
    const int b_ko = ((lid >> 3) & 1) * 16;

    auto load_chunk = [&](int c, int buf) {
        const uint32_t tbu = tbase + buf * STAGEB;
        const long kkB = (long)c << 6;
#pragma unroll
        for (int it = 0; it < 2; it++) {
            const int i = it * 512 + tid;
            const int row = i >> 3, seg = i & 7;
            const long offA = (long)(m0 + row) * CCH + kkB + (seg << 3);
            const uint32_t d = SWZ128((uint32_t)(row * 128 + seg * 16));
            cp16(tbu + d,          AHi + offA);
            cp16(tbu + ABYTES + d, ALo + offA);
        }
#pragma unroll
        for (int it = 0; it < 4; it++) {
            const int i = it * 512 + tid;
            const int row = i >> 3, seg = i & 7;
            const long offB = (long)(n0 + row) * CCH + kkB + (seg << 3);
            const uint32_t d = SWZ128((uint32_t)(row * 128 + seg * 16));
            cp16(tbu + 2 * ABYTES + d,         BHi + offB);
            cp16(tbu + 2 * ABYTES + 32768 + d, BLo + offB);
        }
    };

    float acc[4][4][4];
#pragma unroll
    for (int a = 0; a < 4; a++)
#pragma unroll
        for (int b = 0; b < 4; b++)
#pragma unroll
            for (int i = 0; i < 4; i++) acc[a][b][i] = 0.0f;

    load_chunk(0, 0);
    CP_COMMIT();

    for (int c = 0; c < 8; c++) {
        if (c + 1 < 8) { load_chunk(c + 1, (c + 1) & 1); CP_COMMIT(); CP_WAIT1(); }
        else           { CP_WAIT0(); }
        __syncthreads();

        const uint32_t tbu = tbase + (c & 1) * STAGEB;
#pragma unroll
        for (int ks = 0; ks < 4; ks++) {
            const int kb = ks * 32;
            uint32_t ah[4][4], al[4][4];
#pragma unroll
            for (int mt = 0; mt < 4; mt++) {
                const int row = wm * 64 + mt * 16 + a_r;
                const uint32_t off = SWZ128((uint32_t)(row * 128 + kb + a_ko));
                LDSM_X4(ah[mt], tbu + off);
                LDSM_X4(al[mt], tbu + ABYTES + off);
            }
#pragma unroll
            for (int p = 0; p < 2; p++) {
                const int row = wn * 32 + p * 16 + b_r;
                const uint32_t off = SWZ128((uint32_t)(row * 128 + kb + b_ko));
                uint32_t rh[4], rl[4];
                LDSM_X4(rh, tbu + 2 * ABYTES + off);
                LDSM_X4(rl, tbu + 2 * ABYTES + 32768 + off);
#pragma unroll
                for (int mt = 0; mt < 4; mt++) {
                    mma16816(acc[mt][2*p],   ah[mt], rh);
                    mma16816(acc[mt][2*p],   ah[mt], rl);
                    mma16816(acc[mt][2*p],   al[mt], rh);
                    mma16816(acc[mt][2*p+1], ah[mt], rh + 2);
                    mma16816(acc[mt][2*p+1], ah[mt], rl + 2);
                    mma16816(acc[mt][2*p+1], al[mt], rh + 2);
                }
            }
        }
        __syncthreads();
    }

    bf16* outHi = (sel == 0) ? qHi : (sel == 1) ? kHi : nullptr;
    bf16* outLo = (sel == 0) ? qLo : (sel == 1) ? kLo : nullptr;

    const int er = lid >> 2, ec = (lid & 3) * 2;
#pragma unroll
    for (int mt = 0; mt < 4; mt++) {
#pragma unroll
        for (int nt = 0; nt < 4; nt++) {
            const int n = n0 + wn * 32 + nt * 8 + ec;
            const float b0 = bias[n], b1 = bias[n + 1];
#pragma unroll
            for (int half = 0; half < 2; half++) {
                const int m = m0 + wm * 64 + mt * 16 + er + half * 8;
                const float v0 = acc[mt][nt][half * 2 + 0] + b0;
                const float v1 = acc[mt][nt][half * 2 + 1] + b1;
                if (sel == 2) {
                    *(float2*)(vOut + (size_t)m * CCH + n) = make_float2(v0, v1);
                } else {
                    bf16 h0 = __float2bfloat16(v0), h1 = __float2bfloat16(v1);
                    __nv_bfloat162 hh; hh.x = h0; hh.y = h1;
                    __nv_bfloat162 ll;
                    ll.x = __float2bfloat16(v0 - __bfloat162float(h0));
                    ll.y = __float2bfloat16(v1 - __bfloat162float(h1));
                    *(__nv_bfloat162*)(outHi + (size_t)m * CCH + n) = hh;
                    *(__nv_bfloat162*)(outLo + (size_t)m * CCH + n) = ll;
                }
            }
        }
    }
}

// ---------------- persistent balanced split-K conv GEMM (fp16 2-MMA path) ----------------
// A = activations in fp16 hi/lo (exact split), B = weights single fp16.
__global__ __launch_bounds__(256) void tc_conv_ps(
    const bf16* __restrict__ AHi, const bf16* __restrict__ ALo,
    const bf16* __restrict__ BHi,
    const float* __restrict__ bias, const float* __restrict__ resid,
    float* __restrict__ C, int nW)
{
    constexpr int ABYTES = 128 * 128;             // 16KB
    constexpr int STAGEB = 2 * ABYTES + 32768;    // 64KB: Ah+Al+Bh

    extern __shared__ char smem[];
    const uint32_t sb = smem_u32(smem);
    const uint32_t tbase = (sb + 1023) & ~1023u;
    char* tiles = smem + (tbase - sb);
    int* sBase = (int*)(tiles + 2 * STAGEB);

    const int tid = threadIdx.x, wid = tid >> 5, lid = tid & 31;
    const int wm = wid >> 2, wn = wid & 3;
    const int a_r = lid & 15, a_ko = (lid >> 4) * 16;
    const int b_r = ((lid >> 4) << 3) + (lid & 7);
    const int b_ko = ((lid >> 3) & 1) * 16;
    const int er = lid >> 2, ec = (lid & 3) * 2;

    const long TC = 128L * 216;
    const long u0 = (long)blockIdx.x * TC / nW;
    const long u1 = (long)(blockIdx.x + 1) * TC / nW;
    if (u1 <= u0) return;
    const int t0 = (int)(u0 / 216), t1 = (int)((u1 - 1) / 216);

    for (int tau = t0; tau <= t1; tau++) {
        const int c0 = (tau == t0) ? (int)(u0 - (long)tau * 216) : 0;
        const int c1 = (tau == t1) ? (int)(u1 - (long)tau * 216) : 216;
        const int m0 = (tau >> 1) * 128, n0 = (tau & 1) * 256;

        for (int i = tid; i < 128 * 27; i += 256) {
            const int mloc = i / 27, tap = i - mloc * 27;
            const int m = m0 + mloc;
            const int kt = tap / 9, r9 = tap - kt * 9, kh = r9 / 3, kw = r9 - kh * 3;
            const int t = m >> 10, hw = m & 1023, h = hw >> 5, w = hw & 31;
            int tin = t + kt - 2; tin = tin < 0 ? 0 : tin;
            int hin = h + kh - 1; hin = hin < 0 ? 0 : (hin > 31 ? 31 : hin);
            int win = w + kw - 1; win = win < 0 ? 0 : (win > 31 ? 31 : win);
            sBase[i] = ((tin << 10) + (hin << 5) + win) << 9;
        }
        __syncthreads();

        auto load_chunk = [&](int c, int buf) {
            const uint32_t tbu = tbase + buf * STAGEB;
            const long kkB = (long)c << 6;
            const int tap = c >> 3, cc0 = (c & 7) << 6;
#pragma unroll
            for (int it = 0; it < 4; it++) {
                const int i = it * 256 + tid;
                const int row = i >> 3, seg = i & 7;
                const long offA = (long)sBase[row * 27 + tap] + cc0 + (seg << 3);
                const uint32_t d = SWZ128((uint32_t)(row * 128 + seg * 16));
                cp16(tbu + d,          AHi + offA);
                cp16(tbu + ABYTES + d, ALo + offA);
            }
#pragma unroll
            for (int it = 0; it < 8; it++) {
                const int i = it * 256 + tid;
                const int row = i >> 3, seg = i & 7;
                const long offB = (long)(n0 + row) * CONVK + kkB + (seg << 3);
                const uint32_t d = SWZ128((uint32_t)(row * 128 + seg * 16));
                cp16(tbu + 2 * ABYTES + d, BHi + offB);
            }
        };

        float acc[4][8][4];
#pragma unroll
        for (int a = 0; a < 4; a++)
#pragma unroll
            for (int b = 0; b < 8; b++)
#pragma unroll
                for (int i = 0; i < 4; i++) acc[a][b][i] = 0.0f;

        load_chunk(c0, c0 & 1);
        CP_COMMIT();

        for (int c = c0; c < c1; c++) {
            if (c + 1 < c1) { load_chunk(c + 1, (c + 1) & 1); CP_COMMIT(); CP_WAIT1(); }
            else            { CP_WAIT0(); }
            __syncthreads();

            const uint32_t tbu = tbase + (c & 1) * STAGEB;
#pragma unroll
            for (int ks = 0; ks < 4; ks++) {
                const int kb = ks * 32;
                uint32_t ah[4][4], al[4][4];
#pragma unroll
                for (int mt = 0; mt < 4; mt++) {
                    const int row = wm * 64 + mt * 16 + a_r;
                    const uint32_t off = SWZ128((uint32_t)(row * 128 + kb + a_ko));
                    LDSM_X4(ah[mt], tbu + off);
                    LDSM_X4(al[mt], tbu + ABYTES + off);
                }
#pragma unroll
                for (int p = 0; p < 4; p++) {
                    const int row = wn * 64 + p * 16 + b_r;
                    const uint32_t off = SWZ128((uint32_t)(row * 128 + kb + b_ko));
                    uint32_t rh[4];
                    LDSM_X4(rh, tbu + 2 * ABYTES + off);
#pragma unroll
                    for (int mt = 0; mt < 4; mt++) {
                        mma16816h(acc[mt][2*p],   ah[mt], rh);
                        mma16816h(acc[mt][2*p],   al[mt], rh);
                        mma16816h(acc[mt][2*p+1], ah[mt], rh + 2);
                        mma16816h(acc[mt][2*p+1], al[mt], rh + 2);
                    }
                }
            }
            __syncthreads();
        }

        const bool lead = (c0 == 0);
#pragma unroll
        for (int mt = 0; mt < 4; mt++) {
#pragma unroll
            for (int nt = 0; nt < 8; nt++) {
                const int n = n0 + wn * 64 + nt * 8 + ec;
                float b0 = 0.f, b1 = 0.f;
                if (lead) { b0 = bias[n]; b1 = bias[n + 1]; }
#pragma unroll
                for (int half = 0; half < 2; half++) {
                    const int m = m0 + wm * 64 + mt * 16 + er + half * 8;
                    float v0 = acc[mt][nt][half * 2 + 0] + b0;
                    float v1 = acc[mt][nt][half * 2 + 1] + b1;
                    if (lead && resid) {
                        const float2 rv = *(const float2*)(resid + (size_t)m * CCH + n);
                        v0 += rv.x; v1 += rv.y;
                    }
                    atomicAdd(C + (size_t)m * CCH + n,     v0);
                    atomicAdd(C + (size_t)m * CCH + n + 1, v1);
                }
            }
        }
        __syncthreads();
    }
}

// ---------------- persistent balanced split-K A*V GEMM (varK triangular, bf16) ----------------
__global__ __launch_bounds__(256) void tc_av_ps(
    const bf16* __restrict__ PHi, const bf16* __restrict__ PLo,
    const bf16* __restrict__ VHi, const bf16* __restrict__ VLo,
    float* __restrict__ O, int nW)
{
    constexpr int ABYTES = 128 * 128;
    constexpr int STAGEB = 2 * ABYTES + 65536;

    extern __shared__ char smem[];
    const uint32_t sb = smem_u32(smem);
    const uint32_t tbase = (sb + 1023) & ~1023u;
    char* tiles = smem + (tbase - sb);

    const int tid = threadIdx.x, wid = tid >> 5, lid = tid & 31;
    const int wm = wid >> 2, wn = wid & 3;
    const int a_r = lid & 15, a_ko = (lid >> 4) * 16;
    const int b_r = ((lid >> 4) << 3) + (lid & 7);
    const int b_ko = ((lid >> 3) & 1) * 16;
    const int er = lid >> 2, ec = (lid & 3) * 2;

    const long TU = 9216;
    const long u0 = (long)blockIdx.x * TU / nW;
    const long u1 = (long)(blockIdx.x + 1) * TU / nW;
    long ucur = u0;

    while (ucur < u1) {
        int g = 0;
        while (g < 7 && 128L * (g + 1) * (g + 2) <= ucur) g++;
        const long Pg = 128L * g * (g + 1);
        const int L = 16 * (g + 1);
        const long rem = ucur - Pg;
        const int tl = (int)(rem / L);
        const int c0 = (int)(rem - (long)tl * L);
        int c1 = c0 + (int)(u1 - ucur);
        if (c1 > L) c1 = L;
        const int m0 = (g * 8 + (tl >> 1)) * 128;
        const int n0 = (tl & 1) * 256;

        auto load_chunk = [&](int c, int buf) {
            const uint32_t tbu = tbase + buf * STAGEB;
            const long kkB = (long)c << 6;
#pragma unroll
            for (int it = 0; it < 4; it++) {
                const int i = it * 256 + tid;
                const int row = i >> 3, seg = i & 7;
                const long offA = (long)(m0 + row) * SPOS + kkB + (seg << 3);
                const uint32_t d = SWZ128((uint32_t)(row * 128 + seg * 16));
                cp16(tbu + d,          PHi + offA);
                cp16(tbu + ABYTES + d, PLo + offA);
            }
#pragma unroll
            for (int it = 0; it < 8; it++) {
                const int i = it * 256 + tid;
                const int row = i >> 3, seg = i & 7;
                const long offB = (long)(n0 + row) * SPOS + kkB + (seg << 3);
                const uint32_t d = SWZ128((uint32_t)(row * 128 + seg * 16));
                cp16(tbu + 2 * ABYTES + d,         VHi + offB);
                cp16(tbu + 2 * ABYTES + 32768 + d, VLo + offB);
            }
        };

        float acc[4][8][4];
#pragma unroll
        for (int a = 0; a < 4; a++)
#pragma unroll
            for (int b = 0; b < 8; b++)
#pragma unroll
                for (int i = 0; i < 4; i++) acc[a][b][i] = 0.0f;

        load_chunk(c0, c0 & 1);
        CP_COMMIT();

        for (int c = c0; c < c1; c++) {
            if (c + 1 < c1) { load_chunk(c + 1, (c + 1) & 1); CP_COMMIT(); CP_WAIT1(); }
            else            { CP_WAIT0(); }
            __syncthreads();

            const uint32_t tbu = tbase + (c & 1) * STAGEB;
#pragma unroll
            for (int ks = 0; ks < 4; ks++) {
                const int kb = ks * 32;
                uint32_t ah[4][4], al[4][4];
#pragma unroll
                for (int mt = 0; mt < 4; mt++) {
                    const int row = wm * 64 + mt * 16 + a_r;
                    const uint32_t off = SWZ128((uint32_t)(row * 128 + kb + a_ko));
                    LDSM_X4(ah[mt], tbu + off);
                    LDSM_X4(al[mt], tbu + ABYTES + off);
                }
#pragma unroll
                for (int p = 0; p < 4; p++) {
                    const int row = wn * 64 + p * 16 + b_r;
                    const uint32_t off = SWZ128((uint32_t)(row * 128 + kb + b_ko));
                    uint32_t rh[4], rl[4];
                    LDSM_X4(rh, tbu + 2 * ABYTES + off);
                    LDSM_X4(rl, tbu + 2 * ABYTES + 32768 + off);
#pragma unroll
                    for (int mt = 0; mt < 4; mt++) {
                        mma16816(acc[mt][2*p],   ah[mt], rh);
                        mma16816(acc[mt][2*p],   ah[mt], rl);
                        mma16816(acc[mt][2*p],   al[mt], rh);
                        mma16816(acc[mt][2*p+1], ah[mt], rh + 2);
                        mma16816(acc[mt][2*p+1], ah[mt], rl + 2);
                        mma16816(acc[mt][2*p+1], al[mt], rh + 2);
                    }
                }
            }
            __syncthreads();
        }

#pragma unroll
        for (int mt = 0; mt < 4; mt++) {
#pragma unroll
            for (int nt = 0; nt < 8; nt++) {
                const int n = n0 + wn * 64 + nt * 8 + ec;
#pragma unroll
                for (int half = 0; half < 2; half++) {
                    const int m = m0 + wm * 64 + mt * 16 + er + half * 8;
                    atomicAdd(O + (size_t)m * CCH + n,     acc[mt][nt][half * 2 + 0]);
                    atomicAdd(O + (size_t)m * CCH + n + 1, acc[mt][nt][half * 2 + 1]);
                }
            }
        }
        __syncthreads();
        ucur += c1 - c0;
    }
}

// ---------------- host orchestration ----------------
extern "C" void kernel_launch(void* const* d_in, const int* in_sizes, int n_in,
                              void* d_out, int out_size)
{
    const float* x    = (const float*)d_in[0];
    const float* r1g1 = (const float*)d_in[1];
    const float* r1w1 = (const float*)d_in[2];
    const float* r1b1 = (const float*)d_in[3];
    const float* r1g2 = (const float*)d_in[4];
    const float* r1w2 = (const float*)d_in[5];
    const float* r1b2 = (const float*)d_in[6];
    const float* atg  = (const float*)d_in[7];
    const float* qw   = (const float*)d_in[8];
    const float* qb   = (const float*)d_in[9];
    const float* kw   = (const float*)d_in[10];
    const float* kb   = (const float*)d_in[11];
    const float* vw   = (const float*)d_in[12];
    const float* vb   = (const float*)d_in[13];
    const float* pw   = (const float*)d_in[14];
    const float* pb   = (const float*)d_in[15];
    const float* r2g1 = (const float*)d_in[16];
    const float* r2w1 = (const float*)d_in[17];
    const float* r2b1 = (const float*)d_in[18];
    const float* r2g2 = (const float*)d_in[19];
    const float* r2w2 = (const float*)d_in[20];
    const float* r2b2 = (const float*)d_in[21];
    float* out = (float*)d_out;

    bf16 *nHi, *nLo, *qHi, *qLo, *kHi, *kLo, *vtHi, *vtLo, *pHi, *pLo;
    bf16 *w1Hi, *w1Lo, *w2Hi, *w2Lo, *w3Hi, *w3Lo, *w4Hi, *w4Lo;
    bf16 *qwHi, *qwLo, *kwHi, *kwLo, *vwHi, *vwLo, *pwHi, *pwLo;
    float *s, *t, *h, *y, *o;
    cudaGetSymbolAddress((void**)&nHi, g_nHi);  cudaGetSymbolAddress((void**)&nLo, g_nLo);
    cudaGetSymbolAddress((void**)&w1Hi, g_w1Hi); cudaGetSymbolAddress((void**)&w1Lo, g_w1Lo);
    cudaGetSymbolAddress((void**)&w2Hi, g_w2Hi); cudaGetSymbolAddress((void**)&w2Lo, g_w2Lo);
    cudaGetSymbolAddress((void**)&w3Hi, g_w3Hi); cudaGetSymbolAddress((void**)&w3Lo, g_w3Lo);
    cudaGetSymbolAddress((void**)&w4Hi, g_w4Hi); cudaGetSymbolAddress((void**)&w4Lo, g_w4Lo);
    cudaGetSymbolAddress((void**)&qwHi, g_qwHi); cudaGetSymbolAddress((void**)&qwLo, g_qwLo);
    cudaGetSymbolAddress((void**)&kwHi, g_kwHi); cudaGetSymbolAddress((void**)&kwLo, g_kwLo);
    cudaGetSymbolAddress((void**)&vwHi, g_vwHi); cudaGetSymbolAddress((void**)&vwLo, g_vwLo);
    cudaGetSymbolAddress((void**)&pwHi, g_pwHi); cudaGetSymbolAddress((void**)&pwLo, g_pwLo);
    cudaGetSymbolAddress((void**)&qHi, g_qHi);  cudaGetSymbolAddress((void**)&qLo, g_qLo);
    cudaGetSymbolAddress((void**)&kHi, g_kHi);  cudaGetSymbolAddress((void**)&kLo, g_kLo);
    cudaGetSymbolAddress((void**)&vtHi, g_vtHi); cudaGetSymbolAddress((void**)&vtLo, g_vtLo);
    cudaGetSymbolAddress((void**)&pHi, g_pHi);  cudaGetSymbolAddress((void**)&pLo, g_pLo);
    cudaGetSymbolAddress((void**)&s, g_s);
    cudaGetSymbolAddress((void**)&t, g_t);
    cudaGetSymbolAddress((void**)&h, g_h);
    cudaGetSymbolAddress((void**)&y, g_y);
    cudaGetSymbolAddress((void**)&o, g_o);

    int nSM = 148;
    cudaDeviceGetAttribute(&nSM, cudaDevAttrMultiProcessorCount, 0);

    const int SMB128 = 1024 + 2 * (2 * 128 * 128 + 65536) + 128 * 27 * 4;  // 211456
    const int SMB_AV = 1024 + 2 * (2 * 128 * 128 + 65536);                 // 197632
    const int SMB_CV = 1024 + 2 * (2 * 128 * 128 + 32768) + 128 * 27 * 4;  // 145920
    cudaFuncSetAttribute(tc_gemm<128>, cudaFuncAttributeMaxDynamicSharedMemorySize, SMB128);
    cudaFuncSetAttribute(tc_qkv,       cudaFuncAttributeMaxDynamicSharedMemorySize, SMB_AV);
    cudaFuncSetAttribute(tc_conv_ps,   cudaFuncAttributeMaxDynamicSharedMemorySize, SMB_CV);
    cudaFuncSetAttribute(tc_av_ps,     cudaFuncAttributeMaxDynamicSharedMemorySize, SMB_AV);

    const dim3 gStd(2, 64);
    const dim3 gQKV(2, 192);
    const dim3 gNT(32, 64);
    const dim3 tBlk(32, 8);
    const dim3 gWT3(16, 432);
    const dim3 gWT1(16, 16);
    const dim3 gVT(16, 256);
    const float rs512 = 0.04419417382415922f;
    const size_t ZB = (size_t)SPOS * CCH * sizeof(float);
    const int n4 = SPOS * CCH / 4;

    // ---- fork weight prep onto a side stream (all input-only work) ----
    cudaStream_t s2;
    cudaStreamCreateWithFlags(&s2, cudaStreamNonBlocking);
    cudaEvent_t evFork;
    cudaEventCreateWithFlags(&evFork, cudaEventDisableTiming);
    cudaEvent_t evW[8];
    for (int i = 0; i < 8; i++) cudaEventCreateWithFlags(&evW[i], cudaEventDisableTiming);

    cudaEventRecord(evFork, 0);
    cudaStreamWaitEvent(s2, evFork, 0);
    transpose_split<<<gWT3, tBlk, 0, s2>>>(r1w1, w1Hi, w1Lo, CONVK, CCH, 1); cudaEventRecord(evW[0], s2);
    transpose_split<<<gWT3, tBlk, 0, s2>>>(r1w2, w2Hi, w2Lo, CONVK, CCH, 1); cudaEventRecord(evW[1], s2);
    transpose_split<<<gWT1, tBlk, 0, s2>>>(qw, qwHi, qwLo, CCH, CCH, 0);
    transpose_split<<<gWT1, tBlk, 0, s2>>>(kw, kwHi, kwLo, CCH, CCH, 0);
    transpose_split<<<gWT1, tBlk, 0, s2>>>(vw, vwHi, vwLo, CCH, CCH, 0);     cudaEventRecord(evW[2], s2);
    transpose_split<<<gWT1, tBlk, 0, s2>>>(pw, pwHi, pwLo, CCH, CCH, 0);     cudaEventRecord(evW[5], s2);
    transpose_split<<<gWT3, tBlk, 0, s2>>>(r2w1, w3Hi, w3Lo, CONVK, CCH, 1); cudaEventRecord(evW[6], s2);
    transpose_split<<<gWT3, tBlk, 0, s2>>>(r2w2, w4Hi, w4Lo, CONVK, CCH, 1); cudaEventRecord(evW[7], s2);

    // ---- hoisted zero-fills for accumulation targets (off critical path) ----
    cudaMemsetAsync(h, 0, ZB, 0);
    cudaMemsetAsync(y, 0, ZB, 0);
    cudaMemsetAsync(o, 0, ZB, 0);
    cudaMemsetAsync(out, 0, ZB, 0);

    // ---- resnet 1 (convs on fp16 2-MMA path) ----
    rmsnorm_split<<<SPOS / 8, 256>>>(x, r1g1, nHi, nLo, 1, 1);
    cudaStreamWaitEvent(0, evW[0], 0);
    tc_conv_ps<<<nSM, 256, SMB_CV>>>(nHi, nLo, w1Hi, r1b1, nullptr, h, nSM);
    rmsnorm_split<<<SPOS / 8, 256>>>(h, r1g2, nHi, nLo, 1, 1);
    cudaStreamWaitEvent(0, evW[1], 0);
    tc_conv_ps<<<nSM, 256, SMB_CV>>>(nHi, nLo, w2Hi, r1b2, x, y, nSM);

    // ---- attention (bf16 3-MMA path) ----
    rmsnorm_split<<<SPOS / 8, 256>>>(y, atg, nHi, nLo, 0, 0);
    cudaStreamWaitEvent(0, evW[2], 0);
    tc_qkv<<<gQKV, 512, SMB_AV>>>(nHi, nLo, qwHi, qwLo, kwHi, kwLo, vwHi, vwLo,
                                  qb, kb, vb, qHi, qLo, kHi, kLo, t);
    transpose_split<<<gVT, tBlk>>>(t, vtHi, vtLo, SPOS, CCH, 0);
    cudaMemsetAsync(t, 0, ZB, 0);   // conv3 target; overlaps attention tail

    tc_gemm<128><<<gNT, 512, SMB128>>>(qHi, qLo, CCH, kHi, kLo, CCH, nullptr, nullptr, s, nullptr, nullptr, SPOS, CCH, TCG_CAUSAL, rs512);
    softmax_split<<<SPOS, 256>>>(s, pHi, pLo);
    tc_av_ps<<<nSM, 256, SMB_AV>>>(pHi, pLo, vtHi, vtLo, o, nSM);
    split4_kernel<<<n4 / 256, 256>>>(o, qHi, qLo, n4);   // reuse q buffers for O split
    cudaStreamWaitEvent(0, evW[5], 0);
    tc_gemm<128><<<gStd, 512, SMB128>>>(qHi, qLo, CCH, pwHi, pwLo, CCH, pb, y, h, nullptr, nullptr, CCH, CCH, 0, 1.0f);

    // ---- resnet 2 (convs on fp16 2-MMA path) ----
    rmsnorm_split<<<SPOS / 8, 256>>>(h, r2g1, nHi, nLo, 1, 1);
    cudaStreamWaitEvent(0, evW[6], 0);
    tc_conv_ps<<<nSM, 256, SMB_CV>>>(nHi, nLo, w3Hi, r2b1, nullptr, t, nSM);
    rmsnorm_split<<<SPOS / 8, 256>>>(t, r2g2, nHi, nLo, 1, 1);
    cudaStreamWaitEvent(0, evW[7], 0);
    tc_conv_ps<<<nSM, 256, SMB_CV>>>(nHi, nLo, w4Hi, r2b2, h, out, nSM);
}